// round 9
// baseline (speedup 1.0000x reference)
#include <cuda_runtime.h>
#include <cuda_bf16.h>
#include <math.h>
#include <stdint.h>

// Problem constants
#define SEQ   2048
#define BATCH 2
#define DMODEL 1024
#define NHEAD 16
#define DHEAD 64
#define NROWS (BATCH * SEQ)          // 4096
#define OUT_ELEMS   (NROWS * DMODEL)             // 4,194,304
#define W_ELEMS (DMODEL * DMODEL)                // 1,048,576
#define ATTN_ELEMS  (BATCH * NHEAD * SEQ * SEQ)  // 134,217,728
#define NSCALE 2048                              // rescale blocks in fat kernel

// -------------------- device scratch (no allocations allowed) ------------
__device__ float g_o[NROWS * DMODEL];
__device__ float g_rowsum[BATCH * NHEAD * SEQ];
__device__ __nv_bfloat16 g_inh[3 * OUT_ELEMS];
__device__ __nv_bfloat16 g_inl[3 * OUT_ELEMS];
__device__ __nv_bfloat16 g_wh[4 * W_ELEMS];
__device__ __nv_bfloat16 g_wl[4 * W_ELEMS];
__device__ __nv_bfloat16 g_qh[OUT_ELEMS], g_ql[OUT_ELEMS];
__device__ __nv_bfloat16 g_kh[OUT_ELEMS], g_kl[OUT_ELEMS];
__device__ __nv_bfloat16 g_vh[OUT_ELEMS], g_vl[OUT_ELEMS];
__device__ __nv_bfloat16 g_ctxh[OUT_ELEMS], g_ctxl[OUT_ELEMS];

// ==================== helpers ============================================
__device__ __forceinline__ void ldsm_x4(uint32_t (&r)[4], uint32_t addr) {
    asm volatile("ldmatrix.sync.aligned.m8n8.x4.shared.b16 {%0,%1,%2,%3}, [%4];"
                 : "=r"(r[0]), "=r"(r[1]), "=r"(r[2]), "=r"(r[3]) : "r"(addr));
}
__device__ __forceinline__ void ldsm_x4_t(uint32_t (&r)[4], uint32_t addr) {
    asm volatile("ldmatrix.sync.aligned.m8n8.x4.trans.shared.b16 {%0,%1,%2,%3}, [%4];"
                 : "=r"(r[0]), "=r"(r[1]), "=r"(r[2]), "=r"(r[3]) : "r"(addr));
}
__device__ __forceinline__ void mma16816(float (&c)[4], const uint32_t (&a)[4],
                                         uint32_t b0, uint32_t b1) {
    asm volatile(
        "mma.sync.aligned.m16n8k16.row.col.f32.bf16.bf16.f32 "
        "{%0,%1,%2,%3}, {%4,%5,%6,%7}, {%8,%9}, {%0,%1,%2,%3};"
        : "+f"(c[0]), "+f"(c[1]), "+f"(c[2]), "+f"(c[3])
        : "r"(a[0]), "r"(a[1]), "r"(a[2]), "r"(a[3]), "r"(b0), "r"(b1));
}
__device__ __forceinline__ uint32_t pack_hi(float x, float y) {
    __nv_bfloat162 h = __floats2bfloat162_rn(x, y);
    return *(uint32_t*)&h;
}
__device__ __forceinline__ void cp16(uint32_t dst, const void* src) {
    asm volatile("cp.async.cg.shared.global [%0], [%1], 16;" :: "r"(dst), "l"(src));
}
#define CP_COMMIT() asm volatile("cp.async.commit_group;")
#define CP_WAIT1()  asm volatile("cp.async.wait_group 1;" ::: "memory")

// ==================== split-bf16 conversion pass ==========================
__global__ __launch_bounds__(256)
void convert_split(const float* __restrict__ q, const float* __restrict__ k,
                   const float* __restrict__ v, const float* __restrict__ wq,
                   const float* __restrict__ wk, const float* __restrict__ wv,
                   const float* __restrict__ wo) {
    const int z = blockIdx.z;
    const float* src;
    __nv_bfloat16 *dh, *dl;
    int n4;
    if (z < 3) {
        src = (z == 0) ? q : (z == 1) ? k : v;
        dh = g_inh + (size_t)z * OUT_ELEMS;
        dl = g_inl + (size_t)z * OUT_ELEMS;
        n4 = OUT_ELEMS / 4;
    } else {
        src = (z == 3) ? wq : (z == 4) ? wk : (z == 5) ? wv : wo;
        dh = g_wh + (size_t)(z - 3) * W_ELEMS;
        dl = g_wl + (size_t)(z - 3) * W_ELEMS;
        n4 = W_ELEMS / 4;
    }
    int i = blockIdx.x * 256 + threadIdx.x;
    if (i >= n4) return;
    float4 x = ((const float4*)src)[i];
    float hx = __bfloat162float(__float2bfloat16_rn(x.x));
    float hy = __bfloat162float(__float2bfloat16_rn(x.y));
    float hz = __bfloat162float(__float2bfloat16_rn(x.z));
    float hw = __bfloat162float(__float2bfloat16_rn(x.w));
    uint2 oh = make_uint2(pack_hi(x.x, x.y), pack_hi(x.z, x.w));
    uint2 ol = make_uint2(pack_hi(x.x - hx, x.y - hy), pack_hi(x.z - hz, x.w - hw));
    *(uint2*)&dh[(size_t)i * 4] = oh;
    *(uint2*)&dl[(size_t)i * 4] = ol;
}

// ==================== shared GEMM body (cp.async pipelined) ===============
#define A_LD 40
#define B_LD 136
#define OFF_AH 0
#define OFF_AL (128 * A_LD)
#define OFF_BH (2 * 128 * A_LD)
#define OFF_BL (2 * 128 * A_LD + 32 * B_LD)
#define BUF_ELEMS (2 * 128 * A_LD + 2 * 32 * B_LD)      // 18944 bf16
#define GEMM_SMEM (2 * BUF_ELEMS * 2)                   // 75776 bytes

__device__ __forceinline__ void gemm_body(
    const __nv_bfloat16* __restrict__ AH, const __nv_bfloat16* __restrict__ AL,
    const __nv_bfloat16* __restrict__ WH, const __nv_bfloat16* __restrict__ WL,
    const float* __restrict__ bias, __nv_bfloat16* OH, __nv_bfloat16* OL,
    int bm, int bn) {
    extern __shared__ __align__(16) __nv_bfloat16 gsm[];

    const int tid = threadIdx.x;
    const int lane = tid & 31;
    const int warp = tid >> 5;
    const int wm = (warp & 3) * 32;
    const int wn = (warp >> 2) * 64;
    const int lr = lane & 15;
    const int lh = lane >> 4;

    const uint32_t smem_base = (uint32_t)__cvta_generic_to_shared(gsm);

    float acc[2][8][4];
#pragma unroll
    for (int i = 0; i < 2; ++i)
#pragma unroll
        for (int j = 0; j < 8; ++j)
#pragma unroll
            for (int r = 0; r < 4; ++r) acc[i][j][r] = 0.f;

    const int ar0 = tid >> 2, ao0 = (tid & 3) * 8;
    const int ar1 = (tid + 256) >> 2, ao1 = ((tid + 256) & 3) * 8;
    const int br0 = tid >> 4, bo0 = (tid & 15) * 8;
    const int br1 = (tid + 256) >> 4, bo1 = ((tid + 256) & 15) * 8;

#define ISSUE(bufi, k0)                                                        \
    do {                                                                       \
        uint32_t sb = smem_base + (bufi) * (BUF_ELEMS * 2);                    \
        cp16(sb + (OFF_AH + ar0 * A_LD + ao0) * 2,                             \
             AH + (size_t)(bm + ar0) * DMODEL + (k0) + ao0);                   \
        cp16(sb + (OFF_AH + ar1 * A_LD + ao1) * 2,                             \
             AH + (size_t)(bm + ar1) * DMODEL + (k0) + ao1);                   \
        cp16(sb + (OFF_AL + ar0 * A_LD + ao0) * 2,                             \
             AL + (size_t)(bm + ar0) * DMODEL + (k0) + ao0);                   \
        cp16(sb + (OFF_AL + ar1 * A_LD + ao1) * 2,                             \
             AL + (size_t)(bm + ar1) * DMODEL + (k0) + ao1);                   \
        cp16(sb + (OFF_BH + br0 * B_LD + bo0) * 2,                             \
             WH + (size_t)((k0) + br0) * DMODEL + bn + bo0);                   \
        cp16(sb + (OFF_BH + br1 * B_LD + bo1) * 2,                             \
             WH + (size_t)((k0) + br1) * DMODEL + bn + bo1);                   \
        cp16(sb + (OFF_BL + br0 * B_LD + bo0) * 2,                             \
             WL + (size_t)((k0) + br0) * DMODEL + bn + bo0);                   \
        cp16(sb + (OFF_BL + br1 * B_LD + bo1) * 2,                             \
             WL + (size_t)((k0) + br1) * DMODEL + bn + bo1);                   \
    } while (0)

    ISSUE(0, 0);
    CP_COMMIT();
    ISSUE(1, 32);
    CP_COMMIT();
    CP_WAIT1();
    __syncthreads();

    for (int c = 0; c < DMODEL / 32; ++c) {
        const int buf = c & 1;
        const __nv_bfloat16* Ah = gsm + buf * BUF_ELEMS + OFF_AH;
        const __nv_bfloat16* Al = gsm + buf * BUF_ELEMS + OFF_AL;
        const __nv_bfloat16* Bh = gsm + buf * BUF_ELEMS + OFF_BH;
        const __nv_bfloat16* Bl = gsm + buf * BUF_ELEMS + OFF_BL;
#pragma unroll
        for (int ks = 0; ks < 2; ++ks) {
            uint32_t afh[2][4], afl[2][4];
#pragma unroll
            for (int mt = 0; mt < 2; ++mt) {
                ldsm_x4(afh[mt], (uint32_t)__cvta_generic_to_shared(
                    &Ah[(wm + mt * 16 + lr) * A_LD + ks * 16 + lh * 8]));
                ldsm_x4(afl[mt], (uint32_t)__cvta_generic_to_shared(
                    &Al[(wm + mt * 16 + lr) * A_LD + ks * 16 + lh * 8]));
            }
#pragma unroll
            for (int np = 0; np < 4; ++np) {
                uint32_t bfh[4], bfl[4];
                ldsm_x4_t(bfh, (uint32_t)__cvta_generic_to_shared(
                    &Bh[(ks * 16 + lr) * B_LD + wn + np * 16 + lh * 8]));
                ldsm_x4_t(bfl, (uint32_t)__cvta_generic_to_shared(
                    &Bl[(ks * 16 + lr) * B_LD + wn + np * 16 + lh * 8]));
#pragma unroll
                for (int mt = 0; mt < 2; ++mt) {
                    mma16816(acc[mt][2 * np],     afh[mt], bfh[0], bfh[1]);
                    mma16816(acc[mt][2 * np],     afh[mt], bfl[0], bfl[1]);
                    mma16816(acc[mt][2 * np],     afl[mt], bfh[0], bfh[1]);
                    mma16816(acc[mt][2 * np + 1], afh[mt], bfh[2], bfh[3]);
                    mma16816(acc[mt][2 * np + 1], afh[mt], bfl[2], bfl[3]);
                    mma16816(acc[mt][2 * np + 1], afl[mt], bfh[2], bfh[3]);
                }
            }
        }
        __syncthreads();
        if (c + 2 < DMODEL / 32) {
            ISSUE(buf, (c + 2) * 32);
        }
        CP_COMMIT();
        CP_WAIT1();
        __syncthreads();
    }
#undef ISSUE

    const int gid = lane >> 2;
    const int qid = lane & 3;
#pragma unroll
    for (int mt = 0; mt < 2; ++mt) {
#pragma unroll
        for (int nt = 0; nt < 8; ++nt) {
            int col = bn + wn + nt * 8 + qid * 2;
            float bb0 = bias[col], bb1 = bias[col + 1];
            int r0 = bm + wm + mt * 16 + gid;
            float v00 = acc[mt][nt][0] + bb0, v01 = acc[mt][nt][1] + bb1;
            float v10 = acc[mt][nt][2] + bb0, v11 = acc[mt][nt][3] + bb1;
            if (OH) {
                size_t p0 = (size_t)r0 * DMODEL + col;
                size_t p1 = (size_t)(r0 + 8) * DMODEL + col;
                float h00 = __bfloat162float(__float2bfloat16_rn(v00));
                float h01 = __bfloat162float(__float2bfloat16_rn(v01));
                float h10 = __bfloat162float(__float2bfloat16_rn(v10));
                float h11 = __bfloat162float(__float2bfloat16_rn(v11));
                *(uint32_t*)&OH[p0] = pack_hi(v00, v01);
                *(uint32_t*)&OL[p0] = pack_hi(v00 - h00, v01 - h01);
                *(uint32_t*)&OH[p1] = pack_hi(v10, v11);
                *(uint32_t*)&OL[p1] = pack_hi(v10 - h10, v11 - h11);
            } else {
                *(float2*)&g_o[(size_t)r0 * DMODEL + col] = make_float2(v00, v01);
                *(float2*)&g_o[(size_t)(r0 + 8) * DMODEL + col] = make_float2(v10, v11);
            }
        }
    }
}

// ==================== QKV projection kernel ===============================
__global__ __launch_bounds__(256, 2)
void gemm_qkv(const float* __restrict__ b0p, const float* __restrict__ b1p,
              const float* __restrict__ b2p) {
    const int z = blockIdx.z;
    const __nv_bfloat16* AH = g_inh + (size_t)z * OUT_ELEMS;
    const __nv_bfloat16* AL = g_inl + (size_t)z * OUT_ELEMS;
    const __nv_bfloat16* WH = g_wh + (size_t)z * W_ELEMS;
    const __nv_bfloat16* WL = g_wl + (size_t)z * W_ELEMS;
    const float* bias = (z == 0) ? b0p : (z == 1) ? b1p : b2p;
    __nv_bfloat16* OH = (z == 0) ? g_qh : (z == 1) ? g_kh : g_vh;
    __nv_bfloat16* OL = (z == 0) ? g_ql : (z == 1) ? g_kl : g_vl;
    gemm_body(AH, AL, WH, WL, bias, OH, OL,
              blockIdx.y * 128, blockIdx.x * 128);
}

// ==================== fat kernel: Wo GEMM + attn rescale ==================
// Blocks [0,256): ctx @ Wo -> g_o.  Blocks [256, 256+NSCALE): attn /= rowsum.
__global__ __launch_bounds__(256, 2)
void wo_scale(const float* __restrict__ bo, float* __restrict__ attn) {
    if (blockIdx.x < 256) {
        gemm_body(g_ctxh, g_ctxl, g_wh + (size_t)3 * W_ELEMS,
                  g_wl + (size_t)3 * W_ELEMS, bo, nullptr, nullptr,
                  (blockIdx.x >> 3) * 128, (blockIdx.x & 7) * 128);
        return;
    }
    if (!attn) return;
    const size_t stride = (size_t)NSCALE * 256;          // float4 stride
    size_t i0 = (size_t)(blockIdx.x - 256) * 256 + threadIdx.x;
    float4* p = (float4*)attn;
    // ATTN_ELEMS/4 = 2*stride*32 exactly
#pragma unroll 1
    for (int it = 0; it < 32; ++it) {
        size_t i1 = i0 + (size_t)it * 2 * stride;
        size_t i2 = i1 + stride;
        float4 v1 = __ldcs(&p[i1]);
        float4 v2 = __ldcs(&p[i2]);
        float inv1 = 1.0f / g_rowsum[i1 >> 9];
        float inv2 = 1.0f / g_rowsum[i2 >> 9];
        v1.x *= inv1; v1.y *= inv1; v1.z *= inv1; v1.w *= inv1;
        v2.x *= inv2; v2.y *= inv2; v2.z *= inv2; v2.w *= inv2;
        __stcs(&p[i1], v1);
        __stcs(&p[i2], v2);
    }
}

// ==================== tensor-core attention v2 ============================
#define ALD 72
#define TILE_B (64 * ALD * 2)
#define TCA_SMEM (6 * TILE_B + 512 + 64)

__global__ __launch_bounds__(256, 2)
void attn_tc(float* __restrict__ gattn) {
    extern __shared__ __align__(16) char dsm[];
    __nv_bfloat16* Qh = (__nv_bfloat16*)dsm;
    __nv_bfloat16* Ql = (__nv_bfloat16*)(dsm + 1 * TILE_B);
    __nv_bfloat16* Kh = (__nv_bfloat16*)(dsm + 2 * TILE_B);
    __nv_bfloat16* Kl = (__nv_bfloat16*)(dsm + 3 * TILE_B);
    __nv_bfloat16* Vh = (__nv_bfloat16*)(dsm + 4 * TILE_B);
    __nv_bfloat16* Vl = (__nv_bfloat16*)(dsm + 5 * TILE_B);
    float* sPart = (float*)(dsm + 6 * TILE_B);
    float* red = (float*)(dsm + 2 * TILE_B);

    const int tid = threadIdx.x;
    const int lane = tid & 31;
    const int warp = tid >> 5;
    const int wy = warp & 3;
    const int wx = warp >> 2;
    const int lr = lane & 15;
    const int lh = lane >> 4;
    const int gid = lane >> 2;
    const int qid = lane & 3;

    const int q0 = blockIdx.x * 64;
    const int h = blockIdx.y;
    const int b = blockIdx.z;
    const size_t head_off = (size_t)b * SEQ * DMODEL + h * DHEAD;

    {
        const int row = tid >> 2;
        const int cg = (tid & 3) * 16;
        const size_t src = head_off + (size_t)(q0 + row) * DMODEL + cg;
        *(uint4*)&Qh[row * ALD + cg]     = *(const uint4*)&g_qh[src];
        *(uint4*)&Qh[row * ALD + cg + 8] = *(const uint4*)&g_qh[src + 8];
        *(uint4*)&Ql[row * ALD + cg]     = *(const uint4*)&g_ql[src];
        *(uint4*)&Ql[row * ALD + cg + 8] = *(const uint4*)&g_ql[src + 8];
    }

    float ctx[8][4];
#pragma unroll
    for (int j = 0; j < 8; ++j)
#pragma unroll
        for (int r = 0; r < 4; ++r) ctx[j][r] = 0.f;
    float psum0 = 0.f, psum1 = 0.f;

    const int row0 = wy * 16 + gid;
    const size_t arow0 = (size_t)((b * NHEAD + h) * SEQ + q0 + row0);

    for (int kc = 0; kc < SEQ; kc += 64) {
        __syncthreads();
        {
            const int row = tid >> 2;
            const int cg = (tid & 3) * 16;
            const size_t src = head_off + (size_t)(kc + row) * DMODEL + cg;
            *(uint4*)&Kh[row * ALD + cg]     = *(const uint4*)&g_kh[src];
            *(uint4*)&Kh[row * ALD + cg + 8] = *(const uint4*)&g_kh[src + 8];
            *(uint4*)&Kl[row * ALD + cg]     = *(const uint4*)&g_kl[src];
            *(uint4*)&Kl[row * ALD + cg + 8] = *(const uint4*)&g_kl[src + 8];
            *(uint4*)&Vh[row * ALD + cg]     = *(const uint4*)&g_vh[src];
            *(uint4*)&Vh[row * ALD + cg + 8] = *(const uint4*)&g_vh[src + 8];
            *(uint4*)&Vl[row * ALD + cg]     = *(const uint4*)&g_vl[src];
            *(uint4*)&Vl[row * ALD + cg + 8] = *(const uint4*)&g_vl[src + 8];
        }
        __syncthreads();

        float s[4][4];
#pragma unroll
        for (int j = 0; j < 4; ++j)
#pragma unroll
            for (int r = 0; r < 4; ++r) s[j][r] = 0.f;

#pragma unroll
        for (int ks = 0; ks < 4; ++ks) {
            uint32_t aQh[4], aQl[4];
            ldsm_x4(aQh, (uint32_t)__cvta_generic_to_shared(
                &Qh[(wy * 16 + lr) * ALD + ks * 16 + lh * 8]));
            ldsm_x4(aQl, (uint32_t)__cvta_generic_to_shared(
                &Ql[(wy * 16 + lr) * ALD + ks * 16 + lh * 8]));
            uint32_t bKh[2][4], bKl[2][4];
            const int mat = lane >> 3, rr = lane & 7;
            const int keyo = (mat >> 1) * 8 + rr;
            const int dof = (mat & 1) * 8 + ks * 16;
#pragma unroll
            for (int g = 0; g < 2; ++g) {
                int key = wx * 32 + g * 16 + keyo;
                ldsm_x4(bKh[g], (uint32_t)__cvta_generic_to_shared(
                    &Kh[key * ALD + dof]));
                ldsm_x4(bKl[g], (uint32_t)__cvta_generic_to_shared(
                    &Kl[key * ALD + dof]));
            }
#pragma unroll
            for (int j = 0; j < 4; ++j) {
                const int g = j >> 1, p = (j & 1) * 2;
                mma16816(s[j], aQh, bKh[g][p], bKh[g][p + 1]);
                mma16816(s[j], aQh, bKl[g][p], bKl[g][p + 1]);
                mma16816(s[j], aQl, bKh[g][p], bKh[g][p + 1]);
            }
        }

        uint32_t aPh[2][4], aPl[2][4];
#pragma unroll
        for (int j = 0; j < 4; ++j) {
            float e0 = __expf(s[j][0] * 0.125f);
            float e1 = __expf(s[j][1] * 0.125f);
            float e2 = __expf(s[j][2] * 0.125f);
            float e3 = __expf(s[j][3] * 0.125f);
            psum0 += e0 + e1;
            psum1 += e2 + e3;
            const int col = wx * 32 + j * 8 + qid * 2;
            if (gattn) {
                __stcs((float2*)&gattn[arow0 * SEQ + kc + col], make_float2(e0, e1));
                __stcs((float2*)&gattn[(arow0 + 8) * SEQ + kc + col], make_float2(e2, e3));
            }
            float l0 = e0 - __bfloat162float(__float2bfloat16_rn(e0));
            float l1 = e1 - __bfloat162float(__float2bfloat16_rn(e1));
            float l2 = e2 - __bfloat162float(__float2bfloat16_rn(e2));
            float l3 = e3 - __bfloat162float(__float2bfloat16_rn(e3));
            const int t = j >> 1, half = j & 1;
            aPh[t][half * 2 + 0] = pack_hi(e0, e1);
            aPh[t][half * 2 + 1] = pack_hi(e2, e3);
            aPl[t][half * 2 + 0] = pack_hi(l0, l1);
            aPl[t][half * 2 + 1] = pack_hi(l2, l3);
        }

#pragma unroll
        for (int t = 0; t < 2; ++t) {
            const int kb = wx * 32 + t * 16;
#pragma unroll
            for (int np = 0; np < 4; ++np) {
                uint32_t bVh[4], bVl[4];
                ldsm_x4_t(bVh, (uint32_t)__cvta_generic_to_shared(
                    &Vh[(kb + lr) * ALD + np * 16 + lh * 8]));
                ldsm_x4_t(bVl, (uint32_t)__cvta_generic_to_shared(
                    &Vl[(kb + lr) * ALD + np * 16 + lh * 8]));
                mma16816(ctx[2 * np],     aPh[t], bVh[0], bVh[1]);
                mma16816(ctx[2 * np],     aPh[t], bVl[0], bVl[1]);
                mma16816(ctx[2 * np],     aPl[t], bVh[0], bVh[1]);
                mma16816(ctx[2 * np + 1], aPh[t], bVh[2], bVh[3]);
                mma16816(ctx[2 * np + 1], aPh[t], bVl[2], bVl[3]);
                mma16816(ctx[2 * np + 1], aPl[t], bVh[2], bVh[3]);
            }
        }
    }

    psum0 += __shfl_xor_sync(0xffffffffu, psum0, 1);
    psum0 += __shfl_xor_sync(0xffffffffu, psum0, 2);
    psum1 += __shfl_xor_sync(0xffffffffu, psum1, 1);
    psum1 += __shfl_xor_sync(0xffffffffu, psum1, 2);
    __syncthreads();
    if (qid == 0) {
        sPart[wx * 64 + row0] = psum0;
        sPart[wx * 64 + row0 + 8] = psum1;
    }
    if (wx == 1) {
#pragma unroll
        for (int j = 0; j < 8; ++j) {
            *(float2*)&red[row0 * 68 + j * 8 + qid * 2] =
                make_float2(ctx[j][0], ctx[j][1]);
            *(float2*)&red[(row0 + 8) * 68 + j * 8 + qid * 2] =
                make_float2(ctx[j][2], ctx[j][3]);
        }
    }
    __syncthreads();
    if (wx == 0) {
        float tot0 = sPart[row0] + sPart[64 + row0];
        float tot1 = sPart[row0 + 8] + sPart[64 + row0 + 8];
        if (qid == 0) {
            g_rowsum[arow0] = tot0;
            g_rowsum[arow0 + 8] = tot1;
        }
        float inv0 = 1.0f / tot0, inv1 = 1.0f / tot1;
#pragma unroll
        for (int j = 0; j < 8; ++j) {
            const int col = j * 8 + qid * 2;
            float2 o0 = *(float2*)&red[row0 * 68 + col];
            float2 o1 = *(float2*)&red[(row0 + 8) * 68 + col];
            o0.x = (ctx[j][0] + o0.x) * inv0;
            o0.y = (ctx[j][1] + o0.y) * inv0;
            o1.x = (ctx[j][2] + o1.x) * inv1;
            o1.y = (ctx[j][3] + o1.y) * inv1;
            size_t p0 = (size_t)(b * SEQ + q0 + row0) * DMODEL + h * DHEAD + col;
            size_t p1 = (size_t)(b * SEQ + q0 + row0 + 8) * DMODEL + h * DHEAD + col;
            float h0x = __bfloat162float(__float2bfloat16_rn(o0.x));
            float h0y = __bfloat162float(__float2bfloat16_rn(o0.y));
            float h1x = __bfloat162float(__float2bfloat16_rn(o1.x));
            float h1y = __bfloat162float(__float2bfloat16_rn(o1.y));
            *(uint32_t*)&g_ctxh[p0] = pack_hi(o0.x, o0.y);
            *(uint32_t*)&g_ctxl[p0] = pack_hi(o0.x - h0x, o0.y - h0y);
            *(uint32_t*)&g_ctxh[p1] = pack_hi(o1.x, o1.y);
            *(uint32_t*)&g_ctxl[p1] = pack_hi(o1.x - h1x, o1.y - h1y);
        }
    }
}

// -------------------- LayerNorm ------------------------------------------
__global__ __launch_bounds__(256)
void ln_kernel(const float* __restrict__ gamma, const float* __restrict__ beta,
               float* __restrict__ out) {
    const int row = blockIdx.x;
    const int tid = threadIdx.x;
    __shared__ float red[8];

    float4 x = *(const float4*)&g_o[(size_t)row * DMODEL + tid * 4];
    float s = (x.x + x.y) + (x.z + x.w);
#pragma unroll
    for (int off = 16; off; off >>= 1) s += __shfl_xor_sync(0xffffffffu, s, off);
    if ((tid & 31) == 0) red[tid >> 5] = s;
    __syncthreads();
    float tot = 0.f;
#pragma unroll
    for (int i = 0; i < 8; ++i) tot += red[i];
    float mean = tot * (1.0f / 1024.0f);
    __syncthreads();

    float4 dx = make_float4(x.x - mean, x.y - mean, x.z - mean, x.w - mean);
    float ss = dx.x * dx.x + dx.y * dx.y + dx.z * dx.z + dx.w * dx.w;
#pragma unroll
    for (int off = 16; off; off >>= 1) ss += __shfl_xor_sync(0xffffffffu, ss, off);
    if ((tid & 31) == 0) red[tid >> 5] = ss;
    __syncthreads();
    float tss = 0.f;
#pragma unroll
    for (int i = 0; i < 8; ++i) tss += red[i];
    float var = tss * (1.0f / 1024.0f);
    float rstd = rsqrtf(var + 1e-3f);

    float4 g = *(const float4*)&gamma[tid * 4];
    float4 be = *(const float4*)&beta[tid * 4];
    float4 o;
    o.x = dx.x * rstd * g.x + be.x;
    o.y = dx.y * rstd * g.y + be.y;
    o.z = dx.z * rstd * g.z + be.z;
    o.w = dx.w * rstd * g.w + be.w;
    *(float4*)&out[(size_t)row * DMODEL + tid * 4] = o;
}

// -------------------- launcher --------------------------------------------
extern "C" void kernel_launch(void* const* d_in, const int* in_sizes, int n_in,
                              void* d_out, int out_size) {
    const float* query = (const float*)d_in[0];
    const float* key   = (const float*)d_in[1];
    const float* value = (const float*)d_in[2];
    const float* Wq = (const float*)d_in[3];
    const float* bq = (const float*)d_in[4];
    const float* Wk = (const float*)d_in[5];
    const float* bk = (const float*)d_in[6];
    const float* Wv = (const float*)d_in[7];
    const float* bv = (const float*)d_in[8];
    const float* Wo = (const float*)d_in[9];
    const float* bo = (const float*)d_in[10];
    const float* gamma = (const float*)d_in[11];
    const float* beta  = (const float*)d_in[12];

    float* out = (float*)d_out;
    float* attn = (out_size >= OUT_ELEMS + ATTN_ELEMS) ? (out + OUT_ELEMS) : nullptr;

    cudaFuncSetAttribute(attn_tc, cudaFuncAttributeMaxDynamicSharedMemorySize,
                         TCA_SMEM);
    cudaFuncSetAttribute(gemm_qkv, cudaFuncAttributeMaxDynamicSharedMemorySize,
                         GEMM_SMEM);
    cudaFuncSetAttribute(wo_scale, cudaFuncAttributeMaxDynamicSharedMemorySize,
                         GEMM_SMEM);

    convert_split<<<dim3(OUT_ELEMS / 4 / 256, 1, 7), 256>>>(query, key, value,
                                                            Wq, Wk, Wv, Wo);

    gemm_qkv<<<dim3(DMODEL / 128, NROWS / 128, 3), 256, GEMM_SMEM>>>(bq, bk, bv);

    attn_tc<<<dim3(SEQ / 64, NHEAD, BATCH), 256, TCA_SMEM>>>(attn);

    wo_scale<<<256 + NSCALE, 256, GEMM_SMEM>>>(bo, attn);

    ln_kernel<<<NROWS, 256>>>(gamma, beta, out);
}

// round 10
// speedup vs baseline: 1.5767x; 1.5767x over previous
#include <cuda_runtime.h>
#include <cuda_bf16.h>
#include <math.h>
#include <stdint.h>

// Problem constants
#define SEQ   2048
#define BATCH 2
#define DMODEL 1024
#define NHEAD 16
#define DHEAD 64
#define NROWS (BATCH * SEQ)          // 4096
#define OUT_ELEMS   (NROWS * DMODEL)             // 4,194,304
#define W_ELEMS (DMODEL * DMODEL)                // 1,048,576
#define ATTN_ELEMS  (BATCH * NHEAD * SEQ * SEQ)  // 134,217,728

// -------------------- device scratch (no allocations allowed) ------------
__device__ float g_o[NROWS * DMODEL];
__device__ float g_rowsum[BATCH * NHEAD * SEQ];
__device__ __nv_bfloat16 g_inh[3 * OUT_ELEMS];
__device__ __nv_bfloat16 g_inl[3 * OUT_ELEMS];
__device__ __nv_bfloat16 g_wh[4 * W_ELEMS];
__device__ __nv_bfloat16 g_wl[4 * W_ELEMS];
__device__ __nv_bfloat16 g_qh[OUT_ELEMS], g_ql[OUT_ELEMS];
__device__ __nv_bfloat16 g_kh[OUT_ELEMS], g_kl[OUT_ELEMS];
__device__ __nv_bfloat16 g_vh[OUT_ELEMS], g_vl[OUT_ELEMS];
__device__ __nv_bfloat16 g_ctxh[OUT_ELEMS], g_ctxl[OUT_ELEMS];

// ==================== helpers ============================================
__device__ __forceinline__ void ldsm_x4(uint32_t (&r)[4], uint32_t addr) {
    asm volatile("ldmatrix.sync.aligned.m8n8.x4.shared.b16 {%0,%1,%2,%3}, [%4];"
                 : "=r"(r[0]), "=r"(r[1]), "=r"(r[2]), "=r"(r[3]) : "r"(addr));
}
__device__ __forceinline__ void ldsm_x4_t(uint32_t (&r)[4], uint32_t addr) {
    asm volatile("ldmatrix.sync.aligned.m8n8.x4.trans.shared.b16 {%0,%1,%2,%3}, [%4];"
                 : "=r"(r[0]), "=r"(r[1]), "=r"(r[2]), "=r"(r[3]) : "r"(addr));
}
__device__ __forceinline__ void mma16816(float (&c)[4], const uint32_t (&a)[4],
                                         uint32_t b0, uint32_t b1) {
    asm volatile(
        "mma.sync.aligned.m16n8k16.row.col.f32.bf16.bf16.f32 "
        "{%0,%1,%2,%3}, {%4,%5,%6,%7}, {%8,%9}, {%0,%1,%2,%3};"
        : "+f"(c[0]), "+f"(c[1]), "+f"(c[2]), "+f"(c[3])
        : "r"(a[0]), "r"(a[1]), "r"(a[2]), "r"(a[3]), "r"(b0), "r"(b1));
}
__device__ __forceinline__ uint32_t pack_hi(float x, float y) {
    __nv_bfloat162 h = __floats2bfloat162_rn(x, y);
    return *(uint32_t*)&h;
}
__device__ __forceinline__ void cp16(uint32_t dst, const void* src) {
    asm volatile("cp.async.cg.shared.global [%0], [%1], 16;" :: "r"(dst), "l"(src));
}
#define CP_COMMIT() asm volatile("cp.async.commit_group;")
#define CP_WAIT1()  asm volatile("cp.async.wait_group 1;" ::: "memory")

// ==================== split-bf16 conversion pass ==========================
__global__ __launch_bounds__(256)
void convert_split(const float* __restrict__ q, const float* __restrict__ k,
                   const float* __restrict__ v, const float* __restrict__ wq,
                   const float* __restrict__ wk, const float* __restrict__ wv,
                   const float* __restrict__ wo) {
    const int z = blockIdx.z;
    const float* src;
    __nv_bfloat16 *dh, *dl;
    int n4;
    if (z < 3) {
        src = (z == 0) ? q : (z == 1) ? k : v;
        dh = g_inh + (size_t)z * OUT_ELEMS;
        dl = g_inl + (size_t)z * OUT_ELEMS;
        n4 = OUT_ELEMS / 4;
    } else {
        src = (z == 3) ? wq : (z == 4) ? wk : (z == 5) ? wv : wo;
        dh = g_wh + (size_t)(z - 3) * W_ELEMS;
        dl = g_wl + (size_t)(z - 3) * W_ELEMS;
        n4 = W_ELEMS / 4;
    }
    int i = blockIdx.x * 256 + threadIdx.x;
    if (i >= n4) return;
    float4 x = ((const float4*)src)[i];
    float hx = __bfloat162float(__float2bfloat16_rn(x.x));
    float hy = __bfloat162float(__float2bfloat16_rn(x.y));
    float hz = __bfloat162float(__float2bfloat16_rn(x.z));
    float hw = __bfloat162float(__float2bfloat16_rn(x.w));
    uint2 oh = make_uint2(pack_hi(x.x, x.y), pack_hi(x.z, x.w));
    uint2 ol = make_uint2(pack_hi(x.x - hx, x.y - hy), pack_hi(x.z - hz, x.w - hw));
    *(uint2*)&dh[(size_t)i * 4] = oh;
    *(uint2*)&dl[(size_t)i * 4] = ol;
}

// ==================== shared GEMM body (cp.async pipelined) ===============
#define A_LD 40
#define B_LD 136
#define OFF_AH 0
#define OFF_AL (128 * A_LD)
#define OFF_BH (2 * 128 * A_LD)
#define OFF_BL (2 * 128 * A_LD + 32 * B_LD)
#define BUF_ELEMS (2 * 128 * A_LD + 2 * 32 * B_LD)      // 18944 bf16
#define GEMM_SMEM (2 * BUF_ELEMS * 2)                   // 75776 bytes

__device__ __forceinline__ void gemm_body(
    const __nv_bfloat16* __restrict__ AH, const __nv_bfloat16* __restrict__ AL,
    const __nv_bfloat16* __restrict__ WH, const __nv_bfloat16* __restrict__ WL,
    const float* __restrict__ bias, __nv_bfloat16* OH, __nv_bfloat16* OL,
    int bm, int bn) {
    extern __shared__ __align__(16) __nv_bfloat16 gsm[];

    const int tid = threadIdx.x;
    const int lane = tid & 31;
    const int warp = tid >> 5;
    const int wm = (warp & 3) * 32;
    const int wn = (warp >> 2) * 64;
    const int lr = lane & 15;
    const int lh = lane >> 4;

    const uint32_t smem_base = (uint32_t)__cvta_generic_to_shared(gsm);

    float acc[2][8][4];
#pragma unroll
    for (int i = 0; i < 2; ++i)
#pragma unroll
        for (int j = 0; j < 8; ++j)
#pragma unroll
            for (int r = 0; r < 4; ++r) acc[i][j][r] = 0.f;

    const int ar0 = tid >> 2, ao0 = (tid & 3) * 8;
    const int ar1 = (tid + 256) >> 2, ao1 = ((tid + 256) & 3) * 8;
    const int br0 = tid >> 4, bo0 = (tid & 15) * 8;
    const int br1 = (tid + 256) >> 4, bo1 = ((tid + 256) & 15) * 8;

#define ISSUE(bufi, k0)                                                        \
    do {                                                                       \
        uint32_t sb = smem_base + (bufi) * (BUF_ELEMS * 2);                    \
        cp16(sb + (OFF_AH + ar0 * A_LD + ao0) * 2,                             \
             AH + (size_t)(bm + ar0) * DMODEL + (k0) + ao0);                   \
        cp16(sb + (OFF_AH + ar1 * A_LD + ao1) * 2,                             \
             AH + (size_t)(bm + ar1) * DMODEL + (k0) + ao1);                   \
        cp16(sb + (OFF_AL + ar0 * A_LD + ao0) * 2,                             \
             AL + (size_t)(bm + ar0) * DMODEL + (k0) + ao0);                   \
        cp16(sb + (OFF_AL + ar1 * A_LD + ao1) * 2,                             \
             AL + (size_t)(bm + ar1) * DMODEL + (k0) + ao1);                   \
        cp16(sb + (OFF_BH + br0 * B_LD + bo0) * 2,                             \
             WH + (size_t)((k0) + br0) * DMODEL + bn + bo0);                   \
        cp16(sb + (OFF_BH + br1 * B_LD + bo1) * 2,                             \
             WH + (size_t)((k0) + br1) * DMODEL + bn + bo1);                   \
        cp16(sb + (OFF_BL + br0 * B_LD + bo0) * 2,                             \
             WL + (size_t)((k0) + br0) * DMODEL + bn + bo0);                   \
        cp16(sb + (OFF_BL + br1 * B_LD + bo1) * 2,                             \
             WL + (size_t)((k0) + br1) * DMODEL + bn + bo1);                   \
    } while (0)

    ISSUE(0, 0);
    CP_COMMIT();
    ISSUE(1, 32);
    CP_COMMIT();
    CP_WAIT1();
    __syncthreads();

    for (int c = 0; c < DMODEL / 32; ++c) {
        const int buf = c & 1;
        const __nv_bfloat16* Ah = gsm + buf * BUF_ELEMS + OFF_AH;
        const __nv_bfloat16* Al = gsm + buf * BUF_ELEMS + OFF_AL;
        const __nv_bfloat16* Bh = gsm + buf * BUF_ELEMS + OFF_BH;
        const __nv_bfloat16* Bl = gsm + buf * BUF_ELEMS + OFF_BL;
#pragma unroll
        for (int ks = 0; ks < 2; ++ks) {
            uint32_t afh[2][4], afl[2][4];
#pragma unroll
            for (int mt = 0; mt < 2; ++mt) {
                ldsm_x4(afh[mt], (uint32_t)__cvta_generic_to_shared(
                    &Ah[(wm + mt * 16 + lr) * A_LD + ks * 16 + lh * 8]));
                ldsm_x4(afl[mt], (uint32_t)__cvta_generic_to_shared(
                    &Al[(wm + mt * 16 + lr) * A_LD + ks * 16 + lh * 8]));
            }
#pragma unroll
            for (int np = 0; np < 4; ++np) {
                uint32_t bfh[4], bfl[4];
                ldsm_x4_t(bfh, (uint32_t)__cvta_generic_to_shared(
                    &Bh[(ks * 16 + lr) * B_LD + wn + np * 16 + lh * 8]));
                ldsm_x4_t(bfl, (uint32_t)__cvta_generic_to_shared(
                    &Bl[(ks * 16 + lr) * B_LD + wn + np * 16 + lh * 8]));
#pragma unroll
                for (int mt = 0; mt < 2; ++mt) {
                    mma16816(acc[mt][2 * np],     afh[mt], bfh[0], bfh[1]);
                    mma16816(acc[mt][2 * np],     afh[mt], bfl[0], bfl[1]);
                    mma16816(acc[mt][2 * np],     afl[mt], bfh[0], bfh[1]);
                    mma16816(acc[mt][2 * np + 1], afh[mt], bfh[2], bfh[3]);
                    mma16816(acc[mt][2 * np + 1], afh[mt], bfl[2], bfl[3]);
                    mma16816(acc[mt][2 * np + 1], afl[mt], bfh[2], bfh[3]);
                }
            }
        }
        __syncthreads();
        if (c + 2 < DMODEL / 32) {
            ISSUE(buf, (c + 2) * 32);
        }
        CP_COMMIT();
        CP_WAIT1();
        __syncthreads();
    }
#undef ISSUE

    const int gid = lane >> 2;
    const int qid = lane & 3;
#pragma unroll
    for (int mt = 0; mt < 2; ++mt) {
#pragma unroll
        for (int nt = 0; nt < 8; ++nt) {
            int col = bn + wn + nt * 8 + qid * 2;
            float bb0 = bias[col], bb1 = bias[col + 1];
            int r0 = bm + wm + mt * 16 + gid;
            float v00 = acc[mt][nt][0] + bb0, v01 = acc[mt][nt][1] + bb1;
            float v10 = acc[mt][nt][2] + bb0, v11 = acc[mt][nt][3] + bb1;
            if (OH) {
                size_t p0 = (size_t)r0 * DMODEL + col;
                size_t p1 = (size_t)(r0 + 8) * DMODEL + col;
                float h00 = __bfloat162float(__float2bfloat16_rn(v00));
                float h01 = __bfloat162float(__float2bfloat16_rn(v01));
                float h10 = __bfloat162float(__float2bfloat16_rn(v10));
                float h11 = __bfloat162float(__float2bfloat16_rn(v11));
                *(uint32_t*)&OH[p0] = pack_hi(v00, v01);
                *(uint32_t*)&OL[p0] = pack_hi(v00 - h00, v01 - h01);
                *(uint32_t*)&OH[p1] = pack_hi(v10, v11);
                *(uint32_t*)&OL[p1] = pack_hi(v10 - h10, v11 - h11);
            } else {
                *(float2*)&g_o[(size_t)r0 * DMODEL + col] = make_float2(v00, v01);
                *(float2*)&g_o[(size_t)(r0 + 8) * DMODEL + col] = make_float2(v10, v11);
            }
        }
    }
}

__global__ __launch_bounds__(256, 2)
void gemm_qkv(const float* __restrict__ b0p, const float* __restrict__ b1p,
              const float* __restrict__ b2p) {
    const int z = blockIdx.z;
    const __nv_bfloat16* AH = g_inh + (size_t)z * OUT_ELEMS;
    const __nv_bfloat16* AL = g_inl + (size_t)z * OUT_ELEMS;
    const __nv_bfloat16* WH = g_wh + (size_t)z * W_ELEMS;
    const __nv_bfloat16* WL = g_wl + (size_t)z * W_ELEMS;
    const float* bias = (z == 0) ? b0p : (z == 1) ? b1p : b2p;
    __nv_bfloat16* OH = (z == 0) ? g_qh : (z == 1) ? g_kh : g_vh;
    __nv_bfloat16* OL = (z == 0) ? g_ql : (z == 1) ? g_kl : g_vl;
    gemm_body(AH, AL, WH, WL, bias, OH, OL,
              blockIdx.y * 128, blockIdx.x * 128);
}

__global__ __launch_bounds__(256, 2)
void gemm_wo(const float* __restrict__ bo) {
    gemm_body(g_ctxh, g_ctxl, g_wh + (size_t)3 * W_ELEMS,
              g_wl + (size_t)3 * W_ELEMS, bo, nullptr, nullptr,
              blockIdx.y * 128, blockIdx.x * 128);
}

// ==================== tensor-core attention v3 (cp.async K/V) =============
// smem: Qh,Ql (2 tiles) + KV ring [2 bufs][Kh,Kl,Vh,Vl] (8 tiles) + sPart.
#define ALD 72
#define TILE_B (64 * ALD * 2)                 // 9216 bytes
#define KV_OFF (2 * TILE_B)
#define TCA_SMEM (10 * TILE_B + 576)

__global__ __launch_bounds__(256, 2)
void attn_tc(float* __restrict__ gattn) {
    extern __shared__ __align__(16) char dsm[];
    __nv_bfloat16* Qh = (__nv_bfloat16*)dsm;
    __nv_bfloat16* Ql = (__nv_bfloat16*)(dsm + TILE_B);
    float* sPart = (float*)(dsm + 10 * TILE_B);
    float* red = (float*)(dsm + KV_OFF);      // aliases KV buf0 (post-loop)

    const int tid = threadIdx.x;
    const int lane = tid & 31;
    const int warp = tid >> 5;
    const int wy = warp & 3;
    const int wx = warp >> 2;
    const int lr = lane & 15;
    const int lh = lane >> 4;
    const int gid = lane >> 2;
    const int qid = lane & 3;

    const int q0 = blockIdx.x * 64;
    const int h = blockIdx.y;
    const int b = blockIdx.z;
    const size_t head_off = (size_t)b * SEQ * DMODEL + h * DHEAD;

    const uint32_t smem_base = (uint32_t)__cvta_generic_to_shared(dsm);

    // cp.async coords: tile has 512 16B-chunks; thread does chunks tid, tid+256
    const int r0c = tid >> 3, o0c = (tid & 7) * 8;
    const int r1c = 32 + (tid >> 3), o1c = (tid & 7) * 8;

#define KV_ISSUE(bufi, kc)                                                     \
    do {                                                                       \
        uint32_t sb = smem_base + KV_OFF + (bufi) * (4 * TILE_B);              \
        const size_t s0 = head_off + (size_t)((kc) + r0c) * DMODEL;            \
        const size_t s1 = head_off + (size_t)((kc) + r1c) * DMODEL;            \
        cp16(sb + 0 * TILE_B + (r0c * ALD + o0c) * 2, g_kh + s0 + o0c);        \
        cp16(sb + 0 * TILE_B + (r1c * ALD + o1c) * 2, g_kh + s1 + o1c);        \
        cp16(sb + 1 * TILE_B + (r0c * ALD + o0c) * 2, g_kl + s0 + o0c);        \
        cp16(sb + 1 * TILE_B + (r1c * ALD + o1c) * 2, g_kl + s1 + o1c);        \
        cp16(sb + 2 * TILE_B + (r0c * ALD + o0c) * 2, g_vh + s0 + o0c);        \
        cp16(sb + 2 * TILE_B + (r1c * ALD + o1c) * 2, g_vh + s1 + o1c);        \
        cp16(sb + 3 * TILE_B + (r0c * ALD + o0c) * 2, g_vl + s0 + o0c);        \
        cp16(sb + 3 * TILE_B + (r1c * ALD + o1c) * 2, g_vl + s1 + o1c);        \
    } while (0)

    // Q tile load (regular stores)
    {
        const int row = tid >> 2;
        const int cg = (tid & 3) * 16;
        const size_t src = head_off + (size_t)(q0 + row) * DMODEL + cg;
        *(uint4*)&Qh[row * ALD + cg]     = *(const uint4*)&g_qh[src];
        *(uint4*)&Qh[row * ALD + cg + 8] = *(const uint4*)&g_qh[src + 8];
        *(uint4*)&Ql[row * ALD + cg]     = *(const uint4*)&g_ql[src];
        *(uint4*)&Ql[row * ALD + cg + 8] = *(const uint4*)&g_ql[src + 8];
    }

    KV_ISSUE(0, 0);
    CP_COMMIT();
    KV_ISSUE(1, 64);
    CP_COMMIT();
    CP_WAIT1();
    __syncthreads();

    float ctx[8][4];
#pragma unroll
    for (int j = 0; j < 8; ++j)
#pragma unroll
        for (int r = 0; r < 4; ++r) ctx[j][r] = 0.f;
    float psum0 = 0.f, psum1 = 0.f;

    const int row0 = wy * 16 + gid;
    const size_t arow0 = (size_t)((b * NHEAD + h) * SEQ + q0 + row0);

    for (int c = 0; c < SEQ / 64; ++c) {
        const int buf = c & 1;
        const int kc = c * 64;
        __nv_bfloat16* Kh = (__nv_bfloat16*)(dsm + KV_OFF + buf * 4 * TILE_B);
        __nv_bfloat16* Kl = Kh + 64 * ALD;
        __nv_bfloat16* Vh = Kl + 64 * ALD;
        __nv_bfloat16* Vl = Vh + 64 * ALD;

        // ---- S = Q K^T ----
        float s[4][4];
#pragma unroll
        for (int j = 0; j < 4; ++j)
#pragma unroll
            for (int r = 0; r < 4; ++r) s[j][r] = 0.f;

#pragma unroll
        for (int ks = 0; ks < 4; ++ks) {
            uint32_t aQh[4], aQl[4];
            ldsm_x4(aQh, (uint32_t)__cvta_generic_to_shared(
                &Qh[(wy * 16 + lr) * ALD + ks * 16 + lh * 8]));
            ldsm_x4(aQl, (uint32_t)__cvta_generic_to_shared(
                &Ql[(wy * 16 + lr) * ALD + ks * 16 + lh * 8]));
            uint32_t bKh[2][4], bKl[2][4];
            const int mat = lane >> 3, rr = lane & 7;
            const int keyo = (mat >> 1) * 8 + rr;
            const int dof = (mat & 1) * 8 + ks * 16;
#pragma unroll
            for (int g = 0; g < 2; ++g) {
                int key = wx * 32 + g * 16 + keyo;
                ldsm_x4(bKh[g], (uint32_t)__cvta_generic_to_shared(
                    &Kh[key * ALD + dof]));
                ldsm_x4(bKl[g], (uint32_t)__cvta_generic_to_shared(
                    &Kl[key * ALD + dof]));
            }
#pragma unroll
            for (int j = 0; j < 4; ++j) {
                const int g = j >> 1, p = (j & 1) * 2;
                mma16816(s[j], aQh, bKh[g][p], bKh[g][p + 1]);
                mma16816(s[j], aQh, bKl[g][p], bKl[g][p + 1]);
                mma16816(s[j], aQl, bKh[g][p], bKh[g][p + 1]);
            }
        }

        // ---- exp, rowsum, attn store; P A-frags in registers ----
        uint32_t aPh[2][4], aPl[2][4];
#pragma unroll
        for (int j = 0; j < 4; ++j) {
            float e0 = __expf(s[j][0] * 0.125f);
            float e1 = __expf(s[j][1] * 0.125f);
            float e2 = __expf(s[j][2] * 0.125f);
            float e3 = __expf(s[j][3] * 0.125f);
            psum0 += e0 + e1;
            psum1 += e2 + e3;
            const int col = wx * 32 + j * 8 + qid * 2;
            if (gattn) {
                __stcs((float2*)&gattn[arow0 * SEQ + kc + col], make_float2(e0, e1));
                __stcs((float2*)&gattn[(arow0 + 8) * SEQ + kc + col], make_float2(e2, e3));
            }
            float l0 = e0 - __bfloat162float(__float2bfloat16_rn(e0));
            float l1 = e1 - __bfloat162float(__float2bfloat16_rn(e1));
            float l2 = e2 - __bfloat162float(__float2bfloat16_rn(e2));
            float l3 = e3 - __bfloat162float(__float2bfloat16_rn(e3));
            const int t = j >> 1, half = j & 1;
            aPh[t][half * 2 + 0] = pack_hi(e0, e1);
            aPh[t][half * 2 + 1] = pack_hi(e2, e3);
            aPl[t][half * 2 + 0] = pack_hi(l0, l1);
            aPl[t][half * 2 + 1] = pack_hi(l2, l3);
        }

        // ---- ctx += P V over this warp's 32-key slice ----
#pragma unroll
        for (int t = 0; t < 2; ++t) {
            const int kb = wx * 32 + t * 16;
#pragma unroll
            for (int np = 0; np < 4; ++np) {
                uint32_t bVh[4], bVl[4];
                ldsm_x4_t(bVh, (uint32_t)__cvta_generic_to_shared(
                    &Vh[(kb + lr) * ALD + np * 16 + lh * 8]));
                ldsm_x4_t(bVl, (uint32_t)__cvta_generic_to_shared(
                    &Vl[(kb + lr) * ALD + np * 16 + lh * 8]));
                mma16816(ctx[2 * np],     aPh[t], bVh[0], bVh[1]);
                mma16816(ctx[2 * np],     aPh[t], bVl[0], bVl[1]);
                mma16816(ctx[2 * np],     aPl[t], bVh[0], bVh[1]);
                mma16816(ctx[2 * np + 1], aPh[t], bVh[2], bVh[3]);
                mma16816(ctx[2 * np + 1], aPh[t], bVl[2], bVl[3]);
                mma16816(ctx[2 * np + 1], aPl[t], bVh[2], bVh[3]);
            }
        }

        // ---- refill this buffer with chunk c+2 ----
        __syncthreads();
        if (c + 2 < SEQ / 64) {
            KV_ISSUE(buf, (c + 2) * 64);
        }
        CP_COMMIT();
        CP_WAIT1();
        __syncthreads();
    }
#undef KV_ISSUE

    // ---- rowsum + cross-wx ctx reduction (red aliases KV buf0) ----------
    psum0 += __shfl_xor_sync(0xffffffffu, psum0, 1);
    psum0 += __shfl_xor_sync(0xffffffffu, psum0, 2);
    psum1 += __shfl_xor_sync(0xffffffffu, psum1, 1);
    psum1 += __shfl_xor_sync(0xffffffffu, psum1, 2);
    if (qid == 0) {
        sPart[wx * 64 + row0] = psum0;
        sPart[wx * 64 + row0 + 8] = psum1;
    }
    if (wx == 1) {
#pragma unroll
        for (int j = 0; j < 8; ++j) {
            *(float2*)&red[row0 * 68 + j * 8 + qid * 2] =
                make_float2(ctx[j][0], ctx[j][1]);
            *(float2*)&red[(row0 + 8) * 68 + j * 8 + qid * 2] =
                make_float2(ctx[j][2], ctx[j][3]);
        }
    }
    __syncthreads();
    if (wx == 0) {
        float tot0 = sPart[row0] + sPart[64 + row0];
        float tot1 = sPart[row0 + 8] + sPart[64 + row0 + 8];
        if (qid == 0) {
            g_rowsum[arow0] = tot0;
            g_rowsum[arow0 + 8] = tot1;
        }
        float inv0 = 1.0f / tot0, inv1 = 1.0f / tot1;
#pragma unroll
        for (int j = 0; j < 8; ++j) {
            const int col = j * 8 + qid * 2;
            float2 o0 = *(float2*)&red[row0 * 68 + col];
            float2 o1 = *(float2*)&red[(row0 + 8) * 68 + col];
            o0.x = (ctx[j][0] + o0.x) * inv0;
            o0.y = (ctx[j][1] + o0.y) * inv0;
            o1.x = (ctx[j][2] + o1.x) * inv1;
            o1.y = (ctx[j][3] + o1.y) * inv1;
            size_t p0 = (size_t)(b * SEQ + q0 + row0) * DMODEL + h * DHEAD + col;
            size_t p1 = (size_t)(b * SEQ + q0 + row0 + 8) * DMODEL + h * DHEAD + col;
            float h0x = __bfloat162float(__float2bfloat16_rn(o0.x));
            float h0y = __bfloat162float(__float2bfloat16_rn(o0.y));
            float h1x = __bfloat162float(__float2bfloat16_rn(o1.x));
            float h1y = __bfloat162float(__float2bfloat16_rn(o1.y));
            *(uint32_t*)&g_ctxh[p0] = pack_hi(o0.x, o0.y);
            *(uint32_t*)&g_ctxl[p0] = pack_hi(o0.x - h0x, o0.y - h0y);
            *(uint32_t*)&g_ctxh[p1] = pack_hi(o1.x, o1.y);
            *(uint32_t*)&g_ctxl[p1] = pack_hi(o1.x - h1x, o1.y - h1y);
        }
    }
}

// -------------------- attn rescale: p = e / rowsum ------------------------
__global__ __launch_bounds__(256)
void attn_scale(float* __restrict__ attn) {
    size_t i = (size_t)blockIdx.x * 256 + threadIdx.x;
    size_t row = i >> 9;
    float inv = 1.0f / g_rowsum[row];
    float4* p = (float4*)attn;
    float4 v = p[i];
    v.x *= inv; v.y *= inv; v.z *= inv; v.w *= inv;
    p[i] = v;
}

// -------------------- LayerNorm ------------------------------------------
__global__ __launch_bounds__(256)
void ln_kernel(const float* __restrict__ gamma, const float* __restrict__ beta,
               float* __restrict__ out) {
    const int row = blockIdx.x;
    const int tid = threadIdx.x;
    __shared__ float red[8];

    float4 x = *(const float4*)&g_o[(size_t)row * DMODEL + tid * 4];
    float s = (x.x + x.y) + (x.z + x.w);
#pragma unroll
    for (int off = 16; off; off >>= 1) s += __shfl_xor_sync(0xffffffffu, s, off);
    if ((tid & 31) == 0) red[tid >> 5] = s;
    __syncthreads();
    float tot = 0.f;
#pragma unroll
    for (int i = 0; i < 8; ++i) tot += red[i];
    float mean = tot * (1.0f / 1024.0f);
    __syncthreads();

    float4 dx = make_float4(x.x - mean, x.y - mean, x.z - mean, x.w - mean);
    float ss = dx.x * dx.x + dx.y * dx.y + dx.z * dx.z + dx.w * dx.w;
#pragma unroll
    for (int off = 16; off; off >>= 1) ss += __shfl_xor_sync(0xffffffffu, ss, off);
    if ((tid & 31) == 0) red[tid >> 5] = ss;
    __syncthreads();
    float tss = 0.f;
#pragma unroll
    for (int i = 0; i < 8; ++i) tss += red[i];
    float var = tss * (1.0f / 1024.0f);
    float rstd = rsqrtf(var + 1e-3f);

    float4 g = *(const float4*)&gamma[tid * 4];
    float4 be = *(const float4*)&beta[tid * 4];
    float4 o;
    o.x = dx.x * rstd * g.x + be.x;
    o.y = dx.y * rstd * g.y + be.y;
    o.z = dx.z * rstd * g.z + be.z;
    o.w = dx.w * rstd * g.w + be.w;
    *(float4*)&out[(size_t)row * DMODEL + tid * 4] = o;
}

// -------------------- launcher --------------------------------------------
extern "C" void kernel_launch(void* const* d_in, const int* in_sizes, int n_in,
                              void* d_out, int out_size) {
    const float* query = (const float*)d_in[0];
    const float* key   = (const float*)d_in[1];
    const float* value = (const float*)d_in[2];
    const float* Wq = (const float*)d_in[3];
    const float* bq = (const float*)d_in[4];
    const float* Wk = (const float*)d_in[5];
    const float* bk = (const float*)d_in[6];
    const float* Wv = (const float*)d_in[7];
    const float* bv = (const float*)d_in[8];
    const float* Wo = (const float*)d_in[9];
    const float* bo = (const float*)d_in[10];
    const float* gamma = (const float*)d_in[11];
    const float* beta  = (const float*)d_in[12];

    float* out = (float*)d_out;
    float* attn = (out_size >= OUT_ELEMS + ATTN_ELEMS) ? (out + OUT_ELEMS) : nullptr;

    cudaFuncSetAttribute(attn_tc, cudaFuncAttributeMaxDynamicSharedMemorySize,
                         TCA_SMEM);
    cudaFuncSetAttribute(gemm_qkv, cudaFuncAttributeMaxDynamicSharedMemorySize,
                         GEMM_SMEM);
    cudaFuncSetAttribute(gemm_wo, cudaFuncAttributeMaxDynamicSharedMemorySize,
                         GEMM_SMEM);

    convert_split<<<dim3(OUT_ELEMS / 4 / 256, 1, 7), 256>>>(query, key, value,
                                                            Wq, Wk, Wv, Wo);

    gemm_qkv<<<dim3(DMODEL / 128, NROWS / 128, 3), 256, GEMM_SMEM>>>(bq, bk, bv);

    attn_tc<<<dim3(SEQ / 64, NHEAD, BATCH), 256, TCA_SMEM>>>(attn);

    if (attn) {
        attn_scale<<<ATTN_ELEMS / 4 / 256, 256>>>(attn);
    }

    gemm_wo<<<dim3(DMODEL / 128, NROWS / 128), 256, GEMM_SMEM>>>(bo);

    ln_kernel<<<NROWS, 256>>>(gamma, beta, out);
}

// round 11
// speedup vs baseline: 1.7011x; 1.0789x over previous
#include <cuda_runtime.h>
#include <cuda_bf16.h>
#include <math.h>
#include <stdint.h>

// Problem constants
#define SEQ   2048
#define BATCH 2
#define DMODEL 1024
#define NHEAD 16
#define DHEAD 64
#define NROWS (BATCH * SEQ)          // 4096
#define OUT_ELEMS   (NROWS * DMODEL)             // 4,194,304
#define W_ELEMS (DMODEL * DMODEL)                // 1,048,576
#define ATTN_ELEMS  (BATCH * NHEAD * SEQ * SEQ)  // 134,217,728

// -------------------- device scratch (no allocations allowed) ------------
__device__ float g_o[NROWS * DMODEL];
__device__ float g_rowsum[BATCH * NHEAD * SEQ];
__device__ __nv_bfloat16 g_inh[3 * OUT_ELEMS];
__device__ __nv_bfloat16 g_inl[3 * OUT_ELEMS];
__device__ __nv_bfloat16 g_wh[4 * W_ELEMS];
__device__ __nv_bfloat16 g_wl[4 * W_ELEMS];
__device__ __nv_bfloat16 g_qh[OUT_ELEMS], g_ql[OUT_ELEMS];
__device__ __nv_bfloat16 g_kh[OUT_ELEMS], g_kl[OUT_ELEMS];
__device__ __nv_bfloat16 g_vh[OUT_ELEMS], g_vl[OUT_ELEMS];
__device__ __nv_bfloat16 g_ctxh[OUT_ELEMS], g_ctxl[OUT_ELEMS];

// ==================== helpers ============================================
__device__ __forceinline__ void ldsm_x4(uint32_t (&r)[4], uint32_t addr) {
    asm volatile("ldmatrix.sync.aligned.m8n8.x4.shared.b16 {%0,%1,%2,%3}, [%4];"
                 : "=r"(r[0]), "=r"(r[1]), "=r"(r[2]), "=r"(r[3]) : "r"(addr));
}
__device__ __forceinline__ void ldsm_x4_t(uint32_t (&r)[4], uint32_t addr) {
    asm volatile("ldmatrix.sync.aligned.m8n8.x4.trans.shared.b16 {%0,%1,%2,%3}, [%4];"
                 : "=r"(r[0]), "=r"(r[1]), "=r"(r[2]), "=r"(r[3]) : "r"(addr));
}
__device__ __forceinline__ void mma16816(float (&c)[4], const uint32_t (&a)[4],
                                         uint32_t b0, uint32_t b1) {
    asm volatile(
        "mma.sync.aligned.m16n8k16.row.col.f32.bf16.bf16.f32 "
        "{%0,%1,%2,%3}, {%4,%5,%6,%7}, {%8,%9}, {%0,%1,%2,%3};"
        : "+f"(c[0]), "+f"(c[1]), "+f"(c[2]), "+f"(c[3])
        : "r"(a[0]), "r"(a[1]), "r"(a[2]), "r"(a[3]), "r"(b0), "r"(b1));
}
__device__ __forceinline__ uint32_t pack_hi(float x, float y) {
    __nv_bfloat162 h = __floats2bfloat162_rn(x, y);
    return *(uint32_t*)&h;
}
__device__ __forceinline__ void cp16(uint32_t dst, const void* src) {
    asm volatile("cp.async.cg.shared.global [%0], [%1], 16;" :: "r"(dst), "l"(src));
}
#define CP_COMMIT() asm volatile("cp.async.commit_group;")
#define CP_WAIT1()  asm volatile("cp.async.wait_group 1;" ::: "memory")

// ==================== split-bf16 conversion pass ==========================
__global__ __launch_bounds__(256)
void convert_split(const float* __restrict__ q, const float* __restrict__ k,
                   const float* __restrict__ v, const float* __restrict__ wq,
                   const float* __restrict__ wk, const float* __restrict__ wv,
                   const float* __restrict__ wo) {
    const int z = blockIdx.z;
    const float* src;
    __nv_bfloat16 *dh, *dl;
    int n4;
    if (z < 3) {
        src = (z == 0) ? q : (z == 1) ? k : v;
        dh = g_inh + (size_t)z * OUT_ELEMS;
        dl = g_inl + (size_t)z * OUT_ELEMS;
        n4 = OUT_ELEMS / 4;
    } else {
        src = (z == 3) ? wq : (z == 4) ? wk : (z == 5) ? wv : wo;
        dh = g_wh + (size_t)(z - 3) * W_ELEMS;
        dl = g_wl + (size_t)(z - 3) * W_ELEMS;
        n4 = W_ELEMS / 4;
    }
    int i = blockIdx.x * 256 + threadIdx.x;
    if (i >= n4) return;
    float4 x = ((const float4*)src)[i];
    float hx = __bfloat162float(__float2bfloat16_rn(x.x));
    float hy = __bfloat162float(__float2bfloat16_rn(x.y));
    float hz = __bfloat162float(__float2bfloat16_rn(x.z));
    float hw = __bfloat162float(__float2bfloat16_rn(x.w));
    uint2 oh = make_uint2(pack_hi(x.x, x.y), pack_hi(x.z, x.w));
    uint2 ol = make_uint2(pack_hi(x.x - hx, x.y - hy), pack_hi(x.z - hz, x.w - hw));
    *(uint2*)&dh[(size_t)i * 4] = oh;
    *(uint2*)&dl[(size_t)i * 4] = ol;
}

// ==================== shared GEMM body (cp.async pipelined) ===============
#define A_LD 40
#define B_LD 136
#define OFF_AH 0
#define OFF_AL (128 * A_LD)
#define OFF_BH (2 * 128 * A_LD)
#define OFF_BL (2 * 128 * A_LD + 32 * B_LD)
#define BUF_ELEMS (2 * 128 * A_LD + 2 * 32 * B_LD)      // 18944 bf16
#define GEMM_SMEM (2 * BUF_ELEMS * 2)                   // 75776 bytes

__device__ __forceinline__ void gemm_body(
    const __nv_bfloat16* __restrict__ AH, const __nv_bfloat16* __restrict__ AL,
    const __nv_bfloat16* __restrict__ WH, const __nv_bfloat16* __restrict__ WL,
    const float* __restrict__ bias, __nv_bfloat16* OH, __nv_bfloat16* OL,
    int bm, int bn) {
    extern __shared__ __align__(16) __nv_bfloat16 gsm[];

    const int tid = threadIdx.x;
    const int lane = tid & 31;
    const int warp = tid >> 5;
    const int wm = (warp & 3) * 32;
    const int wn = (warp >> 2) * 64;
    const int lr = lane & 15;
    const int lh = lane >> 4;

    const uint32_t smem_base = (uint32_t)__cvta_generic_to_shared(gsm);

    float acc[2][8][4];
#pragma unroll
    for (int i = 0; i < 2; ++i)
#pragma unroll
        for (int j = 0; j < 8; ++j)
#pragma unroll
            for (int r = 0; r < 4; ++r) acc[i][j][r] = 0.f;

    const int ar0 = tid >> 2, ao0 = (tid & 3) * 8;
    const int ar1 = (tid + 256) >> 2, ao1 = ((tid + 256) & 3) * 8;
    const int br0 = tid >> 4, bo0 = (tid & 15) * 8;
    const int br1 = (tid + 256) >> 4, bo1 = ((tid + 256) & 15) * 8;

#define ISSUE(bufi, k0)                                                        \
    do {                                                                       \
        uint32_t sb = smem_base + (bufi) * (BUF_ELEMS * 2);                    \
        cp16(sb + (OFF_AH + ar0 * A_LD + ao0) * 2,                             \
             AH + (size_t)(bm + ar0) * DMODEL + (k0) + ao0);                   \
        cp16(sb + (OFF_AH + ar1 * A_LD + ao1) * 2,                             \
             AH + (size_t)(bm + ar1) * DMODEL + (k0) + ao1);                   \
        cp16(sb + (OFF_AL + ar0 * A_LD + ao0) * 2,                             \
             AL + (size_t)(bm + ar0) * DMODEL + (k0) + ao0);                   \
        cp16(sb + (OFF_AL + ar1 * A_LD + ao1) * 2,                             \
             AL + (size_t)(bm + ar1) * DMODEL + (k0) + ao1);                   \
        cp16(sb + (OFF_BH + br0 * B_LD + bo0) * 2,                             \
             WH + (size_t)((k0) + br0) * DMODEL + bn + bo0);                   \
        cp16(sb + (OFF_BH + br1 * B_LD + bo1) * 2,                             \
             WH + (size_t)((k0) + br1) * DMODEL + bn + bo1);                   \
        cp16(sb + (OFF_BL + br0 * B_LD + bo0) * 2,                             \
             WL + (size_t)((k0) + br0) * DMODEL + bn + bo0);                   \
        cp16(sb + (OFF_BL + br1 * B_LD + bo1) * 2,                             \
             WL + (size_t)((k0) + br1) * DMODEL + bn + bo1);                   \
    } while (0)

    ISSUE(0, 0);
    CP_COMMIT();
    ISSUE(1, 32);
    CP_COMMIT();
    CP_WAIT1();
    __syncthreads();

    for (int c = 0; c < DMODEL / 32; ++c) {
        const int buf = c & 1;
        const __nv_bfloat16* Ah = gsm + buf * BUF_ELEMS + OFF_AH;
        const __nv_bfloat16* Al = gsm + buf * BUF_ELEMS + OFF_AL;
        const __nv_bfloat16* Bh = gsm + buf * BUF_ELEMS + OFF_BH;
        const __nv_bfloat16* Bl = gsm + buf * BUF_ELEMS + OFF_BL;
#pragma unroll
        for (int ks = 0; ks < 2; ++ks) {
            uint32_t afh[2][4], afl[2][4];
#pragma unroll
            for (int mt = 0; mt < 2; ++mt) {
                ldsm_x4(afh[mt], (uint32_t)__cvta_generic_to_shared(
                    &Ah[(wm + mt * 16 + lr) * A_LD + ks * 16 + lh * 8]));
                ldsm_x4(afl[mt], (uint32_t)__cvta_generic_to_shared(
                    &Al[(wm + mt * 16 + lr) * A_LD + ks * 16 + lh * 8]));
            }
#pragma unroll
            for (int np = 0; np < 4; ++np) {
                uint32_t bfh[4], bfl[4];
                ldsm_x4_t(bfh, (uint32_t)__cvta_generic_to_shared(
                    &Bh[(ks * 16 + lr) * B_LD + wn + np * 16 + lh * 8]));
                ldsm_x4_t(bfl, (uint32_t)__cvta_generic_to_shared(
                    &Bl[(ks * 16 + lr) * B_LD + wn + np * 16 + lh * 8]));
#pragma unroll
                for (int mt = 0; mt < 2; ++mt) {
                    mma16816(acc[mt][2 * np],     afh[mt], bfh[0], bfh[1]);
                    mma16816(acc[mt][2 * np],     afh[mt], bfl[0], bfl[1]);
                    mma16816(acc[mt][2 * np],     afl[mt], bfh[0], bfh[1]);
                    mma16816(acc[mt][2 * np + 1], afh[mt], bfh[2], bfh[3]);
                    mma16816(acc[mt][2 * np + 1], afh[mt], bfl[2], bfl[3]);
                    mma16816(acc[mt][2 * np + 1], afl[mt], bfh[2], bfh[3]);
                }
            }
        }
        __syncthreads();
        if (c + 2 < DMODEL / 32) {
            ISSUE(buf, (c + 2) * 32);
        }
        CP_COMMIT();
        CP_WAIT1();
        __syncthreads();
    }
#undef ISSUE

    const int gid = lane >> 2;
    const int qid = lane & 3;
#pragma unroll
    for (int mt = 0; mt < 2; ++mt) {
#pragma unroll
        for (int nt = 0; nt < 8; ++nt) {
            int col = bn + wn + nt * 8 + qid * 2;
            float bb0 = bias[col], bb1 = bias[col + 1];
            int r0 = bm + wm + mt * 16 + gid;
            float v00 = acc[mt][nt][0] + bb0, v01 = acc[mt][nt][1] + bb1;
            float v10 = acc[mt][nt][2] + bb0, v11 = acc[mt][nt][3] + bb1;
            if (OH) {
                size_t p0 = (size_t)r0 * DMODEL + col;
                size_t p1 = (size_t)(r0 + 8) * DMODEL + col;
                float h00 = __bfloat162float(__float2bfloat16_rn(v00));
                float h01 = __bfloat162float(__float2bfloat16_rn(v01));
                float h10 = __bfloat162float(__float2bfloat16_rn(v10));
                float h11 = __bfloat162float(__float2bfloat16_rn(v11));
                *(uint32_t*)&OH[p0] = pack_hi(v00, v01);
                *(uint32_t*)&OL[p0] = pack_hi(v00 - h00, v01 - h01);
                *(uint32_t*)&OH[p1] = pack_hi(v10, v11);
                *(uint32_t*)&OL[p1] = pack_hi(v10 - h10, v11 - h11);
            } else {
                *(float2*)&g_o[(size_t)r0 * DMODEL + col] = make_float2(v00, v01);
                *(float2*)&g_o[(size_t)(r0 + 8) * DMODEL + col] = make_float2(v10, v11);
            }
        }
    }
}

__global__ __launch_bounds__(256, 2)
void gemm_qkv(const float* __restrict__ b0p, const float* __restrict__ b1p,
              const float* __restrict__ b2p) {
    const int z = blockIdx.z;
    const __nv_bfloat16* AH = g_inh + (size_t)z * OUT_ELEMS;
    const __nv_bfloat16* AL = g_inl + (size_t)z * OUT_ELEMS;
    const __nv_bfloat16* WH = g_wh + (size_t)z * W_ELEMS;
    const __nv_bfloat16* WL = g_wl + (size_t)z * W_ELEMS;
    const float* bias = (z == 0) ? b0p : (z == 1) ? b1p : b2p;
    __nv_bfloat16* OH = (z == 0) ? g_qh : (z == 1) ? g_kh : g_vh;
    __nv_bfloat16* OL = (z == 0) ? g_ql : (z == 1) ? g_kl : g_vl;
    gemm_body(AH, AL, WH, WL, bias, OH, OL,
              blockIdx.y * 128, blockIdx.x * 128);
}

__global__ __launch_bounds__(256, 2)
void gemm_wo(const float* __restrict__ bo) {
    gemm_body(g_ctxh, g_ctxl, g_wh + (size_t)3 * W_ELEMS,
              g_wl + (size_t)3 * W_ELEMS, bo, nullptr, nullptr,
              blockIdx.y * 128, blockIdx.x * 128);
}

// ==================== tensor-core attention v4 ============================
// cp.async K/V pipeline + per-block tail rescale of its own attn rows.
#define ALD 72
#define TILE_B (64 * ALD * 2)                 // 9216 bytes
#define KV_OFF (2 * TILE_B)
#define TCA_SMEM (10 * TILE_B + 576)

__global__ __launch_bounds__(256, 2)
void attn_tc(float* __restrict__ gattn) {
    extern __shared__ __align__(16) char dsm[];
    __nv_bfloat16* Qh = (__nv_bfloat16*)dsm;
    __nv_bfloat16* Ql = (__nv_bfloat16*)(dsm + TILE_B);
    float* sPart = (float*)(dsm + 10 * TILE_B);
    float* red = (float*)(dsm + KV_OFF);      // aliases KV buf0 (post-loop)

    const int tid = threadIdx.x;
    const int lane = tid & 31;
    const int warp = tid >> 5;
    const int wy = warp & 3;
    const int wx = warp >> 2;
    const int lr = lane & 15;
    const int lh = lane >> 4;
    const int gid = lane >> 2;
    const int qid = lane & 3;

    const int q0 = blockIdx.x * 64;
    const int h = blockIdx.y;
    const int b = blockIdx.z;
    const size_t head_off = (size_t)b * SEQ * DMODEL + h * DHEAD;

    const uint32_t smem_base = (uint32_t)__cvta_generic_to_shared(dsm);

    const int r0c = tid >> 3, o0c = (tid & 7) * 8;
    const int r1c = 32 + (tid >> 3), o1c = (tid & 7) * 8;

#define KV_ISSUE(bufi, kc)                                                     \
    do {                                                                       \
        uint32_t sb = smem_base + KV_OFF + (bufi) * (4 * TILE_B);              \
        const size_t s0 = head_off + (size_t)((kc) + r0c) * DMODEL;            \
        const size_t s1 = head_off + (size_t)((kc) + r1c) * DMODEL;            \
        cp16(sb + 0 * TILE_B + (r0c * ALD + o0c) * 2, g_kh + s0 + o0c);        \
        cp16(sb + 0 * TILE_B + (r1c * ALD + o1c) * 2, g_kh + s1 + o1c);        \
        cp16(sb + 1 * TILE_B + (r0c * ALD + o0c) * 2, g_kl + s0 + o0c);        \
        cp16(sb + 1 * TILE_B + (r1c * ALD + o1c) * 2, g_kl + s1 + o1c);        \
        cp16(sb + 2 * TILE_B + (r0c * ALD + o0c) * 2, g_vh + s0 + o0c);        \
        cp16(sb + 2 * TILE_B + (r1c * ALD + o1c) * 2, g_vh + s1 + o1c);        \
        cp16(sb + 3 * TILE_B + (r0c * ALD + o0c) * 2, g_vl + s0 + o0c);        \
        cp16(sb + 3 * TILE_B + (r1c * ALD + o1c) * 2, g_vl + s1 + o1c);        \
    } while (0)

    {
        const int row = tid >> 2;
        const int cg = (tid & 3) * 16;
        const size_t src = head_off + (size_t)(q0 + row) * DMODEL + cg;
        *(uint4*)&Qh[row * ALD + cg]     = *(const uint4*)&g_qh[src];
        *(uint4*)&Qh[row * ALD + cg + 8] = *(const uint4*)&g_qh[src + 8];
        *(uint4*)&Ql[row * ALD + cg]     = *(const uint4*)&g_ql[src];
        *(uint4*)&Ql[row * ALD + cg + 8] = *(const uint4*)&g_ql[src + 8];
    }

    KV_ISSUE(0, 0);
    CP_COMMIT();
    KV_ISSUE(1, 64);
    CP_COMMIT();
    CP_WAIT1();
    __syncthreads();

    float ctx[8][4];
#pragma unroll
    for (int j = 0; j < 8; ++j)
#pragma unroll
        for (int r = 0; r < 4; ++r) ctx[j][r] = 0.f;
    float psum0 = 0.f, psum1 = 0.f;

    const int row0 = wy * 16 + gid;
    const size_t arow0 = (size_t)((b * NHEAD + h) * SEQ + q0 + row0);

    for (int c = 0; c < SEQ / 64; ++c) {
        const int buf = c & 1;
        const int kc = c * 64;
        __nv_bfloat16* Kh = (__nv_bfloat16*)(dsm + KV_OFF + buf * 4 * TILE_B);
        __nv_bfloat16* Kl = Kh + 64 * ALD;
        __nv_bfloat16* Vh = Kl + 64 * ALD;
        __nv_bfloat16* Vl = Vh + 64 * ALD;

        float s[4][4];
#pragma unroll
        for (int j = 0; j < 4; ++j)
#pragma unroll
            for (int r = 0; r < 4; ++r) s[j][r] = 0.f;

#pragma unroll
        for (int ks = 0; ks < 4; ++ks) {
            uint32_t aQh[4], aQl[4];
            ldsm_x4(aQh, (uint32_t)__cvta_generic_to_shared(
                &Qh[(wy * 16 + lr) * ALD + ks * 16 + lh * 8]));
            ldsm_x4(aQl, (uint32_t)__cvta_generic_to_shared(
                &Ql[(wy * 16 + lr) * ALD + ks * 16 + lh * 8]));
            uint32_t bKh[2][4], bKl[2][4];
            const int mat = lane >> 3, rr = lane & 7;
            const int keyo = (mat >> 1) * 8 + rr;
            const int dof = (mat & 1) * 8 + ks * 16;
#pragma unroll
            for (int g = 0; g < 2; ++g) {
                int key = wx * 32 + g * 16 + keyo;
                ldsm_x4(bKh[g], (uint32_t)__cvta_generic_to_shared(
                    &Kh[key * ALD + dof]));
                ldsm_x4(bKl[g], (uint32_t)__cvta_generic_to_shared(
                    &Kl[key * ALD + dof]));
            }
#pragma unroll
            for (int j = 0; j < 4; ++j) {
                const int g = j >> 1, p = (j & 1) * 2;
                mma16816(s[j], aQh, bKh[g][p], bKh[g][p + 1]);
                mma16816(s[j], aQh, bKl[g][p], bKl[g][p + 1]);
                mma16816(s[j], aQl, bKh[g][p], bKh[g][p + 1]);
            }
        }

        uint32_t aPh[2][4], aPl[2][4];
#pragma unroll
        for (int j = 0; j < 4; ++j) {
            float e0 = __expf(s[j][0] * 0.125f);
            float e1 = __expf(s[j][1] * 0.125f);
            float e2 = __expf(s[j][2] * 0.125f);
            float e3 = __expf(s[j][3] * 0.125f);
            psum0 += e0 + e1;
            psum1 += e2 + e3;
            const int col = wx * 32 + j * 8 + qid * 2;
            if (gattn) {
                __stcs((float2*)&gattn[arow0 * SEQ + kc + col], make_float2(e0, e1));
                __stcs((float2*)&gattn[(arow0 + 8) * SEQ + kc + col], make_float2(e2, e3));
            }
            float l0 = e0 - __bfloat162float(__float2bfloat16_rn(e0));
            float l1 = e1 - __bfloat162float(__float2bfloat16_rn(e1));
            float l2 = e2 - __bfloat162float(__float2bfloat16_rn(e2));
            float l3 = e3 - __bfloat162float(__float2bfloat16_rn(e3));
            const int t = j >> 1, half = j & 1;
            aPh[t][half * 2 + 0] = pack_hi(e0, e1);
            aPh[t][half * 2 + 1] = pack_hi(e2, e3);
            aPl[t][half * 2 + 0] = pack_hi(l0, l1);
            aPl[t][half * 2 + 1] = pack_hi(l2, l3);
        }

#pragma unroll
        for (int t = 0; t < 2; ++t) {
            const int kb = wx * 32 + t * 16;
#pragma unroll
            for (int np = 0; np < 4; ++np) {
                uint32_t bVh[4], bVl[4];
                ldsm_x4_t(bVh, (uint32_t)__cvta_generic_to_shared(
                    &Vh[(kb + lr) * ALD + np * 16 + lh * 8]));
                ldsm_x4_t(bVl, (uint32_t)__cvta_generic_to_shared(
                    &Vl[(kb + lr) * ALD + np * 16 + lh * 8]));
                mma16816(ctx[2 * np],     aPh[t], bVh[0], bVh[1]);
                mma16816(ctx[2 * np],     aPh[t], bVl[0], bVl[1]);
                mma16816(ctx[2 * np],     aPl[t], bVh[0], bVh[1]);
                mma16816(ctx[2 * np + 1], aPh[t], bVh[2], bVh[3]);
                mma16816(ctx[2 * np + 1], aPh[t], bVl[2], bVl[3]);
                mma16816(ctx[2 * np + 1], aPl[t], bVh[2], bVh[3]);
            }
        }

        __syncthreads();
        if (c + 2 < SEQ / 64) {
            KV_ISSUE(buf, (c + 2) * 64);
        }
        CP_COMMIT();
        CP_WAIT1();
        __syncthreads();
    }
#undef KV_ISSUE

    // ---- rowsum + cross-wx ctx reduction (red aliases KV buf0) ----------
    psum0 += __shfl_xor_sync(0xffffffffu, psum0, 1);
    psum0 += __shfl_xor_sync(0xffffffffu, psum0, 2);
    psum1 += __shfl_xor_sync(0xffffffffu, psum1, 1);
    psum1 += __shfl_xor_sync(0xffffffffu, psum1, 2);
    if (qid == 0) {
        sPart[wx * 64 + row0] = psum0;
        sPart[wx * 64 + row0 + 8] = psum1;
    }
    if (wx == 1) {
#pragma unroll
        for (int j = 0; j < 8; ++j) {
            *(float2*)&red[row0 * 68 + j * 8 + qid * 2] =
                make_float2(ctx[j][0], ctx[j][1]);
            *(float2*)&red[(row0 + 8) * 68 + j * 8 + qid * 2] =
                make_float2(ctx[j][2], ctx[j][3]);
        }
    }
    __syncthreads();
    if (wx == 0) {
        float tot0 = sPart[row0] + sPart[64 + row0];
        float tot1 = sPart[row0 + 8] + sPart[64 + row0 + 8];
        if (qid == 0) {
            g_rowsum[arow0] = tot0;
            g_rowsum[arow0 + 8] = tot1;
        }
        float inv0 = 1.0f / tot0, inv1 = 1.0f / tot1;
#pragma unroll
        for (int j = 0; j < 8; ++j) {
            const int col = j * 8 + qid * 2;
            float2 o0 = *(float2*)&red[row0 * 68 + col];
            float2 o1 = *(float2*)&red[(row0 + 8) * 68 + col];
            o0.x = (ctx[j][0] + o0.x) * inv0;
            o0.y = (ctx[j][1] + o0.y) * inv0;
            o1.x = (ctx[j][2] + o1.x) * inv1;
            o1.y = (ctx[j][3] + o1.y) * inv1;
            size_t p0 = (size_t)(b * SEQ + q0 + row0) * DMODEL + h * DHEAD + col;
            size_t p1 = (size_t)(b * SEQ + q0 + row0 + 8) * DMODEL + h * DHEAD + col;
            float h0x = __bfloat162float(__float2bfloat16_rn(o0.x));
            float h0y = __bfloat162float(__float2bfloat16_rn(o0.y));
            float h1x = __bfloat162float(__float2bfloat16_rn(o1.x));
            float h1y = __bfloat162float(__float2bfloat16_rn(o1.y));
            *(uint32_t*)&g_ctxh[p0] = pack_hi(o0.x, o0.y);
            *(uint32_t*)&g_ctxl[p0] = pack_hi(o0.x - h0x, o0.y - h0y);
            *(uint32_t*)&g_ctxh[p1] = pack_hi(o1.x, o1.y);
            *(uint32_t*)&g_ctxl[p1] = pack_hi(o1.x - h1x, o1.y - h1y);
        }
    }

    // ---- tail: rescale this block's own 64 attn rows (overlaps other
    //      blocks' compute; removes the separate attn_scale kernel) --------
    if (gattn) {
        __syncthreads();   // sPart valid for all threads; attn stores done
        float4* p = (float4*)gattn;
        const size_t rowbase = (size_t)((b * NHEAD + h) * SEQ + q0);
#pragma unroll 1
        for (int r = 0; r < 64; r += 2) {
            float inv0 = 1.0f / (sPart[r] + sPart[64 + r]);
            float inv1 = 1.0f / (sPart[r + 1] + sPart[64 + r + 1]);
            size_t b0 = (rowbase + r) * (SEQ / 4);
            size_t b1 = b0 + (SEQ / 4);
            float4 v0 = __ldcs(&p[b0 + tid]);
            float4 v1 = __ldcs(&p[b0 + 256 + tid]);
            float4 v2 = __ldcs(&p[b1 + tid]);
            float4 v3 = __ldcs(&p[b1 + 256 + tid]);
            v0.x *= inv0; v0.y *= inv0; v0.z *= inv0; v0.w *= inv0;
            v1.x *= inv0; v1.y *= inv0; v1.z *= inv0; v1.w *= inv0;
            v2.x *= inv1; v2.y *= inv1; v2.z *= inv1; v2.w *= inv1;
            v3.x *= inv1; v3.y *= inv1; v3.z *= inv1; v3.w *= inv1;
            __stcs(&p[b0 + tid], v0);
            __stcs(&p[b0 + 256 + tid], v1);
            __stcs(&p[b1 + tid], v2);
            __stcs(&p[b1 + 256 + tid], v3);
        }
    }
}

// -------------------- LayerNorm ------------------------------------------
__global__ __launch_bounds__(256)
void ln_kernel(const float* __restrict__ gamma, const float* __restrict__ beta,
               float* __restrict__ out) {
    const int row = blockIdx.x;
    const int tid = threadIdx.x;
    __shared__ float red[8];

    float4 x = *(const float4*)&g_o[(size_t)row * DMODEL + tid * 4];
    float s = (x.x + x.y) + (x.z + x.w);
#pragma unroll
    for (int off = 16; off; off >>= 1) s += __shfl_xor_sync(0xffffffffu, s, off);
    if ((tid & 31) == 0) red[tid >> 5] = s;
    __syncthreads();
    float tot = 0.f;
#pragma unroll
    for (int i = 0; i < 8; ++i) tot += red[i];
    float mean = tot * (1.0f / 1024.0f);
    __syncthreads();

    float4 dx = make_float4(x.x - mean, x.y - mean, x.z - mean, x.w - mean);
    float ss = dx.x * dx.x + dx.y * dx.y + dx.z * dx.z + dx.w * dx.w;
#pragma unroll
    for (int off = 16; off; off >>= 1) ss += __shfl_xor_sync(0xffffffffu, ss, off);
    if ((tid & 31) == 0) red[tid >> 5] = ss;
    __syncthreads();
    float tss = 0.f;
#pragma unroll
    for (int i = 0; i < 8; ++i) tss += red[i];
    float var = tss * (1.0f / 1024.0f);
    float rstd = rsqrtf(var + 1e-3f);

    float4 g = *(const float4*)&gamma[tid * 4];
    float4 be = *(const float4*)&beta[tid * 4];
    float4 o;
    o.x = dx.x * rstd * g.x + be.x;
    o.y = dx.y * rstd * g.y + be.y;
    o.z = dx.z * rstd * g.z + be.z;
    o.w = dx.w * rstd * g.w + be.w;
    *(float4*)&out[(size_t)row * DMODEL + tid * 4] = o;
}

// -------------------- launcher --------------------------------------------
extern "C" void kernel_launch(void* const* d_in, const int* in_sizes, int n_in,
                              void* d_out, int out_size) {
    const float* query = (const float*)d_in[0];
    const float* key   = (const float*)d_in[1];
    const float* value = (const float*)d_in[2];
    const float* Wq = (const float*)d_in[3];
    const float* bq = (const float*)d_in[4];
    const float* Wk = (const float*)d_in[5];
    const float* bk = (const float*)d_in[6];
    const float* Wv = (const float*)d_in[7];
    const float* bv = (const float*)d_in[8];
    const float* Wo = (const float*)d_in[9];
    const float* bo = (const float*)d_in[10];
    const float* gamma = (const float*)d_in[11];
    const float* beta  = (const float*)d_in[12];

    float* out = (float*)d_out;
    float* attn = (out_size >= OUT_ELEMS + ATTN_ELEMS) ? (out + OUT_ELEMS) : nullptr;

    cudaFuncSetAttribute(attn_tc, cudaFuncAttributeMaxDynamicSharedMemorySize,
                         TCA_SMEM);
    cudaFuncSetAttribute(gemm_qkv, cudaFuncAttributeMaxDynamicSharedMemorySize,
                         GEMM_SMEM);
    cudaFuncSetAttribute(gemm_wo, cudaFuncAttributeMaxDynamicSharedMemorySize,
                         GEMM_SMEM);

    convert_split<<<dim3(OUT_ELEMS / 4 / 256, 1, 7), 256>>>(query, key, value,
                                                            Wq, Wk, Wv, Wo);

    gemm_qkv<<<dim3(DMODEL / 128, NROWS / 128, 3), 256, GEMM_SMEM>>>(bq, bk, bv);

    attn_tc<<<dim3(SEQ / 64, NHEAD, BATCH), 256, TCA_SMEM>>>(attn);

    gemm_wo<<<dim3(DMODEL / 128, NROWS / 128), 256, GEMM_SMEM>>>(bo);

    ln_kernel<<<NROWS, 256>>>(gamma, beta, out);
}

// round 13
// speedup vs baseline: 1.7040x; 1.0017x over previous
#include <cuda_runtime.h>
#include <cuda_bf16.h>
#include <math.h>
#include <stdint.h>

// Problem constants
#define SEQ   2048
#define BATCH 2
#define DMODEL 1024
#define NHEAD 16
#define DHEAD 64
#define NROWS (BATCH * SEQ)          // 4096
#define OUT_ELEMS   (NROWS * DMODEL)             // 4,194,304
#define W_ELEMS (DMODEL * DMODEL)                // 1,048,576
#define ATTN_ELEMS  (BATCH * NHEAD * SEQ * SEQ)  // 134,217,728

// -------------------- device scratch (no allocations allowed) ------------
__device__ float g_o[NROWS * DMODEL];
__device__ float g_rowsum[BATCH * NHEAD * SEQ];
__device__ __nv_bfloat16 g_inh[3 * OUT_ELEMS];
__device__ __nv_bfloat16 g_inl[3 * OUT_ELEMS];
__device__ __nv_bfloat16 g_wh[4 * W_ELEMS];
__device__ __nv_bfloat16 g_wl[4 * W_ELEMS];
__device__ __nv_bfloat16 g_qh[OUT_ELEMS], g_ql[OUT_ELEMS];
__device__ __nv_bfloat16 g_kh[OUT_ELEMS], g_kl[OUT_ELEMS];
__device__ __nv_bfloat16 g_vh[OUT_ELEMS], g_vl[OUT_ELEMS];
__device__ __nv_bfloat16 g_ctxh[OUT_ELEMS], g_ctxl[OUT_ELEMS];

// ==================== helpers ============================================
__device__ __forceinline__ void ldsm_x4(uint32_t (&r)[4], uint32_t addr) {
    asm volatile("ldmatrix.sync.aligned.m8n8.x4.shared.b16 {%0,%1,%2,%3}, [%4];"
                 : "=r"(r[0]), "=r"(r[1]), "=r"(r[2]), "=r"(r[3]) : "r"(addr));
}
__device__ __forceinline__ void ldsm_x4_t(uint32_t (&r)[4], uint32_t addr) {
    asm volatile("ldmatrix.sync.aligned.m8n8.x4.trans.shared.b16 {%0,%1,%2,%3}, [%4];"
                 : "=r"(r[0]), "=r"(r[1]), "=r"(r[2]), "=r"(r[3]) : "r"(addr));
}
__device__ __forceinline__ void mma16816(float (&c)[4], const uint32_t (&a)[4],
                                         uint32_t b0, uint32_t b1) {
    asm volatile(
        "mma.sync.aligned.m16n8k16.row.col.f32.bf16.bf16.f32 "
        "{%0,%1,%2,%3}, {%4,%5,%6,%7}, {%8,%9}, {%0,%1,%2,%3};"
        : "+f"(c[0]), "+f"(c[1]), "+f"(c[2]), "+f"(c[3])
        : "r"(a[0]), "r"(a[1]), "r"(a[2]), "r"(a[3]), "r"(b0), "r"(b1));
}
__device__ __forceinline__ uint32_t pack_hi(float x, float y) {
    __nv_bfloat162 h = __floats2bfloat162_rn(x, y);
    return *(uint32_t*)&h;
}
__device__ __forceinline__ void cp16(uint32_t dst, const void* src) {
    asm volatile("cp.async.cg.shared.global [%0], [%1], 16;" :: "r"(dst), "l"(src));
}
#define CP_COMMIT() asm volatile("cp.async.commit_group;")
#define CP_WAIT1()  asm volatile("cp.async.wait_group 1;" ::: "memory")

// ==================== split-bf16 conversion pass ==========================
__global__ __launch_bounds__(256)
void convert_split(const float* __restrict__ q, const float* __restrict__ k,
                   const float* __restrict__ v, const float* __restrict__ wq,
                   const float* __restrict__ wk, const float* __restrict__ wv,
                   const float* __restrict__ wo) {
    const int z = blockIdx.z;
    const float* src;
    __nv_bfloat16 *dh, *dl;
    int n4;
    if (z < 3) {
        src = (z == 0) ? q : (z == 1) ? k : v;
        dh = g_inh + (size_t)z * OUT_ELEMS;
        dl = g_inl + (size_t)z * OUT_ELEMS;
        n4 = OUT_ELEMS / 4;
    } else {
        src = (z == 3) ? wq : (z == 4) ? wk : (z == 5) ? wv : wo;
        dh = g_wh + (size_t)(z - 3) * W_ELEMS;
        dl = g_wl + (size_t)(z - 3) * W_ELEMS;
        n4 = W_ELEMS / 4;
    }
    int i = blockIdx.x * 256 + threadIdx.x;
    if (i >= n4) return;
    float4 x = ((const float4*)src)[i];
    float hx = __bfloat162float(__float2bfloat16_rn(x.x));
    float hy = __bfloat162float(__float2bfloat16_rn(x.y));
    float hz = __bfloat162float(__float2bfloat16_rn(x.z));
    float hw = __bfloat162float(__float2bfloat16_rn(x.w));
    uint2 oh = make_uint2(pack_hi(x.x, x.y), pack_hi(x.z, x.w));
    uint2 ol = make_uint2(pack_hi(x.x - hx, x.y - hy), pack_hi(x.z - hz, x.w - hw));
    *(uint2*)&dh[(size_t)i * 4] = oh;
    *(uint2*)&dl[(size_t)i * 4] = ol;
}

// ==================== shared GEMM body (cp.async pipelined) ===============
#define A_LD 40
#define B_LD 136
#define OFF_AH 0
#define OFF_AL (128 * A_LD)
#define OFF_BH (2 * 128 * A_LD)
#define OFF_BL (2 * 128 * A_LD + 32 * B_LD)
#define BUF_ELEMS (2 * 128 * A_LD + 2 * 32 * B_LD)      // 18944 bf16
#define GEMM_SMEM (2 * BUF_ELEMS * 2)                   // 75776 bytes

__device__ __forceinline__ void gemm_body(
    const __nv_bfloat16* __restrict__ AH, const __nv_bfloat16* __restrict__ AL,
    const __nv_bfloat16* __restrict__ WH, const __nv_bfloat16* __restrict__ WL,
    const float* __restrict__ bias, __nv_bfloat16* OH, __nv_bfloat16* OL,
    int bm, int bn) {
    extern __shared__ __align__(16) __nv_bfloat16 gsm[];

    const int tid = threadIdx.x;
    const int lane = tid & 31;
    const int warp = tid >> 5;
    const int wm = (warp & 3) * 32;
    const int wn = (warp >> 2) * 64;
    const int lr = lane & 15;
    const int lh = lane >> 4;

    const uint32_t smem_base = (uint32_t)__cvta_generic_to_shared(gsm);

    float acc[2][8][4];
#pragma unroll
    for (int i = 0; i < 2; ++i)
#pragma unroll
        for (int j = 0; j < 8; ++j)
#pragma unroll
            for (int r = 0; r < 4; ++r) acc[i][j][r] = 0.f;

    const int ar0 = tid >> 2, ao0 = (tid & 3) * 8;
    const int ar1 = (tid + 256) >> 2, ao1 = ((tid + 256) & 3) * 8;
    const int br0 = tid >> 4, bo0 = (tid & 15) * 8;
    const int br1 = (tid + 256) >> 4, bo1 = ((tid + 256) & 15) * 8;

#define ISSUE(bufi, k0)                                                        \
    do {                                                                       \
        uint32_t sb = smem_base + (bufi) * (BUF_ELEMS * 2);                    \
        cp16(sb + (OFF_AH + ar0 * A_LD + ao0) * 2,                             \
             AH + (size_t)(bm + ar0) * DMODEL + (k0) + ao0);                   \
        cp16(sb + (OFF_AH + ar1 * A_LD + ao1) * 2,                             \
             AH + (size_t)(bm + ar1) * DMODEL + (k0) + ao1);                   \
        cp16(sb + (OFF_AL + ar0 * A_LD + ao0) * 2,                             \
             AL + (size_t)(bm + ar0) * DMODEL + (k0) + ao0);                   \
        cp16(sb + (OFF_AL + ar1 * A_LD + ao1) * 2,                             \
             AL + (size_t)(bm + ar1) * DMODEL + (k0) + ao1);                   \
        cp16(sb + (OFF_BH + br0 * B_LD + bo0) * 2,                             \
             WH + (size_t)((k0) + br0) * DMODEL + bn + bo0);                   \
        cp16(sb + (OFF_BH + br1 * B_LD + bo1) * 2,                             \
             WH + (size_t)((k0) + br1) * DMODEL + bn + bo1);                   \
        cp16(sb + (OFF_BL + br0 * B_LD + bo0) * 2,                             \
             WL + (size_t)((k0) + br0) * DMODEL + bn + bo0);                   \
        cp16(sb + (OFF_BL + br1 * B_LD + bo1) * 2,                             \
             WL + (size_t)((k0) + br1) * DMODEL + bn + bo1);                   \
    } while (0)

    ISSUE(0, 0);
    CP_COMMIT();
    ISSUE(1, 32);
    CP_COMMIT();
    CP_WAIT1();
    __syncthreads();

    for (int c = 0; c < DMODEL / 32; ++c) {
        const int buf = c & 1;
        const __nv_bfloat16* Ah = gsm + buf * BUF_ELEMS + OFF_AH;
        const __nv_bfloat16* Al = gsm + buf * BUF_ELEMS + OFF_AL;
        const __nv_bfloat16* Bh = gsm + buf * BUF_ELEMS + OFF_BH;
        const __nv_bfloat16* Bl = gsm + buf * BUF_ELEMS + OFF_BL;
#pragma unroll
        for (int ks = 0; ks < 2; ++ks) {
            uint32_t afh[2][4], afl[2][4];
#pragma unroll
            for (int mt = 0; mt < 2; ++mt) {
                ldsm_x4(afh[mt], (uint32_t)__cvta_generic_to_shared(
                    &Ah[(wm + mt * 16 + lr) * A_LD + ks * 16 + lh * 8]));
                ldsm_x4(afl[mt], (uint32_t)__cvta_generic_to_shared(
                    &Al[(wm + mt * 16 + lr) * A_LD + ks * 16 + lh * 8]));
            }
#pragma unroll
            for (int np = 0; np < 4; ++np) {
                uint32_t bfh[4], bfl[4];
                ldsm_x4_t(bfh, (uint32_t)__cvta_generic_to_shared(
                    &Bh[(ks * 16 + lr) * B_LD + wn + np * 16 + lh * 8]));
                ldsm_x4_t(bfl, (uint32_t)__cvta_generic_to_shared(
                    &Bl[(ks * 16 + lr) * B_LD + wn + np * 16 + lh * 8]));
#pragma unroll
                for (int mt = 0; mt < 2; ++mt) {
                    mma16816(acc[mt][2 * np],     afh[mt], bfh[0], bfh[1]);
                    mma16816(acc[mt][2 * np],     afh[mt], bfl[0], bfl[1]);
                    mma16816(acc[mt][2 * np],     afl[mt], bfh[0], bfh[1]);
                    mma16816(acc[mt][2 * np + 1], afh[mt], bfh[2], bfh[3]);
                    mma16816(acc[mt][2 * np + 1], afh[mt], bfl[2], bfl[3]);
                    mma16816(acc[mt][2 * np + 1], afl[mt], bfh[2], bfh[3]);
                }
            }
        }
        __syncthreads();
        if (c + 2 < DMODEL / 32) {
            ISSUE(buf, (c + 2) * 32);
        }
        CP_COMMIT();
        CP_WAIT1();
        __syncthreads();
    }
#undef ISSUE

    const int gid = lane >> 2;
    const int qid = lane & 3;
#pragma unroll
    for (int mt = 0; mt < 2; ++mt) {
#pragma unroll
        for (int nt = 0; nt < 8; ++nt) {
            int col = bn + wn + nt * 8 + qid * 2;
            float bb0 = bias[col], bb1 = bias[col + 1];
            int r0 = bm + wm + mt * 16 + gid;
            float v00 = acc[mt][nt][0] + bb0, v01 = acc[mt][nt][1] + bb1;
            float v10 = acc[mt][nt][2] + bb0, v11 = acc[mt][nt][3] + bb1;
            if (OH) {
                size_t p0 = (size_t)r0 * DMODEL + col;
                size_t p1 = (size_t)(r0 + 8) * DMODEL + col;
                float h00 = __bfloat162float(__float2bfloat16_rn(v00));
                float h01 = __bfloat162float(__float2bfloat16_rn(v01));
                float h10 = __bfloat162float(__float2bfloat16_rn(v10));
                float h11 = __bfloat162float(__float2bfloat16_rn(v11));
                *(uint32_t*)&OH[p0] = pack_hi(v00, v01);
                *(uint32_t*)&OL[p0] = pack_hi(v00 - h00, v01 - h01);
                *(uint32_t*)&OH[p1] = pack_hi(v10, v11);
                *(uint32_t*)&OL[p1] = pack_hi(v10 - h10, v11 - h11);
            } else {
                *(float2*)&g_o[(size_t)r0 * DMODEL + col] = make_float2(v00, v01);
                *(float2*)&g_o[(size_t)(r0 + 8) * DMODEL + col] = make_float2(v10, v11);
            }
        }
    }
}

__global__ __launch_bounds__(256, 2)
void gemm_qkv(const float* __restrict__ b0p, const float* __restrict__ b1p,
              const float* __restrict__ b2p) {
    const int z = blockIdx.z;
    const __nv_bfloat16* AH = g_inh + (size_t)z * OUT_ELEMS;
    const __nv_bfloat16* AL = g_inl + (size_t)z * OUT_ELEMS;
    const __nv_bfloat16* WH = g_wh + (size_t)z * W_ELEMS;
    const __nv_bfloat16* WL = g_wl + (size_t)z * W_ELEMS;
    const float* bias = (z == 0) ? b0p : (z == 1) ? b1p : b2p;
    __nv_bfloat16* OH = (z == 0) ? g_qh : (z == 1) ? g_kh : g_vh;
    __nv_bfloat16* OL = (z == 0) ? g_ql : (z == 1) ? g_kl : g_vl;
    gemm_body(AH, AL, WH, WL, bias, OH, OL,
              blockIdx.y * 128, blockIdx.x * 128);
}

__global__ __launch_bounds__(256, 2)
void gemm_wo(const float* __restrict__ bo) {
    gemm_body(g_ctxh, g_ctxl, g_wh + (size_t)3 * W_ELEMS,
              g_wl + (size_t)3 * W_ELEMS, bo, nullptr, nullptr,
              blockIdx.y * 128, blockIdx.x * 128);
}

// ==================== tensor-core attention v4 ============================
// cp.async K/V pipeline + per-block tail rescale of its own attn rows.
#define ALD 72
#define TILE_B (64 * ALD * 2)                 // 9216 bytes
#define KV_OFF (2 * TILE_B)
#define TCA_SMEM (10 * TILE_B + 576)

__global__ __launch_bounds__(256, 2)
void attn_tc(float* __restrict__ gattn) {
    extern __shared__ __align__(16) char dsm[];
    __nv_bfloat16* Qh = (__nv_bfloat16*)dsm;
    __nv_bfloat16* Ql = (__nv_bfloat16*)(dsm + TILE_B);
    float* sPart = (float*)(dsm + 10 * TILE_B);
    float* red = (float*)(dsm + KV_OFF);      // aliases KV buf0 (post-loop)

    const int tid = threadIdx.x;
    const int lane = tid & 31;
    const int warp = tid >> 5;
    const int wy = warp & 3;
    const int wx = warp >> 2;
    const int lr = lane & 15;
    const int lh = lane >> 4;
    const int gid = lane >> 2;
    const int qid = lane & 3;

    const int q0 = blockIdx.x * 64;
    const int h = blockIdx.y;
    const int b = blockIdx.z;
    const size_t head_off = (size_t)b * SEQ * DMODEL + h * DHEAD;

    const uint32_t smem_base = (uint32_t)__cvta_generic_to_shared(dsm);

    const int r0c = tid >> 3, o0c = (tid & 7) * 8;
    const int r1c = 32 + (tid >> 3), o1c = (tid & 7) * 8;

#define KV_ISSUE(bufi, kc)                                                     \
    do {                                                                       \
        uint32_t sb = smem_base + KV_OFF + (bufi) * (4 * TILE_B);              \
        const size_t s0 = head_off + (size_t)((kc) + r0c) * DMODEL;            \
        const size_t s1 = head_off + (size_t)((kc) + r1c) * DMODEL;            \
        cp16(sb + 0 * TILE_B + (r0c * ALD + o0c) * 2, g_kh + s0 + o0c);        \
        cp16(sb + 0 * TILE_B + (r1c * ALD + o1c) * 2, g_kh + s1 + o1c);        \
        cp16(sb + 1 * TILE_B + (r0c * ALD + o0c) * 2, g_kl + s0 + o0c);        \
        cp16(sb + 1 * TILE_B + (r1c * ALD + o1c) * 2, g_kl + s1 + o1c);        \
        cp16(sb + 2 * TILE_B + (r0c * ALD + o0c) * 2, g_vh + s0 + o0c);        \
        cp16(sb + 2 * TILE_B + (r1c * ALD + o1c) * 2, g_vh + s1 + o1c);        \
        cp16(sb + 3 * TILE_B + (r0c * ALD + o0c) * 2, g_vl + s0 + o0c);        \
        cp16(sb + 3 * TILE_B + (r1c * ALD + o1c) * 2, g_vl + s1 + o1c);        \
    } while (0)

    {
        const int row = tid >> 2;
        const int cg = (tid & 3) * 16;
        const size_t src = head_off + (size_t)(q0 + row) * DMODEL + cg;
        *(uint4*)&Qh[row * ALD + cg]     = *(const uint4*)&g_qh[src];
        *(uint4*)&Qh[row * ALD + cg + 8] = *(const uint4*)&g_qh[src + 8];
        *(uint4*)&Ql[row * ALD + cg]     = *(const uint4*)&g_ql[src];
        *(uint4*)&Ql[row * ALD + cg + 8] = *(const uint4*)&g_ql[src + 8];
    }

    KV_ISSUE(0, 0);
    CP_COMMIT();
    KV_ISSUE(1, 64);
    CP_COMMIT();
    CP_WAIT1();
    __syncthreads();

    float ctx[8][4];
#pragma unroll
    for (int j = 0; j < 8; ++j)
#pragma unroll
        for (int r = 0; r < 4; ++r) ctx[j][r] = 0.f;
    float psum0 = 0.f, psum1 = 0.f;

    const int row0 = wy * 16 + gid;
    const size_t arow0 = (size_t)((b * NHEAD + h) * SEQ + q0 + row0);

    for (int c = 0; c < SEQ / 64; ++c) {
        const int buf = c & 1;
        const int kc = c * 64;
        __nv_bfloat16* Kh = (__nv_bfloat16*)(dsm + KV_OFF + buf * 4 * TILE_B);
        __nv_bfloat16* Kl = Kh + 64 * ALD;
        __nv_bfloat16* Vh = Kl + 64 * ALD;
        __nv_bfloat16* Vl = Vh + 64 * ALD;

        float s[4][4];
#pragma unroll
        for (int j = 0; j < 4; ++j)
#pragma unroll
            for (int r = 0; r < 4; ++r) s[j][r] = 0.f;

#pragma unroll
        for (int ks = 0; ks < 4; ++ks) {
            uint32_t aQh[4], aQl[4];
            ldsm_x4(aQh, (uint32_t)__cvta_generic_to_shared(
                &Qh[(wy * 16 + lr) * ALD + ks * 16 + lh * 8]));
            ldsm_x4(aQl, (uint32_t)__cvta_generic_to_shared(
                &Ql[(wy * 16 + lr) * ALD + ks * 16 + lh * 8]));
            uint32_t bKh[2][4], bKl[2][4];
            const int mat = lane >> 3, rr = lane & 7;
            const int keyo = (mat >> 1) * 8 + rr;
            const int dof = (mat & 1) * 8 + ks * 16;
#pragma unroll
            for (int g = 0; g < 2; ++g) {
                int key = wx * 32 + g * 16 + keyo;
                ldsm_x4(bKh[g], (uint32_t)__cvta_generic_to_shared(
                    &Kh[key * ALD + dof]));
                ldsm_x4(bKl[g], (uint32_t)__cvta_generic_to_shared(
                    &Kl[key * ALD + dof]));
            }
#pragma unroll
            for (int j = 0; j < 4; ++j) {
                const int g = j >> 1, p = (j & 1) * 2;
                mma16816(s[j], aQh, bKh[g][p], bKh[g][p + 1]);
                mma16816(s[j], aQh, bKl[g][p], bKl[g][p + 1]);
                mma16816(s[j], aQl, bKh[g][p], bKh[g][p + 1]);
            }
        }

        uint32_t aPh[2][4], aPl[2][4];
#pragma unroll
        for (int j = 0; j < 4; ++j) {
            float e0 = __expf(s[j][0] * 0.125f);
            float e1 = __expf(s[j][1] * 0.125f);
            float e2 = __expf(s[j][2] * 0.125f);
            float e3 = __expf(s[j][3] * 0.125f);
            psum0 += e0 + e1;
            psum1 += e2 + e3;
            const int col = wx * 32 + j * 8 + qid * 2;
            if (gattn) {
                __stcs((float2*)&gattn[arow0 * SEQ + kc + col], make_float2(e0, e1));
                __stcs((float2*)&gattn[(arow0 + 8) * SEQ + kc + col], make_float2(e2, e3));
            }
            float l0 = e0 - __bfloat162float(__float2bfloat16_rn(e0));
            float l1 = e1 - __bfloat162float(__float2bfloat16_rn(e1));
            float l2 = e2 - __bfloat162float(__float2bfloat16_rn(e2));
            float l3 = e3 - __bfloat162float(__float2bfloat16_rn(e3));
            const int t = j >> 1, half = j & 1;
            aPh[t][half * 2 + 0] = pack_hi(e0, e1);
            aPh[t][half * 2 + 1] = pack_hi(e2, e3);
            aPl[t][half * 2 + 0] = pack_hi(l0, l1);
            aPl[t][half * 2 + 1] = pack_hi(l2, l3);
        }

#pragma unroll
        for (int t = 0; t < 2; ++t) {
            const int kb = wx * 32 + t * 16;
#pragma unroll
            for (int np = 0; np < 4; ++np) {
                uint32_t bVh[4], bVl[4];
                ldsm_x4_t(bVh, (uint32_t)__cvta_generic_to_shared(
                    &Vh[(kb + lr) * ALD + np * 16 + lh * 8]));
                ldsm_x4_t(bVl, (uint32_t)__cvta_generic_to_shared(
                    &Vl[(kb + lr) * ALD + np * 16 + lh * 8]));
                mma16816(ctx[2 * np],     aPh[t], bVh[0], bVh[1]);
                mma16816(ctx[2 * np],     aPh[t], bVl[0], bVl[1]);
                mma16816(ctx[2 * np],     aPl[t], bVh[0], bVh[1]);
                mma16816(ctx[2 * np + 1], aPh[t], bVh[2], bVh[3]);
                mma16816(ctx[2 * np + 1], aPh[t], bVl[2], bVl[3]);
                mma16816(ctx[2 * np + 1], aPl[t], bVh[2], bVh[3]);
            }
        }

        __syncthreads();
        if (c + 2 < SEQ / 64) {
            KV_ISSUE(buf, (c + 2) * 64);
        }
        CP_COMMIT();
        CP_WAIT1();
        __syncthreads();
    }
#undef KV_ISSUE

    // ---- rowsum + cross-wx ctx reduction (red aliases KV buf0) ----------
    psum0 += __shfl_xor_sync(0xffffffffu, psum0, 1);
    psum0 += __shfl_xor_sync(0xffffffffu, psum0, 2);
    psum1 += __shfl_xor_sync(0xffffffffu, psum1, 1);
    psum1 += __shfl_xor_sync(0xffffffffu, psum1, 2);
    if (qid == 0) {
        sPart[wx * 64 + row0] = psum0;
        sPart[wx * 64 + row0 + 8] = psum1;
    }
    if (wx == 1) {
#pragma unroll
        for (int j = 0; j < 8; ++j) {
            *(float2*)&red[row0 * 68 + j * 8 + qid * 2] =
                make_float2(ctx[j][0], ctx[j][1]);
            *(float2*)&red[(row0 + 8) * 68 + j * 8 + qid * 2] =
                make_float2(ctx[j][2], ctx[j][3]);
        }
    }
    __syncthreads();
    if (wx == 0) {
        float tot0 = sPart[row0] + sPart[64 + row0];
        float tot1 = sPart[row0 + 8] + sPart[64 + row0 + 8];
        if (qid == 0) {
            g_rowsum[arow0] = tot0;
            g_rowsum[arow0 + 8] = tot1;
        }
        float inv0 = 1.0f / tot0, inv1 = 1.0f / tot1;
#pragma unroll
        for (int j = 0; j < 8; ++j) {
            const int col = j * 8 + qid * 2;
            float2 o0 = *(float2*)&red[row0 * 68 + col];
            float2 o1 = *(float2*)&red[(row0 + 8) * 68 + col];
            o0.x = (ctx[j][0] + o0.x) * inv0;
            o0.y = (ctx[j][1] + o0.y) * inv0;
            o1.x = (ctx[j][2] + o1.x) * inv1;
            o1.y = (ctx[j][3] + o1.y) * inv1;
            size_t p0 = (size_t)(b * SEQ + q0 + row0) * DMODEL + h * DHEAD + col;
            size_t p1 = (size_t)(b * SEQ + q0 + row0 + 8) * DMODEL + h * DHEAD + col;
            float h0x = __bfloat162float(__float2bfloat16_rn(o0.x));
            float h0y = __bfloat162float(__float2bfloat16_rn(o0.y));
            float h1x = __bfloat162float(__float2bfloat16_rn(o1.x));
            float h1y = __bfloat162float(__float2bfloat16_rn(o1.y));
            *(uint32_t*)&g_ctxh[p0] = pack_hi(o0.x, o0.y);
            *(uint32_t*)&g_ctxl[p0] = pack_hi(o0.x - h0x, o0.y - h0y);
            *(uint32_t*)&g_ctxh[p1] = pack_hi(o1.x, o1.y);
            *(uint32_t*)&g_ctxl[p1] = pack_hi(o1.x - h1x, o1.y - h1y);
        }
    }

    // ---- tail: rescale this block's own 64 attn rows ---------------------
    if (gattn) {
        __syncthreads();
        float4* p = (float4*)gattn;
        const size_t rowbase = (size_t)((b * NHEAD + h) * SEQ + q0);
#pragma unroll 1
        for (int r = 0; r < 64; r += 2) {
            float inv0 = 1.0f / (sPart[r] + sPart[64 + r]);
            float inv1 = 1.0f / (sPart[r + 1] + sPart[64 + r + 1]);
            size_t b0 = (rowbase + r) * (SEQ / 4);
            size_t b1 = b0 + (SEQ / 4);
            float4 v0 = __ldcs(&p[b0 + tid]);
            float4 v1 = __ldcs(&p[b0 + 256 + tid]);
            float4 v2 = __ldcs(&p[b1 + tid]);
            float4 v3 = __ldcs(&p[b1 + 256 + tid]);
            v0.x *= inv0; v0.y *= inv0; v0.z *= inv0; v0.w *= inv0;
            v1.x *= inv0; v1.y *= inv0; v1.z *= inv0; v1.w *= inv0;
            v2.x *= inv1; v2.y *= inv1; v2.z *= inv1; v2.w *= inv1;
            v3.x *= inv1; v3.y *= inv1; v3.z *= inv1; v3.w *= inv1;
            __stcs(&p[b0 + tid], v0);
            __stcs(&p[b0 + 256 + tid], v1);
            __stcs(&p[b1 + tid], v2);
            __stcs(&p[b1 + 256 + tid], v3);
        }
    }
}

// -------------------- LayerNorm ------------------------------------------
__global__ __launch_bounds__(256)
void ln_kernel(const float* __restrict__ gamma, const float* __restrict__ beta,
               float* __restrict__ out) {
    const int row = blockIdx.x;
    const int tid = threadIdx.x;
    __shared__ float red[8];

    float4 x = *(const float4*)&g_o[(size_t)row * DMODEL + tid * 4];
    float s = (x.x + x.y) + (x.z + x.w);
#pragma unroll
    for (int off = 16; off; off >>= 1) s += __shfl_xor_sync(0xffffffffu, s, off);
    if ((tid & 31) == 0) red[tid >> 5] = s;
    __syncthreads();
    float tot = 0.f;
#pragma unroll
    for (int i = 0; i < 8; ++i) tot += red[i];
    float mean = tot * (1.0f / 1024.0f);
    __syncthreads();

    float4 dx = make_float4(x.x - mean, x.y - mean, x.z - mean, x.w - mean);
    float ss = dx.x * dx.x + dx.y * dx.y + dx.z * dx.z + dx.w * dx.w;
#pragma unroll
    for (int off = 16; off; off >>= 1) ss += __shfl_xor_sync(0xffffffffu, ss, off);
    if ((tid & 31) == 0) red[tid >> 5] = ss;
    __syncthreads();
    float tss = 0.f;
#pragma unroll
    for (int i = 0; i < 8; ++i) tss += red[i];
    float var = tss * (1.0f / 1024.0f);
    float rstd = rsqrtf(var + 1e-3f);

    float4 g = *(const float4*)&gamma[tid * 4];
    float4 be = *(const float4*)&beta[tid * 4];
    float4 o;
    o.x = dx.x * rstd * g.x + be.x;
    o.y = dx.y * rstd * g.y + be.y;
    o.z = dx.z * rstd * g.z + be.z;
    o.w = dx.w * rstd * g.w + be.w;
    *(float4*)&out[(size_t)row * DMODEL + tid * 4] = o;
}

// -------------------- launcher --------------------------------------------
extern "C" void kernel_launch(void* const* d_in, const int* in_sizes, int n_in,
                              void* d_out, int out_size) {
    const float* query = (const float*)d_in[0];
    const float* key   = (const float*)d_in[1];
    const float* value = (const float*)d_in[2];
    const float* Wq = (const float*)d_in[3];
    const float* bq = (const float*)d_in[4];
    const float* Wk = (const float*)d_in[5];
    const float* bk = (const float*)d_in[6];
    const float* Wv = (const float*)d_in[7];
    const float* bv = (const float*)d_in[8];
    const float* Wo = (const float*)d_in[9];
    const float* bo = (const float*)d_in[10];
    const float* gamma = (const float*)d_in[11];
    const float* beta  = (const float*)d_in[12];

    float* out = (float*)d_out;
    float* attn = (out_size >= OUT_ELEMS + ATTN_ELEMS) ? (out + OUT_ELEMS) : nullptr;

    cudaFuncSetAttribute(attn_tc, cudaFuncAttributeMaxDynamicSharedMemorySize,
                         TCA_SMEM);
    cudaFuncSetAttribute(gemm_qkv, cudaFuncAttributeMaxDynamicSharedMemorySize,
                         GEMM_SMEM);
    cudaFuncSetAttribute(gemm_wo, cudaFuncAttributeMaxDynamicSharedMemorySize,
                         GEMM_SMEM);

    convert_split<<<dim3(OUT_ELEMS / 4 / 256, 1, 7), 256>>>(query, key, value,
                                                            Wq, Wk, Wv, Wo);

    gemm_qkv<<<dim3(DMODEL / 128, NROWS / 128, 3), 256, GEMM_SMEM>>>(bq, bk, bv);

    attn_tc<<<dim3(SEQ / 64, NHEAD, BATCH), 256, TCA_SMEM>>>(attn);

    gemm_wo<<<dim3(DMODEL / 128, NROWS / 128), 256, GEMM_SMEM>>>(bo);

    ln_kernel<<<NROWS, 256>>>(gamma, beta, out);
}

// round 14
// speedup vs baseline: 1.7793x; 1.0442x over previous
#include <cuda_runtime.h>
#include <cuda_bf16.h>
#include <math.h>
#include <stdint.h>

// Problem constants
#define SEQ   2048
#define BATCH 2
#define DMODEL 1024
#define NHEAD 16
#define DHEAD 64
#define NROWS (BATCH * SEQ)          // 4096
#define OUT_ELEMS   (NROWS * DMODEL)             // 4,194,304
#define W_ELEMS (DMODEL * DMODEL)                // 1,048,576
#define ATTN_ELEMS  (BATCH * NHEAD * SEQ * SEQ)  // 134,217,728

// -------------------- device scratch (no allocations allowed) ------------
__device__ float g_o[NROWS * DMODEL];
__device__ float g_rowsum[BATCH * NHEAD * SEQ];
__device__ __nv_bfloat16 g_inh[3 * OUT_ELEMS];
__device__ __nv_bfloat16 g_inl[3 * OUT_ELEMS];
__device__ __nv_bfloat16 g_wh[4 * W_ELEMS];
__device__ __nv_bfloat16 g_wl[4 * W_ELEMS];
__device__ __nv_bfloat16 g_qh[OUT_ELEMS], g_ql[OUT_ELEMS];
__device__ __nv_bfloat16 g_kh[OUT_ELEMS], g_kl[OUT_ELEMS];
__device__ __nv_bfloat16 g_vh[OUT_ELEMS], g_vl[OUT_ELEMS];
__device__ __nv_bfloat16 g_ctxh[OUT_ELEMS], g_ctxl[OUT_ELEMS];

// ==================== helpers ============================================
__device__ __forceinline__ void ldsm_x4(uint32_t (&r)[4], uint32_t addr) {
    asm volatile("ldmatrix.sync.aligned.m8n8.x4.shared.b16 {%0,%1,%2,%3}, [%4];"
                 : "=r"(r[0]), "=r"(r[1]), "=r"(r[2]), "=r"(r[3]) : "r"(addr));
}
__device__ __forceinline__ void ldsm_x4_t(uint32_t (&r)[4], uint32_t addr) {
    asm volatile("ldmatrix.sync.aligned.m8n8.x4.trans.shared.b16 {%0,%1,%2,%3}, [%4];"
                 : "=r"(r[0]), "=r"(r[1]), "=r"(r[2]), "=r"(r[3]) : "r"(addr));
}
__device__ __forceinline__ void mma16816(float (&c)[4], const uint32_t (&a)[4],
                                         uint32_t b0, uint32_t b1) {
    asm volatile(
        "mma.sync.aligned.m16n8k16.row.col.f32.bf16.bf16.f32 "
        "{%0,%1,%2,%3}, {%4,%5,%6,%7}, {%8,%9}, {%0,%1,%2,%3};"
        : "+f"(c[0]), "+f"(c[1]), "+f"(c[2]), "+f"(c[3])
        : "r"(a[0]), "r"(a[1]), "r"(a[2]), "r"(a[3]), "r"(b0), "r"(b1));
}
__device__ __forceinline__ uint32_t pack_hi(float x, float y) {
    __nv_bfloat162 h = __floats2bfloat162_rn(x, y);
    return *(uint32_t*)&h;
}
__device__ __forceinline__ void cp16(uint32_t dst, const void* src) {
    asm volatile("cp.async.cg.shared.global [%0], [%1], 16;" :: "r"(dst), "l"(src));
}
#define CP_COMMIT() asm volatile("cp.async.commit_group;")
#define CP_WAIT1()  asm volatile("cp.async.wait_group 1;" ::: "memory")

// ==================== split-bf16 conversion pass ==========================
__global__ __launch_bounds__(256)
void convert_split(const float* __restrict__ q, const float* __restrict__ k,
                   const float* __restrict__ v, const float* __restrict__ wq,
                   const float* __restrict__ wk, const float* __restrict__ wv,
                   const float* __restrict__ wo) {
    const int z = blockIdx.z;
    const float* src;
    __nv_bfloat16 *dh, *dl;
    int n4;
    if (z < 3) {
        src = (z == 0) ? q : (z == 1) ? k : v;
        dh = g_inh + (size_t)z * OUT_ELEMS;
        dl = g_inl + (size_t)z * OUT_ELEMS;
        n4 = OUT_ELEMS / 4;
    } else {
        src = (z == 3) ? wq : (z == 4) ? wk : (z == 5) ? wv : wo;
        dh = g_wh + (size_t)(z - 3) * W_ELEMS;
        dl = g_wl + (size_t)(z - 3) * W_ELEMS;
        n4 = W_ELEMS / 4;
    }
    int i = blockIdx.x * 256 + threadIdx.x;
    if (i >= n4) return;
    float4 x = ((const float4*)src)[i];
    float hx = __bfloat162float(__float2bfloat16_rn(x.x));
    float hy = __bfloat162float(__float2bfloat16_rn(x.y));
    float hz = __bfloat162float(__float2bfloat16_rn(x.z));
    float hw = __bfloat162float(__float2bfloat16_rn(x.w));
    uint2 oh = make_uint2(pack_hi(x.x, x.y), pack_hi(x.z, x.w));
    uint2 ol = make_uint2(pack_hi(x.x - hx, x.y - hy), pack_hi(x.z - hz, x.w - hw));
    *(uint2*)&dh[(size_t)i * 4] = oh;
    *(uint2*)&dl[(size_t)i * 4] = ol;
}

// ==================== shared GEMM body (3-stage cp.async) =================
#define A_LD 40
#define B_LD 136
#define OFF_AH 0
#define OFF_AL (128 * A_LD)
#define OFF_BH (2 * 128 * A_LD)
#define OFF_BL (2 * 128 * A_LD + 32 * B_LD)
#define BUF_ELEMS (2 * 128 * A_LD + 2 * 32 * B_LD)      // 18944 bf16
#define GEMM_SMEM (3 * BUF_ELEMS * 2)                   // 113664 bytes

__device__ __forceinline__ void gemm_body(
    const __nv_bfloat16* __restrict__ AH, const __nv_bfloat16* __restrict__ AL,
    const __nv_bfloat16* __restrict__ WH, const __nv_bfloat16* __restrict__ WL,
    const float* __restrict__ bias, __nv_bfloat16* OH, __nv_bfloat16* OL,
    int bm, int bn) {
    extern __shared__ __align__(16) __nv_bfloat16 gsm[];

    const int tid = threadIdx.x;
    const int lane = tid & 31;
    const int warp = tid >> 5;
    const int wm = (warp & 3) * 32;
    const int wn = (warp >> 2) * 64;
    const int lr = lane & 15;
    const int lh = lane >> 4;

    const uint32_t smem_base = (uint32_t)__cvta_generic_to_shared(gsm);

    float acc[2][8][4];
#pragma unroll
    for (int i = 0; i < 2; ++i)
#pragma unroll
        for (int j = 0; j < 8; ++j)
#pragma unroll
            for (int r = 0; r < 4; ++r) acc[i][j][r] = 0.f;

    const int ar0 = tid >> 2, ao0 = (tid & 3) * 8;
    const int ar1 = (tid + 256) >> 2, ao1 = ((tid + 256) & 3) * 8;
    const int br0 = tid >> 4, bo0 = (tid & 15) * 8;
    const int br1 = (tid + 256) >> 4, bo1 = ((tid + 256) & 15) * 8;

#define ISSUE(bufi, k0)                                                        \
    do {                                                                       \
        uint32_t sb = smem_base + (bufi) * (BUF_ELEMS * 2);                    \
        cp16(sb + (OFF_AH + ar0 * A_LD + ao0) * 2,                             \
             AH + (size_t)(bm + ar0) * DMODEL + (k0) + ao0);                   \
        cp16(sb + (OFF_AH + ar1 * A_LD + ao1) * 2,                             \
             AH + (size_t)(bm + ar1) * DMODEL + (k0) + ao1);                   \
        cp16(sb + (OFF_AL + ar0 * A_LD + ao0) * 2,                             \
             AL + (size_t)(bm + ar0) * DMODEL + (k0) + ao0);                   \
        cp16(sb + (OFF_AL + ar1 * A_LD + ao1) * 2,                             \
             AL + (size_t)(bm + ar1) * DMODEL + (k0) + ao1);                   \
        cp16(sb + (OFF_BH + br0 * B_LD + bo0) * 2,                             \
             WH + (size_t)((k0) + br0) * DMODEL + bn + bo0);                   \
        cp16(sb + (OFF_BH + br1 * B_LD + bo1) * 2,                             \
             WH + (size_t)((k0) + br1) * DMODEL + bn + bo1);                   \
        cp16(sb + (OFF_BL + br0 * B_LD + bo0) * 2,                             \
             WL + (size_t)((k0) + br0) * DMODEL + bn + bo0);                   \
        cp16(sb + (OFF_BL + br1 * B_LD + bo1) * 2,                             \
             WL + (size_t)((k0) + br1) * DMODEL + bn + bo1);                   \
    } while (0)

    // prologue: chunks 0 and 1 into bufs 0,1
    ISSUE(0, 0);
    CP_COMMIT();
    ISSUE(1, 32);
    CP_COMMIT();

    // mainloop: one sync per iteration (3-stage ring)
    for (int c = 0; c < DMODEL / 32; ++c) {
        CP_WAIT1();            // chunk c's group complete (chunk c+1 may pend)
        __syncthreads();       // visibility + all warps done reading buf (c-1)%3
        const int buf = c % 3;
        const __nv_bfloat16* Ah = gsm + buf * BUF_ELEMS + OFF_AH;
        const __nv_bfloat16* Al = gsm + buf * BUF_ELEMS + OFF_AL;
        const __nv_bfloat16* Bh = gsm + buf * BUF_ELEMS + OFF_BH;
        const __nv_bfloat16* Bl = gsm + buf * BUF_ELEMS + OFF_BL;
#pragma unroll
        for (int ks = 0; ks < 2; ++ks) {
            uint32_t afh[2][4], afl[2][4];
#pragma unroll
            for (int mt = 0; mt < 2; ++mt) {
                ldsm_x4(afh[mt], (uint32_t)__cvta_generic_to_shared(
                    &Ah[(wm + mt * 16 + lr) * A_LD + ks * 16 + lh * 8]));
                ldsm_x4(afl[mt], (uint32_t)__cvta_generic_to_shared(
                    &Al[(wm + mt * 16 + lr) * A_LD + ks * 16 + lh * 8]));
            }
#pragma unroll
            for (int np = 0; np < 4; ++np) {
                uint32_t bfh[4], bfl[4];
                ldsm_x4_t(bfh, (uint32_t)__cvta_generic_to_shared(
                    &Bh[(ks * 16 + lr) * B_LD + wn + np * 16 + lh * 8]));
                ldsm_x4_t(bfl, (uint32_t)__cvta_generic_to_shared(
                    &Bl[(ks * 16 + lr) * B_LD + wn + np * 16 + lh * 8]));
#pragma unroll
                for (int mt = 0; mt < 2; ++mt) {
                    mma16816(acc[mt][2 * np],     afh[mt], bfh[0], bfh[1]);
                    mma16816(acc[mt][2 * np],     afh[mt], bfl[0], bfl[1]);
                    mma16816(acc[mt][2 * np],     afl[mt], bfh[0], bfh[1]);
                    mma16816(acc[mt][2 * np + 1], afh[mt], bfh[2], bfh[3]);
                    mma16816(acc[mt][2 * np + 1], afh[mt], bfl[2], bfl[3]);
                    mma16816(acc[mt][2 * np + 1], afl[mt], bfh[2], bfh[3]);
                }
            }
        }
        // refill buf (c+2)%3 == (c-1+3)%3 (freed by the sync above)
        if (c + 2 < DMODEL / 32) {
            ISSUE((c + 2) % 3, (c + 2) * 32);
        }
        CP_COMMIT();           // empty group when nothing issued keeps count
    }
#undef ISSUE

    const int gid = lane >> 2;
    const int qid = lane & 3;
#pragma unroll
    for (int mt = 0; mt < 2; ++mt) {
#pragma unroll
        for (int nt = 0; nt < 8; ++nt) {
            int col = bn + wn + nt * 8 + qid * 2;
            float bb0 = bias[col], bb1 = bias[col + 1];
            int r0 = bm + wm + mt * 16 + gid;
            float v00 = acc[mt][nt][0] + bb0, v01 = acc[mt][nt][1] + bb1;
            float v10 = acc[mt][nt][2] + bb0, v11 = acc[mt][nt][3] + bb1;
            if (OH) {
                size_t p0 = (size_t)r0 * DMODEL + col;
                size_t p1 = (size_t)(r0 + 8) * DMODEL + col;
                float h00 = __bfloat162float(__float2bfloat16_rn(v00));
                float h01 = __bfloat162float(__float2bfloat16_rn(v01));
                float h10 = __bfloat162float(__float2bfloat16_rn(v10));
                float h11 = __bfloat162float(__float2bfloat16_rn(v11));
                *(uint32_t*)&OH[p0] = pack_hi(v00, v01);
                *(uint32_t*)&OL[p0] = pack_hi(v00 - h00, v01 - h01);
                *(uint32_t*)&OH[p1] = pack_hi(v10, v11);
                *(uint32_t*)&OL[p1] = pack_hi(v10 - h10, v11 - h11);
            } else {
                *(float2*)&g_o[(size_t)r0 * DMODEL + col] = make_float2(v00, v01);
                *(float2*)&g_o[(size_t)(r0 + 8) * DMODEL + col] = make_float2(v10, v11);
            }
        }
    }
}

__global__ __launch_bounds__(256, 2)
void gemm_qkv(const float* __restrict__ b0p, const float* __restrict__ b1p,
              const float* __restrict__ b2p) {
    const int z = blockIdx.z;
    const __nv_bfloat16* AH = g_inh + (size_t)z * OUT_ELEMS;
    const __nv_bfloat16* AL = g_inl + (size_t)z * OUT_ELEMS;
    const __nv_bfloat16* WH = g_wh + (size_t)z * W_ELEMS;
    const __nv_bfloat16* WL = g_wl + (size_t)z * W_ELEMS;
    const float* bias = (z == 0) ? b0p : (z == 1) ? b1p : b2p;
    __nv_bfloat16* OH = (z == 0) ? g_qh : (z == 1) ? g_kh : g_vh;
    __nv_bfloat16* OL = (z == 0) ? g_ql : (z == 1) ? g_kl : g_vl;
    gemm_body(AH, AL, WH, WL, bias, OH, OL,
              blockIdx.y * 128, blockIdx.x * 128);
}

__global__ __launch_bounds__(256, 2)
void gemm_wo(const float* __restrict__ bo) {
    gemm_body(g_ctxh, g_ctxl, g_wh + (size_t)3 * W_ELEMS,
              g_wl + (size_t)3 * W_ELEMS, bo, nullptr, nullptr,
              blockIdx.y * 128, blockIdx.x * 128);
}

// ==================== tensor-core attention v4 (unchanged from R13) =======
#define ALD 72
#define TILE_B (64 * ALD * 2)                 // 9216 bytes
#define KV_OFF (2 * TILE_B)
#define TCA_SMEM (10 * TILE_B + 576)

__global__ __launch_bounds__(256, 2)
void attn_tc(float* __restrict__ gattn) {
    extern __shared__ __align__(16) char dsm[];
    __nv_bfloat16* Qh = (__nv_bfloat16*)dsm;
    __nv_bfloat16* Ql = (__nv_bfloat16*)(dsm + TILE_B);
    float* sPart = (float*)(dsm + 10 * TILE_B);
    float* red = (float*)(dsm + KV_OFF);      // aliases KV buf0 (post-loop)

    const int tid = threadIdx.x;
    const int lane = tid & 31;
    const int warp = tid >> 5;
    const int wy = warp & 3;
    const int wx = warp >> 2;
    const int lr = lane & 15;
    const int lh = lane >> 4;
    const int gid = lane >> 2;
    const int qid = lane & 3;

    const int q0 = blockIdx.x * 64;
    const int h = blockIdx.y;
    const int b = blockIdx.z;
    const size_t head_off = (size_t)b * SEQ * DMODEL + h * DHEAD;

    const uint32_t smem_base = (uint32_t)__cvta_generic_to_shared(dsm);

    const int r0c = tid >> 3, o0c = (tid & 7) * 8;
    const int r1c = 32 + (tid >> 3), o1c = (tid & 7) * 8;

#define KV_ISSUE(bufi, kc)                                                     \
    do {                                                                       \
        uint32_t sb = smem_base + KV_OFF + (bufi) * (4 * TILE_B);              \
        const size_t s0 = head_off + (size_t)((kc) + r0c) * DMODEL;            \
        const size_t s1 = head_off + (size_t)((kc) + r1c) * DMODEL;            \
        cp16(sb + 0 * TILE_B + (r0c * ALD + o0c) * 2, g_kh + s0 + o0c);        \
        cp16(sb + 0 * TILE_B + (r1c * ALD + o1c) * 2, g_kh + s1 + o1c);        \
        cp16(sb + 1 * TILE_B + (r0c * ALD + o0c) * 2, g_kl + s0 + o0c);        \
        cp16(sb + 1 * TILE_B + (r1c * ALD + o1c) * 2, g_kl + s1 + o1c);        \
        cp16(sb + 2 * TILE_B + (r0c * ALD + o0c) * 2, g_vh + s0 + o0c);        \
        cp16(sb + 2 * TILE_B + (r1c * ALD + o1c) * 2, g_vh + s1 + o1c);        \
        cp16(sb + 3 * TILE_B + (r0c * ALD + o0c) * 2, g_vl + s0 + o0c);        \
        cp16(sb + 3 * TILE_B + (r1c * ALD + o1c) * 2, g_vl + s1 + o1c);        \
    } while (0)

    {
        const int row = tid >> 2;
        const int cg = (tid & 3) * 16;
        const size_t src = head_off + (size_t)(q0 + row) * DMODEL + cg;
        *(uint4*)&Qh[row * ALD + cg]     = *(const uint4*)&g_qh[src];
        *(uint4*)&Qh[row * ALD + cg + 8] = *(const uint4*)&g_qh[src + 8];
        *(uint4*)&Ql[row * ALD + cg]     = *(const uint4*)&g_ql[src];
        *(uint4*)&Ql[row * ALD + cg + 8] = *(const uint4*)&g_ql[src + 8];
    }

    KV_ISSUE(0, 0);
    CP_COMMIT();
    KV_ISSUE(1, 64);
    CP_COMMIT();
    CP_WAIT1();
    __syncthreads();

    float ctx[8][4];
#pragma unroll
    for (int j = 0; j < 8; ++j)
#pragma unroll
        for (int r = 0; r < 4; ++r) ctx[j][r] = 0.f;
    float psum0 = 0.f, psum1 = 0.f;

    const int row0 = wy * 16 + gid;
    const size_t arow0 = (size_t)((b * NHEAD + h) * SEQ + q0 + row0);

    for (int c = 0; c < SEQ / 64; ++c) {
        const int buf = c & 1;
        const int kc = c * 64;
        __nv_bfloat16* Kh = (__nv_bfloat16*)(dsm + KV_OFF + buf * 4 * TILE_B);
        __nv_bfloat16* Kl = Kh + 64 * ALD;
        __nv_bfloat16* Vh = Kl + 64 * ALD;
        __nv_bfloat16* Vl = Vh + 64 * ALD;

        float s[4][4];
#pragma unroll
        for (int j = 0; j < 4; ++j)
#pragma unroll
            for (int r = 0; r < 4; ++r) s[j][r] = 0.f;

#pragma unroll
        for (int ks = 0; ks < 4; ++ks) {
            uint32_t aQh[4], aQl[4];
            ldsm_x4(aQh, (uint32_t)__cvta_generic_to_shared(
                &Qh[(wy * 16 + lr) * ALD + ks * 16 + lh * 8]));
            ldsm_x4(aQl, (uint32_t)__cvta_generic_to_shared(
                &Ql[(wy * 16 + lr) * ALD + ks * 16 + lh * 8]));
            uint32_t bKh[2][4], bKl[2][4];
            const int mat = lane >> 3, rr = lane & 7;
            const int keyo = (mat >> 1) * 8 + rr;
            const int dof = (mat & 1) * 8 + ks * 16;
#pragma unroll
            for (int g = 0; g < 2; ++g) {
                int key = wx * 32 + g * 16 + keyo;
                ldsm_x4(bKh[g], (uint32_t)__cvta_generic_to_shared(
                    &Kh[key * ALD + dof]));
                ldsm_x4(bKl[g], (uint32_t)__cvta_generic_to_shared(
                    &Kl[key * ALD + dof]));
            }
#pragma unroll
            for (int j = 0; j < 4; ++j) {
                const int g = j >> 1, p = (j & 1) * 2;
                mma16816(s[j], aQh, bKh[g][p], bKh[g][p + 1]);
                mma16816(s[j], aQh, bKl[g][p], bKl[g][p + 1]);
                mma16816(s[j], aQl, bKh[g][p], bKh[g][p + 1]);
            }
        }

        uint32_t aPh[2][4], aPl[2][4];
#pragma unroll
        for (int j = 0; j < 4; ++j) {
            float e0 = __expf(s[j][0] * 0.125f);
            float e1 = __expf(s[j][1] * 0.125f);
            float e2 = __expf(s[j][2] * 0.125f);
            float e3 = __expf(s[j][3] * 0.125f);
            psum0 += e0 + e1;
            psum1 += e2 + e3;
            const int col = wx * 32 + j * 8 + qid * 2;
            if (gattn) {
                __stcs((float2*)&gattn[arow0 * SEQ + kc + col], make_float2(e0, e1));
                __stcs((float2*)&gattn[(arow0 + 8) * SEQ + kc + col], make_float2(e2, e3));
            }
            float l0 = e0 - __bfloat162float(__float2bfloat16_rn(e0));
            float l1 = e1 - __bfloat162float(__float2bfloat16_rn(e1));
            float l2 = e2 - __bfloat162float(__float2bfloat16_rn(e2));
            float l3 = e3 - __bfloat162float(__float2bfloat16_rn(e3));
            const int t = j >> 1, half = j & 1;
            aPh[t][half * 2 + 0] = pack_hi(e0, e1);
            aPh[t][half * 2 + 1] = pack_hi(e2, e3);
            aPl[t][half * 2 + 0] = pack_hi(l0, l1);
            aPl[t][half * 2 + 1] = pack_hi(l2, l3);
        }

#pragma unroll
        for (int t = 0; t < 2; ++t) {
            const int kb = wx * 32 + t * 16;
#pragma unroll
            for (int np = 0; np < 4; ++np) {
                uint32_t bVh[4], bVl[4];
                ldsm_x4_t(bVh, (uint32_t)__cvta_generic_to_shared(
                    &Vh[(kb + lr) * ALD + np * 16 + lh * 8]));
                ldsm_x4_t(bVl, (uint32_t)__cvta_generic_to_shared(
                    &Vl[(kb + lr) * ALD + np * 16 + lh * 8]));
                mma16816(ctx[2 * np],     aPh[t], bVh[0], bVh[1]);
                mma16816(ctx[2 * np],     aPh[t], bVl[0], bVl[1]);
                mma16816(ctx[2 * np],     aPl[t], bVh[0], bVh[1]);
                mma16816(ctx[2 * np + 1], aPh[t], bVh[2], bVh[3]);
                mma16816(ctx[2 * np + 1], aPh[t], bVl[2], bVl[3]);
                mma16816(ctx[2 * np + 1], aPl[t], bVh[2], bVh[3]);
            }
        }

        __syncthreads();
        if (c + 2 < SEQ / 64) {
            KV_ISSUE(buf, (c + 2) * 64);
        }
        CP_COMMIT();
        CP_WAIT1();
        __syncthreads();
    }
#undef KV_ISSUE

    // ---- rowsum + cross-wx ctx reduction (red aliases KV buf0) ----------
    psum0 += __shfl_xor_sync(0xffffffffu, psum0, 1);
    psum0 += __shfl_xor_sync(0xffffffffu, psum0, 2);
    psum1 += __shfl_xor_sync(0xffffffffu, psum1, 1);
    psum1 += __shfl_xor_sync(0xffffffffu, psum1, 2);
    if (qid == 0) {
        sPart[wx * 64 + row0] = psum0;
        sPart[wx * 64 + row0 + 8] = psum1;
    }
    if (wx == 1) {
#pragma unroll
        for (int j = 0; j < 8; ++j) {
            *(float2*)&red[row0 * 68 + j * 8 + qid * 2] =
                make_float2(ctx[j][0], ctx[j][1]);
            *(float2*)&red[(row0 + 8) * 68 + j * 8 + qid * 2] =
                make_float2(ctx[j][2], ctx[j][3]);
        }
    }
    __syncthreads();
    if (wx == 0) {
        float tot0 = sPart[row0] + sPart[64 + row0];
        float tot1 = sPart[row0 + 8] + sPart[64 + row0 + 8];
        if (qid == 0) {
            g_rowsum[arow0] = tot0;
            g_rowsum[arow0 + 8] = tot1;
        }
        float inv0 = 1.0f / tot0, inv1 = 1.0f / tot1;
#pragma unroll
        for (int j = 0; j < 8; ++j) {
            const int col = j * 8 + qid * 2;
            float2 o0 = *(float2*)&red[row0 * 68 + col];
            float2 o1 = *(float2*)&red[(row0 + 8) * 68 + col];
            o0.x = (ctx[j][0] + o0.x) * inv0;
            o0.y = (ctx[j][1] + o0.y) * inv0;
            o1.x = (ctx[j][2] + o1.x) * inv1;
            o1.y = (ctx[j][3] + o1.y) * inv1;
            size_t p0 = (size_t)(b * SEQ + q0 + row0) * DMODEL + h * DHEAD + col;
            size_t p1 = (size_t)(b * SEQ + q0 + row0 + 8) * DMODEL + h * DHEAD + col;
            float h0x = __bfloat162float(__float2bfloat16_rn(o0.x));
            float h0y = __bfloat162float(__float2bfloat16_rn(o0.y));
            float h1x = __bfloat162float(__float2bfloat16_rn(o1.x));
            float h1y = __bfloat162float(__float2bfloat16_rn(o1.y));
            *(uint32_t*)&g_ctxh[p0] = pack_hi(o0.x, o0.y);
            *(uint32_t*)&g_ctxl[p0] = pack_hi(o0.x - h0x, o0.y - h0y);
            *(uint32_t*)&g_ctxh[p1] = pack_hi(o1.x, o1.y);
            *(uint32_t*)&g_ctxl[p1] = pack_hi(o1.x - h1x, o1.y - h1y);
        }
    }

    // ---- tail: rescale this block's own 64 attn rows ---------------------
    if (gattn) {
        __syncthreads();
        float4* p = (float4*)gattn;
        const size_t rowbase = (size_t)((b * NHEAD + h) * SEQ + q0);
#pragma unroll 1
        for (int r = 0; r < 64; r += 2) {
            float inv0 = 1.0f / (sPart[r] + sPart[64 + r]);
            float inv1 = 1.0f / (sPart[r + 1] + sPart[64 + r + 1]);
            size_t b0 = (rowbase + r) * (SEQ / 4);
            size_t b1 = b0 + (SEQ / 4);
            float4 v0 = __ldcs(&p[b0 + tid]);
            float4 v1 = __ldcs(&p[b0 + 256 + tid]);
            float4 v2 = __ldcs(&p[b1 + tid]);
            float4 v3 = __ldcs(&p[b1 + 256 + tid]);
            v0.x *= inv0; v0.y *= inv0; v0.z *= inv0; v0.w *= inv0;
            v1.x *= inv0; v1.y *= inv0; v1.z *= inv0; v1.w *= inv0;
            v2.x *= inv1; v2.y *= inv1; v2.z *= inv1; v2.w *= inv1;
            v3.x *= inv1; v3.y *= inv1; v3.z *= inv1; v3.w *= inv1;
            __stcs(&p[b0 + tid], v0);
            __stcs(&p[b0 + 256 + tid], v1);
            __stcs(&p[b1 + tid], v2);
            __stcs(&p[b1 + 256 + tid], v3);
        }
    }
}

// -------------------- LayerNorm ------------------------------------------
__global__ __launch_bounds__(256)
void ln_kernel(const float* __restrict__ gamma, const float* __restrict__ beta,
               float* __restrict__ out) {
    const int row = blockIdx.x;
    const int tid = threadIdx.x;
    __shared__ float red[8];

    float4 x = *(const float4*)&g_o[(size_t)row * DMODEL + tid * 4];
    float s = (x.x + x.y) + (x.z + x.w);
#pragma unroll
    for (int off = 16; off; off >>= 1) s += __shfl_xor_sync(0xffffffffu, s, off);
    if ((tid & 31) == 0) red[tid >> 5] = s;
    __syncthreads();
    float tot = 0.f;
#pragma unroll
    for (int i = 0; i < 8; ++i) tot += red[i];
    float mean = tot * (1.0f / 1024.0f);
    __syncthreads();

    float4 dx = make_float4(x.x - mean, x.y - mean, x.z - mean, x.w - mean);
    float ss = dx.x * dx.x + dx.y * dx.y + dx.z * dx.z + dx.w * dx.w;
#pragma unroll
    for (int off = 16; off; off >>= 1) ss += __shfl_xor_sync(0xffffffffu, ss, off);
    if ((tid & 31) == 0) red[tid >> 5] = ss;
    __syncthreads();
    float tss = 0.f;
#pragma unroll
    for (int i = 0; i < 8; ++i) tss += red[i];
    float var = tss * (1.0f / 1024.0f);
    float rstd = rsqrtf(var + 1e-3f);

    float4 g = *(const float4*)&gamma[tid * 4];
    float4 be = *(const float4*)&beta[tid * 4];
    float4 o;
    o.x = dx.x * rstd * g.x + be.x;
    o.y = dx.y * rstd * g.y + be.y;
    o.z = dx.z * rstd * g.z + be.z;
    o.w = dx.w * rstd * g.w + be.w;
    *(float4*)&out[(size_t)row * DMODEL + tid * 4] = o;
}

// -------------------- launcher --------------------------------------------
extern "C" void kernel_launch(void* const* d_in, const int* in_sizes, int n_in,
                              void* d_out, int out_size) {
    const float* query = (const float*)d_in[0];
    const float* key   = (const float*)d_in[1];
    const float* value = (const float*)d_in[2];
    const float* Wq = (const float*)d_in[3];
    const float* bq = (const float*)d_in[4];
    const float* Wk = (const float*)d_in[5];
    const float* bk = (const float*)d_in[6];
    const float* Wv = (const float*)d_in[7];
    const float* bv = (const float*)d_in[8];
    const float* Wo = (const float*)d_in[9];
    const float* bo = (const float*)d_in[10];
    const float* gamma = (const float*)d_in[11];
    const float* beta  = (const float*)d_in[12];

    float* out = (float*)d_out;
    float* attn = (out_size >= OUT_ELEMS + ATTN_ELEMS) ? (out + OUT_ELEMS) : nullptr;

    cudaFuncSetAttribute(attn_tc, cudaFuncAttributeMaxDynamicSharedMemorySize,
                         TCA_SMEM);
    cudaFuncSetAttribute(gemm_qkv, cudaFuncAttributeMaxDynamicSharedMemorySize,
                         GEMM_SMEM);
    cudaFuncSetAttribute(gemm_wo, cudaFuncAttributeMaxDynamicSharedMemorySize,
                         GEMM_SMEM);

    convert_split<<<dim3(OUT_ELEMS / 4 / 256, 1, 7), 256>>>(query, key, value,
                                                            Wq, Wk, Wv, Wo);

    gemm_qkv<<<dim3(DMODEL / 128, NROWS / 128, 3), 256, GEMM_SMEM>>>(bq, bk, bv);

    attn_tc<<<dim3(SEQ / 64, NHEAD, BATCH), 256, TCA_SMEM>>>(attn);

    gemm_wo<<<dim3(DMODEL / 128, NROWS / 128), 256, GEMM_SMEM>>>(bo);

    ln_kernel<<<NROWS, 256>>>(gamma, beta, out);
}

// round 15
// speedup vs baseline: 1.7869x; 1.0042x over previous
#include <cuda_runtime.h>
#include <cuda_bf16.h>
#include <math.h>
#include <stdint.h>

// Problem constants
#define SEQ   2048
#define BATCH 2
#define DMODEL 1024
#define NHEAD 16
#define DHEAD 64
#define NROWS (BATCH * SEQ)          // 4096
#define OUT_ELEMS   (NROWS * DMODEL)             // 4,194,304
#define W_ELEMS (DMODEL * DMODEL)                // 1,048,576
#define ATTN_ELEMS  (BATCH * NHEAD * SEQ * SEQ)  // 134,217,728

// -------------------- device scratch (no allocations allowed) ------------
__device__ float g_o[NROWS * DMODEL];
__device__ float g_rowsum[BATCH * NHEAD * SEQ];
__device__ __nv_bfloat16 g_inh[3 * OUT_ELEMS];
__device__ __nv_bfloat16 g_inl[3 * OUT_ELEMS];
__device__ __nv_bfloat16 g_wh[4 * W_ELEMS];
__device__ __nv_bfloat16 g_wl[4 * W_ELEMS];
__device__ __nv_bfloat16 g_qh[OUT_ELEMS], g_ql[OUT_ELEMS];
__device__ __nv_bfloat16 g_kh[OUT_ELEMS], g_kl[OUT_ELEMS];
__device__ __nv_bfloat16 g_vh[OUT_ELEMS], g_vl[OUT_ELEMS];
__device__ __nv_bfloat16 g_ctxh[OUT_ELEMS], g_ctxl[OUT_ELEMS];

// ==================== helpers ============================================
__device__ __forceinline__ void ldsm_x4(uint32_t (&r)[4], uint32_t addr) {
    asm volatile("ldmatrix.sync.aligned.m8n8.x4.shared.b16 {%0,%1,%2,%3}, [%4];"
                 : "=r"(r[0]), "=r"(r[1]), "=r"(r[2]), "=r"(r[3]) : "r"(addr));
}
__device__ __forceinline__ void ldsm_x4_t(uint32_t (&r)[4], uint32_t addr) {
    asm volatile("ldmatrix.sync.aligned.m8n8.x4.trans.shared.b16 {%0,%1,%2,%3}, [%4];"
                 : "=r"(r[0]), "=r"(r[1]), "=r"(r[2]), "=r"(r[3]) : "r"(addr));
}
__device__ __forceinline__ void mma16816(float (&c)[4], const uint32_t (&a)[4],
                                         uint32_t b0, uint32_t b1) {
    asm volatile(
        "mma.sync.aligned.m16n8k16.row.col.f32.bf16.bf16.f32 "
        "{%0,%1,%2,%3}, {%4,%5,%6,%7}, {%8,%9}, {%0,%1,%2,%3};"
        : "+f"(c[0]), "+f"(c[1]), "+f"(c[2]), "+f"(c[3])
        : "r"(a[0]), "r"(a[1]), "r"(a[2]), "r"(a[3]), "r"(b0), "r"(b1));
}
__device__ __forceinline__ uint32_t pack_hi(float x, float y) {
    __nv_bfloat162 h = __floats2bfloat162_rn(x, y);
    return *(uint32_t*)&h;
}
// truncation split: bf16x2 of high halves (1 PRMT)
__device__ __forceinline__ uint32_t pack_trunc(float x, float y) {
    return __byte_perm(__float_as_uint(x), __float_as_uint(y), 0x7632);
}
__device__ __forceinline__ float trunc_hi(float x) {
    return __uint_as_float(__float_as_uint(x) & 0xffff0000u);
}
__device__ __forceinline__ void cp16(uint32_t dst, const void* src) {
    asm volatile("cp.async.cg.shared.global [%0], [%1], 16;" :: "r"(dst), "l"(src));
}
#define CP_COMMIT() asm volatile("cp.async.commit_group;")
#define CP_WAIT1()  asm volatile("cp.async.wait_group 1;" ::: "memory")

// ==================== split-bf16 conversion pass ==========================
__global__ __launch_bounds__(256)
void convert_split(const float* __restrict__ q, const float* __restrict__ k,
                   const float* __restrict__ v, const float* __restrict__ wq,
                   const float* __restrict__ wk, const float* __restrict__ wv,
                   const float* __restrict__ wo) {
    const int z = blockIdx.z;
    const float* src;
    __nv_bfloat16 *dh, *dl;
    int n4;
    if (z < 3) {
        src = (z == 0) ? q : (z == 1) ? k : v;
        dh = g_inh + (size_t)z * OUT_ELEMS;
        dl = g_inl + (size_t)z * OUT_ELEMS;
        n4 = OUT_ELEMS / 4;
    } else {
        src = (z == 3) ? wq : (z == 4) ? wk : (z == 5) ? wv : wo;
        dh = g_wh + (size_t)(z - 3) * W_ELEMS;
        dl = g_wl + (size_t)(z - 3) * W_ELEMS;
        n4 = W_ELEMS / 4;
    }
    int i = blockIdx.x * 256 + threadIdx.x;
    if (i >= n4) return;
    float4 x = ((const float4*)src)[i];
    float hx = __bfloat162float(__float2bfloat16_rn(x.x));
    float hy = __bfloat162float(__float2bfloat16_rn(x.y));
    float hz = __bfloat162float(__float2bfloat16_rn(x.z));
    float hw = __bfloat162float(__float2bfloat16_rn(x.w));
    uint2 oh = make_uint2(pack_hi(x.x, x.y), pack_hi(x.z, x.w));
    uint2 ol = make_uint2(pack_hi(x.x - hx, x.y - hy), pack_hi(x.z - hz, x.w - hw));
    *(uint2*)&dh[(size_t)i * 4] = oh;
    *(uint2*)&dl[(size_t)i * 4] = ol;
}

// ==================== shared GEMM body (3-stage cp.async) =================
#define A_LD 40
#define B_LD 136
#define OFF_AH 0
#define OFF_AL (128 * A_LD)
#define OFF_BH (2 * 128 * A_LD)
#define OFF_BL (2 * 128 * A_LD + 32 * B_LD)
#define BUF_ELEMS (2 * 128 * A_LD + 2 * 32 * B_LD)      // 18944 bf16
#define GEMM_SMEM (3 * BUF_ELEMS * 2)                   // 113664 bytes

__device__ __forceinline__ void gemm_body(
    const __nv_bfloat16* __restrict__ AH, const __nv_bfloat16* __restrict__ AL,
    const __nv_bfloat16* __restrict__ WH, const __nv_bfloat16* __restrict__ WL,
    const float* __restrict__ bias, __nv_bfloat16* OH, __nv_bfloat16* OL,
    int bm, int bn) {
    extern __shared__ __align__(16) __nv_bfloat16 gsm[];

    const int tid = threadIdx.x;
    const int lane = tid & 31;
    const int warp = tid >> 5;
    const int wm = (warp & 3) * 32;
    const int wn = (warp >> 2) * 64;
    const int lr = lane & 15;
    const int lh = lane >> 4;

    const uint32_t smem_base = (uint32_t)__cvta_generic_to_shared(gsm);

    float acc[2][8][4];
#pragma unroll
    for (int i = 0; i < 2; ++i)
#pragma unroll
        for (int j = 0; j < 8; ++j)
#pragma unroll
            for (int r = 0; r < 4; ++r) acc[i][j][r] = 0.f;

    const int ar0 = tid >> 2, ao0 = (tid & 3) * 8;
    const int ar1 = (tid + 256) >> 2, ao1 = ((tid + 256) & 3) * 8;
    const int br0 = tid >> 4, bo0 = (tid & 15) * 8;
    const int br1 = (tid + 256) >> 4, bo1 = ((tid + 256) & 15) * 8;

#define ISSUE(bufi, k0)                                                        \
    do {                                                                       \
        uint32_t sb = smem_base + (bufi) * (BUF_ELEMS * 2);                    \
        cp16(sb + (OFF_AH + ar0 * A_LD + ao0) * 2,                             \
             AH + (size_t)(bm + ar0) * DMODEL + (k0) + ao0);                   \
        cp16(sb + (OFF_AH + ar1 * A_LD + ao1) * 2,                             \
             AH + (size_t)(bm + ar1) * DMODEL + (k0) + ao1);                   \
        cp16(sb + (OFF_AL + ar0 * A_LD + ao0) * 2,                             \
             AL + (size_t)(bm + ar0) * DMODEL + (k0) + ao0);                   \
        cp16(sb + (OFF_AL + ar1 * A_LD + ao1) * 2,                             \
             AL + (size_t)(bm + ar1) * DMODEL + (k0) + ao1);                   \
        cp16(sb + (OFF_BH + br0 * B_LD + bo0) * 2,                             \
             WH + (size_t)((k0) + br0) * DMODEL + bn + bo0);                   \
        cp16(sb + (OFF_BH + br1 * B_LD + bo1) * 2,                             \
             WH + (size_t)((k0) + br1) * DMODEL + bn + bo1);                   \
        cp16(sb + (OFF_BL + br0 * B_LD + bo0) * 2,                             \
             WL + (size_t)((k0) + br0) * DMODEL + bn + bo0);                   \
        cp16(sb + (OFF_BL + br1 * B_LD + bo1) * 2,                             \
             WL + (size_t)((k0) + br1) * DMODEL + bn + bo1);                   \
    } while (0)

    ISSUE(0, 0);
    CP_COMMIT();
    ISSUE(1, 32);
    CP_COMMIT();

    for (int c = 0; c < DMODEL / 32; ++c) {
        CP_WAIT1();
        __syncthreads();
        const int buf = c % 3;
        const __nv_bfloat16* Ah = gsm + buf * BUF_ELEMS + OFF_AH;
        const __nv_bfloat16* Al = gsm + buf * BUF_ELEMS + OFF_AL;
        const __nv_bfloat16* Bh = gsm + buf * BUF_ELEMS + OFF_BH;
        const __nv_bfloat16* Bl = gsm + buf * BUF_ELEMS + OFF_BL;
#pragma unroll
        for (int ks = 0; ks < 2; ++ks) {
            uint32_t afh[2][4], afl[2][4];
#pragma unroll
            for (int mt = 0; mt < 2; ++mt) {
                ldsm_x4(afh[mt], (uint32_t)__cvta_generic_to_shared(
                    &Ah[(wm + mt * 16 + lr) * A_LD + ks * 16 + lh * 8]));
                ldsm_x4(afl[mt], (uint32_t)__cvta_generic_to_shared(
                    &Al[(wm + mt * 16 + lr) * A_LD + ks * 16 + lh * 8]));
            }
#pragma unroll
            for (int np = 0; np < 4; ++np) {
                uint32_t bfh[4], bfl[4];
                ldsm_x4_t(bfh, (uint32_t)__cvta_generic_to_shared(
                    &Bh[(ks * 16 + lr) * B_LD + wn + np * 16 + lh * 8]));
                ldsm_x4_t(bfl, (uint32_t)__cvta_generic_to_shared(
                    &Bl[(ks * 16 + lr) * B_LD + wn + np * 16 + lh * 8]));
#pragma unroll
                for (int mt = 0; mt < 2; ++mt) {
                    mma16816(acc[mt][2 * np],     afh[mt], bfh[0], bfh[1]);
                    mma16816(acc[mt][2 * np],     afh[mt], bfl[0], bfl[1]);
                    mma16816(acc[mt][2 * np],     afl[mt], bfh[0], bfh[1]);
                    mma16816(acc[mt][2 * np + 1], afh[mt], bfh[2], bfh[3]);
                    mma16816(acc[mt][2 * np + 1], afh[mt], bfl[2], bfl[3]);
                    mma16816(acc[mt][2 * np + 1], afl[mt], bfh[2], bfh[3]);
                }
            }
        }
        if (c + 2 < DMODEL / 32) {
            ISSUE((c + 2) % 3, (c + 2) * 32);
        }
        CP_COMMIT();
    }
#undef ISSUE

    const int gid = lane >> 2;
    const int qid = lane & 3;
#pragma unroll
    for (int mt = 0; mt < 2; ++mt) {
#pragma unroll
        for (int nt = 0; nt < 8; ++nt) {
            int col = bn + wn + nt * 8 + qid * 2;
            float bb0 = bias[col], bb1 = bias[col + 1];
            int r0 = bm + wm + mt * 16 + gid;
            float v00 = acc[mt][nt][0] + bb0, v01 = acc[mt][nt][1] + bb1;
            float v10 = acc[mt][nt][2] + bb0, v11 = acc[mt][nt][3] + bb1;
            if (OH) {
                size_t p0 = (size_t)r0 * DMODEL + col;
                size_t p1 = (size_t)(r0 + 8) * DMODEL + col;
                float h00 = __bfloat162float(__float2bfloat16_rn(v00));
                float h01 = __bfloat162float(__float2bfloat16_rn(v01));
                float h10 = __bfloat162float(__float2bfloat16_rn(v10));
                float h11 = __bfloat162float(__float2bfloat16_rn(v11));
                *(uint32_t*)&OH[p0] = pack_hi(v00, v01);
                *(uint32_t*)&OL[p0] = pack_hi(v00 - h00, v01 - h01);
                *(uint32_t*)&OH[p1] = pack_hi(v10, v11);
                *(uint32_t*)&OL[p1] = pack_hi(v10 - h10, v11 - h11);
            } else {
                *(float2*)&g_o[(size_t)r0 * DMODEL + col] = make_float2(v00, v01);
                *(float2*)&g_o[(size_t)(r0 + 8) * DMODEL + col] = make_float2(v10, v11);
            }
        }
    }
}

__global__ __launch_bounds__(256, 2)
void gemm_qkv(const float* __restrict__ b0p, const float* __restrict__ b1p,
              const float* __restrict__ b2p) {
    const int z = blockIdx.z;
    const __nv_bfloat16* AH = g_inh + (size_t)z * OUT_ELEMS;
    const __nv_bfloat16* AL = g_inl + (size_t)z * OUT_ELEMS;
    const __nv_bfloat16* WH = g_wh + (size_t)z * W_ELEMS;
    const __nv_bfloat16* WL = g_wl + (size_t)z * W_ELEMS;
    const float* bias = (z == 0) ? b0p : (z == 1) ? b1p : b2p;
    __nv_bfloat16* OH = (z == 0) ? g_qh : (z == 1) ? g_kh : g_vh;
    __nv_bfloat16* OL = (z == 0) ? g_ql : (z == 1) ? g_kl : g_vl;
    gemm_body(AH, AL, WH, WL, bias, OH, OL,
              blockIdx.y * 128, blockIdx.x * 128);
}

__global__ __launch_bounds__(256, 2)
void gemm_wo(const float* __restrict__ bo) {
    gemm_body(g_ctxh, g_ctxl, g_wh + (size_t)3 * W_ELEMS,
              g_wl + (size_t)3 * W_ELEMS, bo, nullptr, nullptr,
              blockIdx.y * 128, blockIdx.x * 128);
}

// ==================== tensor-core attention v4.1 ==========================
// cp.async K/V pipeline + per-block tail rescale; truncation split for P.
#define ALD 72
#define TILE_B (64 * ALD * 2)                 // 9216 bytes
#define KV_OFF (2 * TILE_B)
#define TCA_SMEM (10 * TILE_B + 576)

__global__ __launch_bounds__(256, 2)
void attn_tc(float* __restrict__ gattn) {
    extern __shared__ __align__(16) char dsm[];
    __nv_bfloat16* Qh = (__nv_bfloat16*)dsm;
    __nv_bfloat16* Ql = (__nv_bfloat16*)(dsm + TILE_B);
    float* sPart = (float*)(dsm + 10 * TILE_B);
    float* red = (float*)(dsm + KV_OFF);      // aliases KV buf0 (post-loop)

    const int tid = threadIdx.x;
    const int lane = tid & 31;
    const int warp = tid >> 5;
    const int wy = warp & 3;
    const int wx = warp >> 2;
    const int lr = lane & 15;
    const int lh = lane >> 4;
    const int gid = lane >> 2;
    const int qid = lane & 3;

    const int q0 = blockIdx.x * 64;
    const int h = blockIdx.y;
    const int b = blockIdx.z;
    const size_t head_off = (size_t)b * SEQ * DMODEL + h * DHEAD;

    const uint32_t smem_base = (uint32_t)__cvta_generic_to_shared(dsm);

    const int r0c = tid >> 3, o0c = (tid & 7) * 8;
    const int r1c = 32 + (tid >> 3), o1c = (tid & 7) * 8;

#define KV_ISSUE(bufi, kc)                                                     \
    do {                                                                       \
        uint32_t sb = smem_base + KV_OFF + (bufi) * (4 * TILE_B);              \
        const size_t s0 = head_off + (size_t)((kc) + r0c) * DMODEL;            \
        const size_t s1 = head_off + (size_t)((kc) + r1c) * DMODEL;            \
        cp16(sb + 0 * TILE_B + (r0c * ALD + o0c) * 2, g_kh + s0 + o0c);        \
        cp16(sb + 0 * TILE_B + (r1c * ALD + o1c) * 2, g_kh + s1 + o1c);        \
        cp16(sb + 1 * TILE_B + (r0c * ALD + o0c) * 2, g_kl + s0 + o0c);        \
        cp16(sb + 1 * TILE_B + (r1c * ALD + o1c) * 2, g_kl + s1 + o1c);        \
        cp16(sb + 2 * TILE_B + (r0c * ALD + o0c) * 2, g_vh + s0 + o0c);        \
        cp16(sb + 2 * TILE_B + (r1c * ALD + o1c) * 2, g_vh + s1 + o1c);        \
        cp16(sb + 3 * TILE_B + (r0c * ALD + o0c) * 2, g_vl + s0 + o0c);        \
        cp16(sb + 3 * TILE_B + (r1c * ALD + o1c) * 2, g_vl + s1 + o1c);        \
    } while (0)

    {
        const int row = tid >> 2;
        const int cg = (tid & 3) * 16;
        const size_t src = head_off + (size_t)(q0 + row) * DMODEL + cg;
        *(uint4*)&Qh[row * ALD + cg]     = *(const uint4*)&g_qh[src];
        *(uint4*)&Qh[row * ALD + cg + 8] = *(const uint4*)&g_qh[src + 8];
        *(uint4*)&Ql[row * ALD + cg]     = *(const uint4*)&g_ql[src];
        *(uint4*)&Ql[row * ALD + cg + 8] = *(const uint4*)&g_ql[src + 8];
    }

    KV_ISSUE(0, 0);
    CP_COMMIT();
    KV_ISSUE(1, 64);
    CP_COMMIT();
    CP_WAIT1();
    __syncthreads();

    float ctx[8][4];
#pragma unroll
    for (int j = 0; j < 8; ++j)
#pragma unroll
        for (int r = 0; r < 4; ++r) ctx[j][r] = 0.f;
    float psum0 = 0.f, psum1 = 0.f;

    const int row0 = wy * 16 + gid;
    const size_t arow0 = (size_t)((b * NHEAD + h) * SEQ + q0 + row0);

    for (int c = 0; c < SEQ / 64; ++c) {
        const int buf = c & 1;
        const int kc = c * 64;
        __nv_bfloat16* Kh = (__nv_bfloat16*)(dsm + KV_OFF + buf * 4 * TILE_B);
        __nv_bfloat16* Kl = Kh + 64 * ALD;
        __nv_bfloat16* Vh = Kl + 64 * ALD;
        __nv_bfloat16* Vl = Vh + 64 * ALD;

        float s[4][4];
#pragma unroll
        for (int j = 0; j < 4; ++j)
#pragma unroll
            for (int r = 0; r < 4; ++r) s[j][r] = 0.f;

#pragma unroll
        for (int ks = 0; ks < 4; ++ks) {
            uint32_t aQh[4], aQl[4];
            ldsm_x4(aQh, (uint32_t)__cvta_generic_to_shared(
                &Qh[(wy * 16 + lr) * ALD + ks * 16 + lh * 8]));
            ldsm_x4(aQl, (uint32_t)__cvta_generic_to_shared(
                &Ql[(wy * 16 + lr) * ALD + ks * 16 + lh * 8]));
            uint32_t bKh[2][4], bKl[2][4];
            const int mat = lane >> 3, rr = lane & 7;
            const int keyo = (mat >> 1) * 8 + rr;
            const int dof = (mat & 1) * 8 + ks * 16;
#pragma unroll
            for (int g = 0; g < 2; ++g) {
                int key = wx * 32 + g * 16 + keyo;
                ldsm_x4(bKh[g], (uint32_t)__cvta_generic_to_shared(
                    &Kh[key * ALD + dof]));
                ldsm_x4(bKl[g], (uint32_t)__cvta_generic_to_shared(
                    &Kl[key * ALD + dof]));
            }
#pragma unroll
            for (int j = 0; j < 4; ++j) {
                const int g = j >> 1, p = (j & 1) * 2;
                mma16816(s[j], aQh, bKh[g][p], bKh[g][p + 1]);
                mma16816(s[j], aQh, bKl[g][p], bKl[g][p + 1]);
                mma16816(s[j], aQl, bKh[g][p], bKh[g][p + 1]);
            }
        }

        uint32_t aPh[2][4], aPl[2][4];
#pragma unroll
        for (int j = 0; j < 4; ++j) {
            float e0 = __expf(s[j][0] * 0.125f);
            float e1 = __expf(s[j][1] * 0.125f);
            float e2 = __expf(s[j][2] * 0.125f);
            float e3 = __expf(s[j][3] * 0.125f);
            psum0 += e0 + e1;
            psum1 += e2 + e3;
            const int col = wx * 32 + j * 8 + qid * 2;
            if (gattn) {
                __stcs((float2*)&gattn[arow0 * SEQ + kc + col], make_float2(e0, e1));
                __stcs((float2*)&gattn[(arow0 + 8) * SEQ + kc + col], make_float2(e2, e3));
            }
            // truncation split: hi = upper 16 bits, lo = exact remainder
            const int t = j >> 1, half = j & 1;
            aPh[t][half * 2 + 0] = pack_trunc(e0, e1);
            aPh[t][half * 2 + 1] = pack_trunc(e2, e3);
            aPl[t][half * 2 + 0] = pack_hi(e0 - trunc_hi(e0), e1 - trunc_hi(e1));
            aPl[t][half * 2 + 1] = pack_hi(e2 - trunc_hi(e2), e3 - trunc_hi(e3));
        }

#pragma unroll
        for (int t = 0; t < 2; ++t) {
            const int kb = wx * 32 + t * 16;
#pragma unroll
            for (int np = 0; np < 4; ++np) {
                uint32_t bVh[4], bVl[4];
                ldsm_x4_t(bVh, (uint32_t)__cvta_generic_to_shared(
                    &Vh[(kb + lr) * ALD + np * 16 + lh * 8]));
                ldsm_x4_t(bVl, (uint32_t)__cvta_generic_to_shared(
                    &Vl[(kb + lr) * ALD + np * 16 + lh * 8]));
                mma16816(ctx[2 * np],     aPh[t], bVh[0], bVh[1]);
                mma16816(ctx[2 * np],     aPh[t], bVl[0], bVl[1]);
                mma16816(ctx[2 * np],     aPl[t], bVh[0], bVh[1]);
                mma16816(ctx[2 * np + 1], aPh[t], bVh[2], bVh[3]);
                mma16816(ctx[2 * np + 1], aPh[t], bVl[2], bVl[3]);
                mma16816(ctx[2 * np + 1], aPl[t], bVh[2], bVh[3]);
            }
        }

        __syncthreads();
        if (c + 2 < SEQ / 64) {
            KV_ISSUE(buf, (c + 2) * 64);
        }
        CP_COMMIT();
        CP_WAIT1();
        __syncthreads();
    }
#undef KV_ISSUE

    // ---- rowsum + cross-wx ctx reduction (red aliases KV buf0) ----------
    psum0 += __shfl_xor_sync(0xffffffffu, psum0, 1);
    psum0 += __shfl_xor_sync(0xffffffffu, psum0, 2);
    psum1 += __shfl_xor_sync(0xffffffffu, psum1, 1);
    psum1 += __shfl_xor_sync(0xffffffffu, psum1, 2);
    if (qid == 0) {
        sPart[wx * 64 + row0] = psum0;
        sPart[wx * 64 + row0 + 8] = psum1;
    }
    if (wx == 1) {
#pragma unroll
        for (int j = 0; j < 8; ++j) {
            *(float2*)&red[row0 * 68 + j * 8 + qid * 2] =
                make_float2(ctx[j][0], ctx[j][1]);
            *(float2*)&red[(row0 + 8) * 68 + j * 8 + qid * 2] =
                make_float2(ctx[j][2], ctx[j][3]);
        }
    }
    __syncthreads();
    if (wx == 0) {
        float tot0 = sPart[row0] + sPart[64 + row0];
        float tot1 = sPart[row0 + 8] + sPart[64 + row0 + 8];
        if (qid == 0) {
            g_rowsum[arow0] = tot0;
            g_rowsum[arow0 + 8] = tot1;
        }
        float inv0 = 1.0f / tot0, inv1 = 1.0f / tot1;
#pragma unroll
        for (int j = 0; j < 8; ++j) {
            const int col = j * 8 + qid * 2;
            float2 o0 = *(float2*)&red[row0 * 68 + col];
            float2 o1 = *(float2*)&red[(row0 + 8) * 68 + col];
            o0.x = (ctx[j][0] + o0.x) * inv0;
            o0.y = (ctx[j][1] + o0.y) * inv0;
            o1.x = (ctx[j][2] + o1.x) * inv1;
            o1.y = (ctx[j][3] + o1.y) * inv1;
            size_t p0 = (size_t)(b * SEQ + q0 + row0) * DMODEL + h * DHEAD + col;
            size_t p1 = (size_t)(b * SEQ + q0 + row0 + 8) * DMODEL + h * DHEAD + col;
            float h0x = __bfloat162float(__float2bfloat16_rn(o0.x));
            float h0y = __bfloat162float(__float2bfloat16_rn(o0.y));
            float h1x = __bfloat162float(__float2bfloat16_rn(o1.x));
            float h1y = __bfloat162float(__float2bfloat16_rn(o1.y));
            *(uint32_t*)&g_ctxh[p0] = pack_hi(o0.x, o0.y);
            *(uint32_t*)&g_ctxl[p0] = pack_hi(o0.x - h0x, o0.y - h0y);
            *(uint32_t*)&g_ctxh[p1] = pack_hi(o1.x, o1.y);
            *(uint32_t*)&g_ctxl[p1] = pack_hi(o1.x - h1x, o1.y - h1y);
        }
    }

    // ---- tail: rescale this block's own 64 attn rows ---------------------
    if (gattn) {
        __syncthreads();
        float4* p = (float4*)gattn;
        const size_t rowbase = (size_t)((b * NHEAD + h) * SEQ + q0);
#pragma unroll 1
        for (int r = 0; r < 64; r += 2) {
            float inv0 = 1.0f / (sPart[r] + sPart[64 + r]);
            float inv1 = 1.0f / (sPart[r + 1] + sPart[64 + r + 1]);
            size_t b0 = (rowbase + r) * (SEQ / 4);
            size_t b1 = b0 + (SEQ / 4);
            float4 v0 = __ldcs(&p[b0 + tid]);
            float4 v1 = __ldcs(&p[b0 + 256 + tid]);
            float4 v2 = __ldcs(&p[b1 + tid]);
            float4 v3 = __ldcs(&p[b1 + 256 + tid]);
            v0.x *= inv0; v0.y *= inv0; v0.z *= inv0; v0.w *= inv0;
            v1.x *= inv0; v1.y *= inv0; v1.z *= inv0; v1.w *= inv0;
            v2.x *= inv1; v2.y *= inv1; v2.z *= inv1; v2.w *= inv1;
            v3.x *= inv1; v3.y *= inv1; v3.z *= inv1; v3.w *= inv1;
            __stcs(&p[b0 + tid], v0);
            __stcs(&p[b0 + 256 + tid], v1);
            __stcs(&p[b1 + tid], v2);
            __stcs(&p[b1 + 256 + tid], v3);
        }
    }
}

// -------------------- LayerNorm ------------------------------------------
__global__ __launch_bounds__(256)
void ln_kernel(const float* __restrict__ gamma, const float* __restrict__ beta,
               float* __restrict__ out) {
    const int row = blockIdx.x;
    const int tid = threadIdx.x;
    __shared__ float red[8];

    float4 x = *(const float4*)&g_o[(size_t)row * DMODEL + tid * 4];
    float s = (x.x + x.y) + (x.z + x.w);
#pragma unroll
    for (int off = 16; off; off >>= 1) s += __shfl_xor_sync(0xffffffffu, s, off);
    if ((tid & 31) == 0) red[tid >> 5] = s;
    __syncthreads();
    float tot = 0.f;
#pragma unroll
    for (int i = 0; i < 8; ++i) tot += red[i];
    float mean = tot * (1.0f / 1024.0f);
    __syncthreads();

    float4 dx = make_float4(x.x - mean, x.y - mean, x.z - mean, x.w - mean);
    float ss = dx.x * dx.x + dx.y * dx.y + dx.z * dx.z + dx.w * dx.w;
#pragma unroll
    for (int off = 16; off; off >>= 1) ss += __shfl_xor_sync(0xffffffffu, ss, off);
    if ((tid & 31) == 0) red[tid >> 5] = ss;
    __syncthreads();
    float tss = 0.f;
#pragma unroll
    for (int i = 0; i < 8; ++i) tss += red[i];
    float var = tss * (1.0f / 1024.0f);
    float rstd = rsqrtf(var + 1e-3f);

    float4 g = *(const float4*)&gamma[tid * 4];
    float4 be = *(const float4*)&beta[tid * 4];
    float4 o;
    o.x = dx.x * rstd * g.x + be.x;
    o.y = dx.y * rstd * g.y + be.y;
    o.z = dx.z * rstd * g.z + be.z;
    o.w = dx.w * rstd * g.w + be.w;
    *(float4*)&out[(size_t)row * DMODEL + tid * 4] = o;
}

// -------------------- launcher --------------------------------------------
extern "C" void kernel_launch(void* const* d_in, const int* in_sizes, int n_in,
                              void* d_out, int out_size) {
    const float* query = (const float*)d_in[0];
    const float* key   = (const float*)d_in[1];
    const float* value = (const float*)d_in[2];
    const float* Wq = (const float*)d_in[3];
    const float* bq = (const float*)d_in[4];
    const float* Wk = (const float*)d_in[5];
    const float* bk = (const float*)d_in[6];
    const float* Wv = (const float*)d_in[7];
    const float* bv = (const float*)d_in[8];
    const float* Wo = (const float*)d_in[9];
    const float* bo = (const float*)d_in[10];
    const float* gamma = (const float*)d_in[11];
    const float* beta  = (const float*)d_in[12];

    float* out = (float*)d_out;
    float* attn = (out_size >= OUT_ELEMS + ATTN_ELEMS) ? (out + OUT_ELEMS) : nullptr;

    cudaFuncSetAttribute(attn_tc, cudaFuncAttributeMaxDynamicSharedMemorySize,
                         TCA_SMEM);
    cudaFuncSetAttribute(gemm_qkv, cudaFuncAttributeMaxDynamicSharedMemorySize,
                         GEMM_SMEM);
    cudaFuncSetAttribute(gemm_wo, cudaFuncAttributeMaxDynamicSharedMemorySize,
                         GEMM_SMEM);

    convert_split<<<dim3(OUT_ELEMS / 4 / 256, 1, 7), 256>>>(query, key, value,
                                                            Wq, Wk, Wv, Wo);

    gemm_qkv<<<dim3(DMODEL / 128, NROWS / 128, 3), 256, GEMM_SMEM>>>(bq, bk, bv);

    attn_tc<<<dim3(SEQ / 64, NHEAD, BATCH), 256, TCA_SMEM>>>(attn);

    gemm_wo<<<dim3(DMODEL / 128, NROWS / 128), 256, GEMM_SMEM>>>(bo);

    ln_kernel<<<NROWS, 256>>>(gamma, beta, out);
}

// round 16
// speedup vs baseline: 1.8950x; 1.0605x over previous
#include <cuda_runtime.h>
#include <cuda_bf16.h>
#include <math.h>
#include <stdint.h>

// Problem constants
#define SEQ   2048
#define BATCH 2
#define DMODEL 1024
#define NHEAD 16
#define DHEAD 64
#define NROWS (BATCH * SEQ)          // 4096
#define OUT_ELEMS   (NROWS * DMODEL)             // 4,194,304
#define W_ELEMS (DMODEL * DMODEL)                // 1,048,576
#define ATTN_ELEMS  (BATCH * NHEAD * SEQ * SEQ)  // 134,217,728

// -------------------- device scratch (no allocations allowed) ------------
__device__ float g_o[NROWS * DMODEL];
__device__ float g_rowsum[BATCH * NHEAD * SEQ];
__device__ __nv_bfloat16 g_inh[3 * OUT_ELEMS];
__device__ __nv_bfloat16 g_inl[3 * OUT_ELEMS];
__device__ __nv_bfloat16 g_wh[4 * W_ELEMS];
__device__ __nv_bfloat16 g_wl[4 * W_ELEMS];
__device__ __nv_bfloat16 g_qh[OUT_ELEMS], g_ql[OUT_ELEMS];
__device__ __nv_bfloat16 g_kh[OUT_ELEMS], g_kl[OUT_ELEMS];
__device__ __nv_bfloat16 g_vh[OUT_ELEMS], g_vl[OUT_ELEMS];
__device__ __nv_bfloat16 g_ctxh[OUT_ELEMS], g_ctxl[OUT_ELEMS];

// ==================== helpers ============================================
__device__ __forceinline__ void ldsm_x4(uint32_t (&r)[4], uint32_t addr) {
    asm volatile("ldmatrix.sync.aligned.m8n8.x4.shared.b16 {%0,%1,%2,%3}, [%4];"
                 : "=r"(r[0]), "=r"(r[1]), "=r"(r[2]), "=r"(r[3]) : "r"(addr));
}
__device__ __forceinline__ void ldsm_x4_t(uint32_t (&r)[4], uint32_t addr) {
    asm volatile("ldmatrix.sync.aligned.m8n8.x4.trans.shared.b16 {%0,%1,%2,%3}, [%4];"
                 : "=r"(r[0]), "=r"(r[1]), "=r"(r[2]), "=r"(r[3]) : "r"(addr));
}
__device__ __forceinline__ void mma16816(float (&c)[4], const uint32_t (&a)[4],
                                         uint32_t b0, uint32_t b1) {
    asm volatile(
        "mma.sync.aligned.m16n8k16.row.col.f32.bf16.bf16.f32 "
        "{%0,%1,%2,%3}, {%4,%5,%6,%7}, {%8,%9}, {%0,%1,%2,%3};"
        : "+f"(c[0]), "+f"(c[1]), "+f"(c[2]), "+f"(c[3])
        : "r"(a[0]), "r"(a[1]), "r"(a[2]), "r"(a[3]), "r"(b0), "r"(b1));
}
__device__ __forceinline__ uint32_t pack_hi(float x, float y) {
    __nv_bfloat162 h = __floats2bfloat162_rn(x, y);
    return *(uint32_t*)&h;
}
// truncation split: bf16x2 of high halves (1 PRMT)
__device__ __forceinline__ uint32_t pack_trunc(float x, float y) {
    return __byte_perm(__float_as_uint(x), __float_as_uint(y), 0x7632);
}
__device__ __forceinline__ float trunc_hi(float x) {
    return __uint_as_float(__float_as_uint(x) & 0xffff0000u);
}
__device__ __forceinline__ void cp16(uint32_t dst, const void* src) {
    asm volatile("cp.async.cg.shared.global [%0], [%1], 16;" :: "r"(dst), "l"(src));
}
#define CP_COMMIT() asm volatile("cp.async.commit_group;")
#define CP_WAIT1()  asm volatile("cp.async.wait_group 1;" ::: "memory")

// ==================== split-bf16 conversion pass ==========================
__global__ __launch_bounds__(256)
void convert_split(const float* __restrict__ q, const float* __restrict__ k,
                   const float* __restrict__ v, const float* __restrict__ wq,
                   const float* __restrict__ wk, const float* __restrict__ wv,
                   const float* __restrict__ wo) {
    const int z = blockIdx.z;
    const float* src;
    __nv_bfloat16 *dh, *dl;
    int n4;
    if (z < 3) {
        src = (z == 0) ? q : (z == 1) ? k : v;
        dh = g_inh + (size_t)z * OUT_ELEMS;
        dl = g_inl + (size_t)z * OUT_ELEMS;
        n4 = OUT_ELEMS / 4;
    } else {
        src = (z == 3) ? wq : (z == 4) ? wk : (z == 5) ? wv : wo;
        dh = g_wh + (size_t)(z - 3) * W_ELEMS;
        dl = g_wl + (size_t)(z - 3) * W_ELEMS;
        n4 = W_ELEMS / 4;
    }
    int i = blockIdx.x * 256 + threadIdx.x;
    if (i >= n4) return;
    float4 x = ((const float4*)src)[i];
    float hx = __bfloat162float(__float2bfloat16_rn(x.x));
    float hy = __bfloat162float(__float2bfloat16_rn(x.y));
    float hz = __bfloat162float(__float2bfloat16_rn(x.z));
    float hw = __bfloat162float(__float2bfloat16_rn(x.w));
    uint2 oh = make_uint2(pack_hi(x.x, x.y), pack_hi(x.z, x.w));
    uint2 ol = make_uint2(pack_hi(x.x - hx, x.y - hy), pack_hi(x.z - hz, x.w - hw));
    *(uint2*)&dh[(size_t)i * 4] = oh;
    *(uint2*)&dl[(size_t)i * 4] = ol;
}

// ==================== shared GEMM body (3-stage cp.async) =================
#define A_LD 40
#define B_LD 136
#define OFF_AH 0
#define OFF_AL (128 * A_LD)
#define OFF_BH (2 * 128 * A_LD)
#define OFF_BL (2 * 128 * A_LD + 32 * B_LD)
#define BUF_ELEMS (2 * 128 * A_LD + 2 * 32 * B_LD)      // 18944 bf16
#define GEMM_SMEM (3 * BUF_ELEMS * 2)                   // 113664 bytes

__device__ __forceinline__ void gemm_body(
    const __nv_bfloat16* __restrict__ AH, const __nv_bfloat16* __restrict__ AL,
    const __nv_bfloat16* __restrict__ WH, const __nv_bfloat16* __restrict__ WL,
    const float* __restrict__ bias, __nv_bfloat16* OH, __nv_bfloat16* OL,
    int bm, int bn) {
    extern __shared__ __align__(16) __nv_bfloat16 gsm[];

    const int tid = threadIdx.x;
    const int lane = tid & 31;
    const int warp = tid >> 5;
    const int wm = (warp & 3) * 32;
    const int wn = (warp >> 2) * 64;
    const int lr = lane & 15;
    const int lh = lane >> 4;

    const uint32_t smem_base = (uint32_t)__cvta_generic_to_shared(gsm);

    float acc[2][8][4];
#pragma unroll
    for (int i = 0; i < 2; ++i)
#pragma unroll
        for (int j = 0; j < 8; ++j)
#pragma unroll
            for (int r = 0; r < 4; ++r) acc[i][j][r] = 0.f;

    const int ar0 = tid >> 2, ao0 = (tid & 3) * 8;
    const int ar1 = (tid + 256) >> 2, ao1 = ((tid + 256) & 3) * 8;
    const int br0 = tid >> 4, bo0 = (tid & 15) * 8;
    const int br1 = (tid + 256) >> 4, bo1 = ((tid + 256) & 15) * 8;

#define ISSUE(bufi, k0)                                                        \
    do {                                                                       \
        uint32_t sb = smem_base + (bufi) * (BUF_ELEMS * 2);                    \
        cp16(sb + (OFF_AH + ar0 * A_LD + ao0) * 2,                             \
             AH + (size_t)(bm + ar0) * DMODEL + (k0) + ao0);                   \
        cp16(sb + (OFF_AH + ar1 * A_LD + ao1) * 2,                             \
             AH + (size_t)(bm + ar1) * DMODEL + (k0) + ao1);                   \
        cp16(sb + (OFF_AL + ar0 * A_LD + ao0) * 2,                             \
             AL + (size_t)(bm + ar0) * DMODEL + (k0) + ao0);                   \
        cp16(sb + (OFF_AL + ar1 * A_LD + ao1) * 2,                             \
             AL + (size_t)(bm + ar1) * DMODEL + (k0) + ao1);                   \
        cp16(sb + (OFF_BH + br0 * B_LD + bo0) * 2,                             \
             WH + (size_t)((k0) + br0) * DMODEL + bn + bo0);                   \
        cp16(sb + (OFF_BH + br1 * B_LD + bo1) * 2,                             \
             WH + (size_t)((k0) + br1) * DMODEL + bn + bo1);                   \
        cp16(sb + (OFF_BL + br0 * B_LD + bo0) * 2,                             \
             WL + (size_t)((k0) + br0) * DMODEL + bn + bo0);                   \
        cp16(sb + (OFF_BL + br1 * B_LD + bo1) * 2,                             \
             WL + (size_t)((k0) + br1) * DMODEL + bn + bo1);                   \
    } while (0)

    ISSUE(0, 0);
    CP_COMMIT();
    ISSUE(1, 32);
    CP_COMMIT();

    for (int c = 0; c < DMODEL / 32; ++c) {
        CP_WAIT1();
        __syncthreads();
        const int buf = c % 3;
        const __nv_bfloat16* Ah = gsm + buf * BUF_ELEMS + OFF_AH;
        const __nv_bfloat16* Al = gsm + buf * BUF_ELEMS + OFF_AL;
        const __nv_bfloat16* Bh = gsm + buf * BUF_ELEMS + OFF_BH;
        const __nv_bfloat16* Bl = gsm + buf * BUF_ELEMS + OFF_BL;
#pragma unroll
        for (int ks = 0; ks < 2; ++ks) {
            uint32_t afh[2][4], afl[2][4];
#pragma unroll
            for (int mt = 0; mt < 2; ++mt) {
                ldsm_x4(afh[mt], (uint32_t)__cvta_generic_to_shared(
                    &Ah[(wm + mt * 16 + lr) * A_LD + ks * 16 + lh * 8]));
                ldsm_x4(afl[mt], (uint32_t)__cvta_generic_to_shared(
                    &Al[(wm + mt * 16 + lr) * A_LD + ks * 16 + lh * 8]));
            }
#pragma unroll
            for (int np = 0; np < 4; ++np) {
                uint32_t bfh[4], bfl[4];
                ldsm_x4_t(bfh, (uint32_t)__cvta_generic_to_shared(
                    &Bh[(ks * 16 + lr) * B_LD + wn + np * 16 + lh * 8]));
                ldsm_x4_t(bfl, (uint32_t)__cvta_generic_to_shared(
                    &Bl[(ks * 16 + lr) * B_LD + wn + np * 16 + lh * 8]));
#pragma unroll
                for (int mt = 0; mt < 2; ++mt) {
                    mma16816(acc[mt][2 * np],     afh[mt], bfh[0], bfh[1]);
                    mma16816(acc[mt][2 * np],     afh[mt], bfl[0], bfl[1]);
                    mma16816(acc[mt][2 * np],     afl[mt], bfh[0], bfh[1]);
                    mma16816(acc[mt][2 * np + 1], afh[mt], bfh[2], bfh[3]);
                    mma16816(acc[mt][2 * np + 1], afh[mt], bfl[2], bfl[3]);
                    mma16816(acc[mt][2 * np + 1], afl[mt], bfh[2], bfh[3]);
                }
            }
        }
        if (c + 2 < DMODEL / 32) {
            ISSUE((c + 2) % 3, (c + 2) * 32);
        }
        CP_COMMIT();
    }
#undef ISSUE

    const int gid = lane >> 2;
    const int qid = lane & 3;
#pragma unroll
    for (int mt = 0; mt < 2; ++mt) {
#pragma unroll
        for (int nt = 0; nt < 8; ++nt) {
            int col = bn + wn + nt * 8 + qid * 2;
            float bb0 = bias[col], bb1 = bias[col + 1];
            int r0 = bm + wm + mt * 16 + gid;
            float v00 = acc[mt][nt][0] + bb0, v01 = acc[mt][nt][1] + bb1;
            float v10 = acc[mt][nt][2] + bb0, v11 = acc[mt][nt][3] + bb1;
            if (OH) {
                size_t p0 = (size_t)r0 * DMODEL + col;
                size_t p1 = (size_t)(r0 + 8) * DMODEL + col;
                float h00 = __bfloat162float(__float2bfloat16_rn(v00));
                float h01 = __bfloat162float(__float2bfloat16_rn(v01));
                float h10 = __bfloat162float(__float2bfloat16_rn(v10));
                float h11 = __bfloat162float(__float2bfloat16_rn(v11));
                *(uint32_t*)&OH[p0] = pack_hi(v00, v01);
                *(uint32_t*)&OL[p0] = pack_hi(v00 - h00, v01 - h01);
                *(uint32_t*)&OH[p1] = pack_hi(v10, v11);
                *(uint32_t*)&OL[p1] = pack_hi(v10 - h10, v11 - h11);
            } else {
                *(float2*)&g_o[(size_t)r0 * DMODEL + col] = make_float2(v00, v01);
                *(float2*)&g_o[(size_t)(r0 + 8) * DMODEL + col] = make_float2(v10, v11);
            }
        }
    }
}

__global__ __launch_bounds__(256, 2)
void gemm_qkv(const float* __restrict__ b0p, const float* __restrict__ b1p,
              const float* __restrict__ b2p) {
    const int z = blockIdx.z;
    const __nv_bfloat16* AH = g_inh + (size_t)z * OUT_ELEMS;
    const __nv_bfloat16* AL = g_inl + (size_t)z * OUT_ELEMS;
    const __nv_bfloat16* WH = g_wh + (size_t)z * W_ELEMS;
    const __nv_bfloat16* WL = g_wl + (size_t)z * W_ELEMS;
    const float* bias = (z == 0) ? b0p : (z == 1) ? b1p : b2p;
    __nv_bfloat16* OH = (z == 0) ? g_qh : (z == 1) ? g_kh : g_vh;
    __nv_bfloat16* OL = (z == 0) ? g_ql : (z == 1) ? g_kl : g_vl;
    gemm_body(AH, AL, WH, WL, bias, OH, OL,
              blockIdx.y * 128, blockIdx.x * 128);
}

__global__ __launch_bounds__(256, 2)
void gemm_wo(const float* __restrict__ bo) {
    gemm_body(g_ctxh, g_ctxl, g_wh + (size_t)3 * W_ELEMS,
              g_wl + (size_t)3 * W_ELEMS, bo, nullptr, nullptr,
              blockIdx.y * 128, blockIdx.x * 128);
}

// ==================== tensor-core attention v4.2 ==========================
// cp.async K/V pipeline + per-block tail rescale; truncation split for P.
// attn intermediate kept L2-resident (plain st/ld); only final write streams.
#define ALD 72
#define TILE_B (64 * ALD * 2)                 // 9216 bytes
#define KV_OFF (2 * TILE_B)
#define TCA_SMEM (10 * TILE_B + 576)

__global__ __launch_bounds__(256, 2)
void attn_tc(float* __restrict__ gattn) {
    extern __shared__ __align__(16) char dsm[];
    __nv_bfloat16* Qh = (__nv_bfloat16*)dsm;
    __nv_bfloat16* Ql = (__nv_bfloat16*)(dsm + TILE_B);
    float* sPart = (float*)(dsm + 10 * TILE_B);
    float* red = (float*)(dsm + KV_OFF);      // aliases KV buf0 (post-loop)

    const int tid = threadIdx.x;
    const int lane = tid & 31;
    const int warp = tid >> 5;
    const int wy = warp & 3;
    const int wx = warp >> 2;
    const int lr = lane & 15;
    const int lh = lane >> 4;
    const int gid = lane >> 2;
    const int qid = lane & 3;

    const int q0 = blockIdx.x * 64;
    const int h = blockIdx.y;
    const int b = blockIdx.z;
    const size_t head_off = (size_t)b * SEQ * DMODEL + h * DHEAD;

    const uint32_t smem_base = (uint32_t)__cvta_generic_to_shared(dsm);

    const int r0c = tid >> 3, o0c = (tid & 7) * 8;
    const int r1c = 32 + (tid >> 3), o1c = (tid & 7) * 8;

#define KV_ISSUE(bufi, kc)                                                     \
    do {                                                                       \
        uint32_t sb = smem_base + KV_OFF + (bufi) * (4 * TILE_B);              \
        const size_t s0 = head_off + (size_t)((kc) + r0c) * DMODEL;            \
        const size_t s1 = head_off + (size_t)((kc) + r1c) * DMODEL;            \
        cp16(sb + 0 * TILE_B + (r0c * ALD + o0c) * 2, g_kh + s0 + o0c);        \
        cp16(sb + 0 * TILE_B + (r1c * ALD + o1c) * 2, g_kh + s1 + o1c);        \
        cp16(sb + 1 * TILE_B + (r0c * ALD + o0c) * 2, g_kl + s0 + o0c);        \
        cp16(sb + 1 * TILE_B + (r1c * ALD + o1c) * 2, g_kl + s1 + o1c);        \
        cp16(sb + 2 * TILE_B + (r0c * ALD + o0c) * 2, g_vh + s0 + o0c);        \
        cp16(sb + 2 * TILE_B + (r1c * ALD + o1c) * 2, g_vh + s1 + o1c);        \
        cp16(sb + 3 * TILE_B + (r0c * ALD + o0c) * 2, g_vl + s0 + o0c);        \
        cp16(sb + 3 * TILE_B + (r1c * ALD + o1c) * 2, g_vl + s1 + o1c);        \
    } while (0)

    {
        const int row = tid >> 2;
        const int cg = (tid & 3) * 16;
        const size_t src = head_off + (size_t)(q0 + row) * DMODEL + cg;
        *(uint4*)&Qh[row * ALD + cg]     = *(const uint4*)&g_qh[src];
        *(uint4*)&Qh[row * ALD + cg + 8] = *(const uint4*)&g_qh[src + 8];
        *(uint4*)&Ql[row * ALD + cg]     = *(const uint4*)&g_ql[src];
        *(uint4*)&Ql[row * ALD + cg + 8] = *(const uint4*)&g_ql[src + 8];
    }

    KV_ISSUE(0, 0);
    CP_COMMIT();
    KV_ISSUE(1, 64);
    CP_COMMIT();
    CP_WAIT1();
    __syncthreads();

    float ctx[8][4];
#pragma unroll
    for (int j = 0; j < 8; ++j)
#pragma unroll
        for (int r = 0; r < 4; ++r) ctx[j][r] = 0.f;
    float psum0 = 0.f, psum1 = 0.f;

    const int row0 = wy * 16 + gid;
    const size_t arow0 = (size_t)((b * NHEAD + h) * SEQ + q0 + row0);

    for (int c = 0; c < SEQ / 64; ++c) {
        const int buf = c & 1;
        const int kc = c * 64;
        __nv_bfloat16* Kh = (__nv_bfloat16*)(dsm + KV_OFF + buf * 4 * TILE_B);
        __nv_bfloat16* Kl = Kh + 64 * ALD;
        __nv_bfloat16* Vh = Kl + 64 * ALD;
        __nv_bfloat16* Vl = Vh + 64 * ALD;

        float s[4][4];
#pragma unroll
        for (int j = 0; j < 4; ++j)
#pragma unroll
            for (int r = 0; r < 4; ++r) s[j][r] = 0.f;

#pragma unroll
        for (int ks = 0; ks < 4; ++ks) {
            uint32_t aQh[4], aQl[4];
            ldsm_x4(aQh, (uint32_t)__cvta_generic_to_shared(
                &Qh[(wy * 16 + lr) * ALD + ks * 16 + lh * 8]));
            ldsm_x4(aQl, (uint32_t)__cvta_generic_to_shared(
                &Ql[(wy * 16 + lr) * ALD + ks * 16 + lh * 8]));
            uint32_t bKh[2][4], bKl[2][4];
            const int mat = lane >> 3, rr = lane & 7;
            const int keyo = (mat >> 1) * 8 + rr;
            const int dof = (mat & 1) * 8 + ks * 16;
#pragma unroll
            for (int g = 0; g < 2; ++g) {
                int key = wx * 32 + g * 16 + keyo;
                ldsm_x4(bKh[g], (uint32_t)__cvta_generic_to_shared(
                    &Kh[key * ALD + dof]));
                ldsm_x4(bKl[g], (uint32_t)__cvta_generic_to_shared(
                    &Kl[key * ALD + dof]));
            }
#pragma unroll
            for (int j = 0; j < 4; ++j) {
                const int g = j >> 1, p = (j & 1) * 2;
                mma16816(s[j], aQh, bKh[g][p], bKh[g][p + 1]);
                mma16816(s[j], aQh, bKl[g][p], bKl[g][p + 1]);
                mma16816(s[j], aQl, bKh[g][p], bKh[g][p + 1]);
            }
        }

        uint32_t aPh[2][4], aPl[2][4];
#pragma unroll
        for (int j = 0; j < 4; ++j) {
            float e0 = __expf(s[j][0] * 0.125f);
            float e1 = __expf(s[j][1] * 0.125f);
            float e2 = __expf(s[j][2] * 0.125f);
            float e3 = __expf(s[j][3] * 0.125f);
            psum0 += e0 + e1;
            psum1 += e2 + e3;
            const int col = wx * 32 + j * 8 + qid * 2;
            if (gattn) {
                // plain stores: keep lines dirty in L2 for the tail re-read
                *(float2*)&gattn[arow0 * SEQ + kc + col] = make_float2(e0, e1);
                *(float2*)&gattn[(arow0 + 8) * SEQ + kc + col] = make_float2(e2, e3);
            }
            const int t = j >> 1, half = j & 1;
            aPh[t][half * 2 + 0] = pack_trunc(e0, e1);
            aPh[t][half * 2 + 1] = pack_trunc(e2, e3);
            aPl[t][half * 2 + 0] = pack_hi(e0 - trunc_hi(e0), e1 - trunc_hi(e1));
            aPl[t][half * 2 + 1] = pack_hi(e2 - trunc_hi(e2), e3 - trunc_hi(e3));
        }

#pragma unroll
        for (int t = 0; t < 2; ++t) {
            const int kb = wx * 32 + t * 16;
#pragma unroll
            for (int np = 0; np < 4; ++np) {
                uint32_t bVh[4], bVl[4];
                ldsm_x4_t(bVh, (uint32_t)__cvta_generic_to_shared(
                    &Vh[(kb + lr) * ALD + np * 16 + lh * 8]));
                ldsm_x4_t(bVl, (uint32_t)__cvta_generic_to_shared(
                    &Vl[(kb + lr) * ALD + np * 16 + lh * 8]));
                mma16816(ctx[2 * np],     aPh[t], bVh[0], bVh[1]);
                mma16816(ctx[2 * np],     aPh[t], bVl[0], bVl[1]);
                mma16816(ctx[2 * np],     aPl[t], bVh[0], bVh[1]);
                mma16816(ctx[2 * np + 1], aPh[t], bVh[2], bVh[3]);
                mma16816(ctx[2 * np + 1], aPh[t], bVl[2], bVl[3]);
                mma16816(ctx[2 * np + 1], aPl[t], bVh[2], bVh[3]);
            }
        }

        __syncthreads();
        if (c + 2 < SEQ / 64) {
            KV_ISSUE(buf, (c + 2) * 64);
        }
        CP_COMMIT();
        CP_WAIT1();
        __syncthreads();
    }
#undef KV_ISSUE

    // ---- rowsum + cross-wx ctx reduction (red aliases KV buf0) ----------
    psum0 += __shfl_xor_sync(0xffffffffu, psum0, 1);
    psum0 += __shfl_xor_sync(0xffffffffu, psum0, 2);
    psum1 += __shfl_xor_sync(0xffffffffu, psum1, 1);
    psum1 += __shfl_xor_sync(0xffffffffu, psum1, 2);
    if (qid == 0) {
        sPart[wx * 64 + row0] = psum0;
        sPart[wx * 64 + row0 + 8] = psum1;
    }
    if (wx == 1) {
#pragma unroll
        for (int j = 0; j < 8; ++j) {
            *(float2*)&red[row0 * 68 + j * 8 + qid * 2] =
                make_float2(ctx[j][0], ctx[j][1]);
            *(float2*)&red[(row0 + 8) * 68 + j * 8 + qid * 2] =
                make_float2(ctx[j][2], ctx[j][3]);
        }
    }
    __syncthreads();
    if (wx == 0) {
        float tot0 = sPart[row0] + sPart[64 + row0];
        float tot1 = sPart[row0 + 8] + sPart[64 + row0 + 8];
        if (qid == 0) {
            g_rowsum[arow0] = tot0;
            g_rowsum[arow0 + 8] = tot1;
        }
        float inv0 = 1.0f / tot0, inv1 = 1.0f / tot1;
#pragma unroll
        for (int j = 0; j < 8; ++j) {
            const int col = j * 8 + qid * 2;
            float2 o0 = *(float2*)&red[row0 * 68 + col];
            float2 o1 = *(float2*)&red[(row0 + 8) * 68 + col];
            o0.x = (ctx[j][0] + o0.x) * inv0;
            o0.y = (ctx[j][1] + o0.y) * inv0;
            o1.x = (ctx[j][2] + o1.x) * inv1;
            o1.y = (ctx[j][3] + o1.y) * inv1;
            size_t p0 = (size_t)(b * SEQ + q0 + row0) * DMODEL + h * DHEAD + col;
            size_t p1 = (size_t)(b * SEQ + q0 + row0 + 8) * DMODEL + h * DHEAD + col;
            float h0x = __bfloat162float(__float2bfloat16_rn(o0.x));
            float h0y = __bfloat162float(__float2bfloat16_rn(o0.y));
            float h1x = __bfloat162float(__float2bfloat16_rn(o1.x));
            float h1y = __bfloat162float(__float2bfloat16_rn(o1.y));
            *(uint32_t*)&g_ctxh[p0] = pack_hi(o0.x, o0.y);
            *(uint32_t*)&g_ctxl[p0] = pack_hi(o0.x - h0x, o0.y - h0y);
            *(uint32_t*)&g_ctxh[p1] = pack_hi(o1.x, o1.y);
            *(uint32_t*)&g_ctxl[p1] = pack_hi(o1.x - h1x, o1.y - h1y);
        }
    }

    // ---- tail: rescale this block's own 64 attn rows ---------------------
    // Reads should hit dirty L2 lines written by this block's main loop;
    // final stores stream out (terminal data).
    if (gattn) {
        __syncthreads();
        float4* p = (float4*)gattn;
        const size_t rowbase = (size_t)((b * NHEAD + h) * SEQ + q0);
#pragma unroll 1
        for (int r = 0; r < 64; r += 2) {
            float inv0 = 1.0f / (sPart[r] + sPart[64 + r]);
            float inv1 = 1.0f / (sPart[r + 1] + sPart[64 + r + 1]);
            size_t b0 = (rowbase + r) * (SEQ / 4);
            size_t b1 = b0 + (SEQ / 4);
            float4 v0 = p[b0 + tid];
            float4 v1 = p[b0 + 256 + tid];
            float4 v2 = p[b1 + tid];
            float4 v3 = p[b1 + 256 + tid];
            v0.x *= inv0; v0.y *= inv0; v0.z *= inv0; v0.w *= inv0;
            v1.x *= inv0; v1.y *= inv0; v1.z *= inv0; v1.w *= inv0;
            v2.x *= inv1; v2.y *= inv1; v2.z *= inv1; v2.w *= inv1;
            v3.x *= inv1; v3.y *= inv1; v3.z *= inv1; v3.w *= inv1;
            __stcs(&p[b0 + tid], v0);
            __stcs(&p[b0 + 256 + tid], v1);
            __stcs(&p[b1 + tid], v2);
            __stcs(&p[b1 + 256 + tid], v3);
        }
    }
}

// -------------------- LayerNorm ------------------------------------------
__global__ __launch_bounds__(256)
void ln_kernel(const float* __restrict__ gamma, const float* __restrict__ beta,
               float* __restrict__ out) {
    const int row = blockIdx.x;
    const int tid = threadIdx.x;
    __shared__ float red[8];

    float4 x = *(const float4*)&g_o[(size_t)row * DMODEL + tid * 4];
    float s = (x.x + x.y) + (x.z + x.w);
#pragma unroll
    for (int off = 16; off; off >>= 1) s += __shfl_xor_sync(0xffffffffu, s, off);
    if ((tid & 31) == 0) red[tid >> 5] = s;
    __syncthreads();
    float tot = 0.f;
#pragma unroll
    for (int i = 0; i < 8; ++i) tot += red[i];
    float mean = tot * (1.0f / 1024.0f);
    __syncthreads();

    float4 dx = make_float4(x.x - mean, x.y - mean, x.z - mean, x.w - mean);
    float ss = dx.x * dx.x + dx.y * dx.y + dx.z * dx.z + dx.w * dx.w;
#pragma unroll
    for (int off = 16; off; off >>= 1) ss += __shfl_xor_sync(0xffffffffu, ss, off);
    if ((tid & 31) == 0) red[tid >> 5] = ss;
    __syncthreads();
    float tss = 0.f;
#pragma unroll
    for (int i = 0; i < 8; ++i) tss += red[i];
    float var = tss * (1.0f / 1024.0f);
    float rstd = rsqrtf(var + 1e-3f);

    float4 g = *(const float4*)&gamma[tid * 4];
    float4 be = *(const float4*)&beta[tid * 4];
    float4 o;
    o.x = dx.x * rstd * g.x + be.x;
    o.y = dx.y * rstd * g.y + be.y;
    o.z = dx.z * rstd * g.z + be.z;
    o.w = dx.w * rstd * g.w + be.w;
    *(float4*)&out[(size_t)row * DMODEL + tid * 4] = o;
}

// -------------------- launcher --------------------------------------------
extern "C" void kernel_launch(void* const* d_in, const int* in_sizes, int n_in,
                              void* d_out, int out_size) {
    const float* query = (const float*)d_in[0];
    const float* key   = (const float*)d_in[1];
    const float* value = (const float*)d_in[2];
    const float* Wq = (const float*)d_in[3];
    const float* bq = (const float*)d_in[4];
    const float* Wk = (const float*)d_in[5];
    const float* bk = (const float*)d_in[6];
    const float* Wv = (const float*)d_in[7];
    const float* bv = (const float*)d_in[8];
    const float* Wo = (const float*)d_in[9];
    const float* bo = (const float*)d_in[10];
    const float* gamma = (const float*)d_in[11];
    const float* beta  = (const float*)d_in[12];

    float* out = (float*)d_out;
    float* attn = (out_size >= OUT_ELEMS + ATTN_ELEMS) ? (out + OUT_ELEMS) : nullptr;

    cudaFuncSetAttribute(attn_tc, cudaFuncAttributeMaxDynamicSharedMemorySize,
                         TCA_SMEM);
    cudaFuncSetAttribute(gemm_qkv, cudaFuncAttributeMaxDynamicSharedMemorySize,
                         GEMM_SMEM);
    cudaFuncSetAttribute(gemm_wo, cudaFuncAttributeMaxDynamicSharedMemorySize,
                         GEMM_SMEM);

    convert_split<<<dim3(OUT_ELEMS / 4 / 256, 1, 7), 256>>>(query, key, value,
                                                            Wq, Wk, Wv, Wo);

    gemm_qkv<<<dim3(DMODEL / 128, NROWS / 128, 3), 256, GEMM_SMEM>>>(bq, bk, bv);

    attn_tc<<<dim3(SEQ / 64, NHEAD, BATCH), 256, TCA_SMEM>>>(attn);

    gemm_wo<<<dim3(DMODEL / 128, NROWS / 128), 256, GEMM_SMEM>>>(bo);

    ln_kernel<<<NROWS, 256>>>(gamma, beta, out);
}